// round 1
// baseline (speedup 1.0000x reference)
#include <cuda_runtime.h>

#define BB   4
#define SS   2048
#define HIDD 1024
#define NH   16
#define NKV  4
#define HD   64
#define GROUPS 4
#define SCALE_F 0.125f

// Scratch (allocation-free: __device__ globals)
__device__ float g_q [BB*NH *SS*HD];   // [B,NH,S,D]
__device__ float g_k [BB*NKV*SS*HD];   // [B,NKV,S,D]
__device__ float g_v [BB*NKV*SS*HD];
__device__ float g_ao[BB*SS*NH*HD];    // [B,S,NH*D] attention output

// ---------------------------------------------------------------------------
// Fused QKV projection GEMM: X[8192,1024] @ {Wq,Wk,Wv}^T, scatter to g_q/g_k/g_v
// ---------------------------------------------------------------------------
#define GBM 128
#define GBN 128
#define GBK 16

__global__ __launch_bounds__(256) void qkv_gemm(
    const float* __restrict__ X,
    const float* __restrict__ Wq, const float* __restrict__ Wk, const float* __restrict__ Wv,
    const float* __restrict__ bq, const float* __restrict__ bk, const float* __restrict__ bv)
{
    __shared__ float As[GBK][GBM];
    __shared__ float Bs[GBK][GBN];

    const int tid = threadIdx.x;
    const int bx = blockIdx.x, by = blockIdx.y;
    const int n0 = bx * GBN;

    const float* W; const float* bias; int noff;
    if (n0 < 1024)      { W = Wq; bias = bq; noff = 0;    }
    else if (n0 < 1280) { W = Wk; bias = bk; noff = 1024; }
    else                { W = Wv; bias = bv; noff = 1280; }

    const int lrow = tid >> 2;      // 0..63
    const int lc4  = tid & 3;       // 0..3  (float4 within 16-col K tile)
    const int tx = tid & 15, ty = tid >> 4;

    float acc[8][8];
    #pragma unroll
    for (int i = 0; i < 8; i++)
        #pragma unroll
        for (int j = 0; j < 8; j++) acc[i][j] = 0.f;

    for (int kt = 0; kt < HIDD; kt += GBK) {
        float4 a0 = *(const float4*)&X[(size_t)(by*GBM + lrow     )*HIDD + kt + lc4*4];
        float4 a1 = *(const float4*)&X[(size_t)(by*GBM + lrow + 64)*HIDD + kt + lc4*4];
        float4 w0 = *(const float4*)&W[(size_t)(n0 - noff + lrow     )*HIDD + kt + lc4*4];
        float4 w1 = *(const float4*)&W[(size_t)(n0 - noff + lrow + 64)*HIDD + kt + lc4*4];

        __syncthreads();
        As[lc4*4+0][lrow] = a0.x; As[lc4*4+1][lrow] = a0.y;
        As[lc4*4+2][lrow] = a0.z; As[lc4*4+3][lrow] = a0.w;
        As[lc4*4+0][lrow+64] = a1.x; As[lc4*4+1][lrow+64] = a1.y;
        As[lc4*4+2][lrow+64] = a1.z; As[lc4*4+3][lrow+64] = a1.w;
        Bs[lc4*4+0][lrow] = w0.x; Bs[lc4*4+1][lrow] = w0.y;
        Bs[lc4*4+2][lrow] = w0.z; Bs[lc4*4+3][lrow] = w0.w;
        Bs[lc4*4+0][lrow+64] = w1.x; Bs[lc4*4+1][lrow+64] = w1.y;
        Bs[lc4*4+2][lrow+64] = w1.z; Bs[lc4*4+3][lrow+64] = w1.w;
        __syncthreads();

        #pragma unroll
        for (int kk = 0; kk < GBK; kk++) {
            float4 av0 = *(float4*)&As[kk][ty*8];
            float4 av1 = *(float4*)&As[kk][ty*8+4];
            float4 bv0 = *(float4*)&Bs[kk][tx*8];
            float4 bv1 = *(float4*)&Bs[kk][tx*8+4];
            float a[8] = {av0.x,av0.y,av0.z,av0.w, av1.x,av1.y,av1.z,av1.w};
            float b[8] = {bv0.x,bv0.y,bv0.z,bv0.w, bv1.x,bv1.y,bv1.z,bv1.w};
            #pragma unroll
            for (int i = 0; i < 8; i++)
                #pragma unroll
                for (int j = 0; j < 8; j++)
                    acc[i][j] += a[i] * b[j];
        }
    }

    // epilogue: bias + scatter into [B, heads, S, D] layout
    #pragma unroll
    for (int i = 0; i < 8; i++) {
        int m = by*GBM + ty*8 + i;
        int b_ = m >> 11;           // /2048
        int s  = m & 2047;
        #pragma unroll
        for (int j = 0; j < 8; j++) {
            int n = n0 + tx*8 + j;
            float val = acc[i][j] + bias[n - noff];
            if (n < 1024) {
                int h = n >> 6, d = n & 63;
                g_q[(((size_t)b_*NH + h)*SS + s)*HD + d] = val;
            } else if (n < 1280) {
                int nn = n - 1024; int h = nn >> 6, d = nn & 63;
                g_k[(((size_t)b_*NKV + h)*SS + s)*HD + d] = val;
            } else {
                int nn = n - 1280; int h = nn >> 6, d = nn & 63;
                g_v[(((size_t)b_*NKV + h)*SS + s)*HD + d] = val;
            }
        }
    }
}

// ---------------------------------------------------------------------------
// RoPE (duplicated-half convention): applied in place to g_q (which=0) / g_k (1)
// ---------------------------------------------------------------------------
__global__ void rope_kernel(int which, const float* __restrict__ cos_t,
                            const float* __restrict__ sin_t, int total)
{
    int idx = blockIdx.x * blockDim.x + threadIdx.x;
    if (idx >= total) return;
    float* buf = which ? g_k : g_q;
    int d  = idx & 31;
    int s  = (idx >> 5) & 2047;
    int bh = idx >> 16;               // / (2048*32)
    float* p = buf + ((size_t)bh*SS + s)*HD;
    float x1 = p[d], x2 = p[d+32];
    float c1 = cos_t[s*HD + d],      s1 = sin_t[s*HD + d];
    float c2 = cos_t[s*HD + d + 32], s2 = sin_t[s*HD + d + 32];
    p[d]      = x1*c1 - x2*s1;
    p[d+32]   = x2*c2 + x1*s2;
}

// ---------------------------------------------------------------------------
// Flash attention: 1 query row per thread, K/V tiles of 32 rows in smem.
// Writes g_ao in [B, S, NH*D] layout so O-proj reads row-major.
// ---------------------------------------------------------------------------
#define FA_BN 32

__global__ __launch_bounds__(128) void flash_kernel()
{
    const int b  = blockIdx.z;
    const int h  = blockIdx.y;
    const int qt = blockIdx.x;
    const int tid = threadIdx.x;
    const int srow = qt*128 + tid;
    const int hk = h / GROUPS;

    __shared__ float4 Ks[FA_BN][16];
    __shared__ float4 Vs[FA_BN][16];

    const float4* qrow = (const float4*)(g_q + (((size_t)b*NH + h)*SS + srow)*HD);
    float4 qv[16];
    #pragma unroll
    for (int i = 0; i < 16; i++) {
        float4 t = qrow[i];
        t.x *= SCALE_F; t.y *= SCALE_F; t.z *= SCALE_F; t.w *= SCALE_F;
        qv[i] = t;
    }

    float4 ov[16];
    #pragma unroll
    for (int i = 0; i < 16; i++) ov[i] = make_float4(0.f,0.f,0.f,0.f);
    float mval = -1e30f, lsum = 0.f;

    const float4* kbase = (const float4*)(g_k + (((size_t)b*NKV + hk)*SS)*HD);
    const float4* vbase = (const float4*)(g_v + (((size_t)b*NKV + hk)*SS)*HD);

    for (int t = 0; t < SS/FA_BN; t++) {
        __syncthreads();
        // cooperative load: 512 float4 per tile, 128 threads -> 4 each
        #pragma unroll
        for (int r = 0; r < 4; r++) {
            int li = tid + r*128;           // 0..511
            ((float4*)Ks)[li] = kbase[(size_t)t*FA_BN*16 + li];
            ((float4*)Vs)[li] = vbase[(size_t)t*FA_BN*16 + li];
        }
        __syncthreads();

        float s[FA_BN];
        float tmax = mval;
        #pragma unroll
        for (int j = 0; j < FA_BN; j++) {
            float4 a4 = make_float4(0.f,0.f,0.f,0.f);
            #pragma unroll
            for (int i = 0; i < 16; i++) {
                float4 kk = Ks[j][i];
                a4.x += qv[i].x*kk.x; a4.y += qv[i].y*kk.y;
                a4.z += qv[i].z*kk.z; a4.w += qv[i].w*kk.w;
            }
            s[j] = (a4.x + a4.y) + (a4.z + a4.w);
            tmax = fmaxf(tmax, s[j]);
        }
        float corr = __expf(mval - tmax);
        mval = tmax;
        float part = 0.f;
        #pragma unroll
        for (int j = 0; j < FA_BN; j++) {
            s[j] = __expf(s[j] - mval);
            part += s[j];
        }
        lsum = lsum * corr + part;
        #pragma unroll
        for (int i = 0; i < 16; i++) {
            ov[i].x *= corr; ov[i].y *= corr; ov[i].z *= corr; ov[i].w *= corr;
        }
        #pragma unroll
        for (int j = 0; j < FA_BN; j++) {
            float p = s[j];
            #pragma unroll
            for (int i = 0; i < 16; i++) {
                float4 vv = Vs[j][i];
                ov[i].x += p*vv.x; ov[i].y += p*vv.y;
                ov[i].z += p*vv.z; ov[i].w += p*vv.w;
            }
        }
    }

    float inv_l = 1.f / lsum;
    float4* orow = (float4*)(g_ao + ((size_t)b*SS + srow)*(NH*HD) + h*HD);
    #pragma unroll
    for (int i = 0; i < 16; i++) {
        float4 t = ov[i];
        t.x *= inv_l; t.y *= inv_l; t.z *= inv_l; t.w *= inv_l;
        orow[i] = t;
    }
}

// ---------------------------------------------------------------------------
// Output projection: g_ao[8192,1024] @ Wo^T + bo -> d_out
// ---------------------------------------------------------------------------
__global__ __launch_bounds__(256) void oproj_gemm(
    const float* __restrict__ Wo, const float* __restrict__ bo,
    float* __restrict__ C)
{
    __shared__ float As[GBK][GBM];
    __shared__ float Bs[GBK][GBN];

    const int tid = threadIdx.x;
    const int bx = blockIdx.x, by = blockIdx.y;
    const int n0 = bx * GBN;
    const int lrow = tid >> 2;
    const int lc4  = tid & 3;
    const int tx = tid & 15, ty = tid >> 4;
    const float* A = g_ao;

    float acc[8][8];
    #pragma unroll
    for (int i = 0; i < 8; i++)
        #pragma unroll
        for (int j = 0; j < 8; j++) acc[i][j] = 0.f;

    for (int kt = 0; kt < HIDD; kt += GBK) {
        float4 a0 = *(const float4*)&A [(size_t)(by*GBM + lrow     )*HIDD + kt + lc4*4];
        float4 a1 = *(const float4*)&A [(size_t)(by*GBM + lrow + 64)*HIDD + kt + lc4*4];
        float4 w0 = *(const float4*)&Wo[(size_t)(n0 + lrow     )*HIDD + kt + lc4*4];
        float4 w1 = *(const float4*)&Wo[(size_t)(n0 + lrow + 64)*HIDD + kt + lc4*4];

        __syncthreads();
        As[lc4*4+0][lrow] = a0.x; As[lc4*4+1][lrow] = a0.y;
        As[lc4*4+2][lrow] = a0.z; As[lc4*4+3][lrow] = a0.w;
        As[lc4*4+0][lrow+64] = a1.x; As[lc4*4+1][lrow+64] = a1.y;
        As[lc4*4+2][lrow+64] = a1.z; As[lc4*4+3][lrow+64] = a1.w;
        Bs[lc4*4+0][lrow] = w0.x; Bs[lc4*4+1][lrow] = w0.y;
        Bs[lc4*4+2][lrow] = w0.z; Bs[lc4*4+3][lrow] = w0.w;
        Bs[lc4*4+0][lrow+64] = w1.x; Bs[lc4*4+1][lrow+64] = w1.y;
        Bs[lc4*4+2][lrow+64] = w1.z; Bs[lc4*4+3][lrow+64] = w1.w;
        __syncthreads();

        #pragma unroll
        for (int kk = 0; kk < GBK; kk++) {
            float4 av0 = *(float4*)&As[kk][ty*8];
            float4 av1 = *(float4*)&As[kk][ty*8+4];
            float4 bv0 = *(float4*)&Bs[kk][tx*8];
            float4 bv1 = *(float4*)&Bs[kk][tx*8+4];
            float a[8] = {av0.x,av0.y,av0.z,av0.w, av1.x,av1.y,av1.z,av1.w};
            float b[8] = {bv0.x,bv0.y,bv0.z,bv0.w, bv1.x,bv1.y,bv1.z,bv1.w};
            #pragma unroll
            for (int i = 0; i < 8; i++)
                #pragma unroll
                for (int j = 0; j < 8; j++)
                    acc[i][j] += a[i] * b[j];
        }
    }

    #pragma unroll
    for (int i = 0; i < 8; i++) {
        int m = by*GBM + ty*8 + i;
        #pragma unroll
        for (int j = 0; j < 8; j++) {
            int n = n0 + tx*8 + j;
            C[(size_t)m*HIDD + n] = acc[i][j] + bo[n];
        }
    }
}

// ---------------------------------------------------------------------------
extern "C" void kernel_launch(void* const* d_in, const int* in_sizes, int n_in,
                              void* d_out, int out_size)
{
    const float* X    = (const float*)d_in[0];
    const float* cosp = (const float*)d_in[1];
    const float* sinp = (const float*)d_in[2];
    const float* Wq   = (const float*)d_in[3];
    const float* bq   = (const float*)d_in[4];
    const float* Wk   = (const float*)d_in[5];
    const float* bk   = (const float*)d_in[6];
    const float* Wv   = (const float*)d_in[7];
    const float* bv   = (const float*)d_in[8];
    const float* Wo   = (const float*)d_in[9];
    const float* bo   = (const float*)d_in[10];
    float* out = (float*)d_out;

    // 1. QKV projection (M=8192, N=1536, K=1024)
    dim3 g1(1536/GBN, 8192/GBM);
    qkv_gemm<<<g1, 256>>>(X, Wq, Wk, Wv, bq, bk, bv);

    // 2. RoPE on q and k
    int tq = BB*NH *SS*32;
    int tk = BB*NKV*SS*32;
    rope_kernel<<<(tq + 255)/256, 256>>>(0, cosp, sinp, tq);
    rope_kernel<<<(tk + 255)/256, 256>>>(1, cosp, sinp, tk);

    // 3. Flash attention
    dim3 g3(SS/128, NH, BB);
    flash_kernel<<<g3, 128>>>();

    // 4. Output projection (M=8192, N=1024, K=1024)
    dim3 g4(1024/GBN, 8192/GBM);
    oproj_gemm<<<g4, 256>>>(Wo, bo, out);
}

// round 2
// speedup vs baseline: 2.4249x; 2.4249x over previous
#include <cuda_runtime.h>
#include <cuda_bf16.h>
#include <cstdint>

#define BB   4
#define SS   2048
#define HIDD 1024
#define NH   16
#define NKV  4
#define HD   64
#define GROUPS 4
#define SCALE_F 0.125f

// Scratch (allocation-free: __device__ globals)
__device__ float g_q [BB*NH *SS*HD];   // [B,NH,S,D]
__device__ float g_k [BB*NKV*SS*HD];   // [B,NKV,S,D]
__device__ float g_v [BB*NKV*SS*HD];
__device__ float g_ao[BB*SS*NH*HD];    // [B,S,NH*D]

// ---------------------------------------------------------------------------
// helpers
// ---------------------------------------------------------------------------
__device__ __forceinline__ void mma16816(float* c, const uint32_t* a, const uint32_t* b) {
    asm volatile(
        "mma.sync.aligned.m16n8k16.row.col.f32.bf16.bf16.f32 "
        "{%0,%1,%2,%3}, {%4,%5,%6,%7}, {%8,%9}, {%0,%1,%2,%3};"
        : "+f"(c[0]), "+f"(c[1]), "+f"(c[2]), "+f"(c[3])
        : "r"(a[0]), "r"(a[1]), "r"(a[2]), "r"(a[3]), "r"(b[0]), "r"(b[1]));
}

__device__ __forceinline__ uint32_t pack_bf2(float lo, float hi) {
    __nv_bfloat162 t;
    t.x = __float2bfloat16(lo);
    t.y = __float2bfloat16(hi);
    return *(uint32_t*)&t;
}

// split fp32 x into hi (bf16) + lo (bf16 of residual)
__device__ __forceinline__ void split1(float x, __nv_bfloat16& h, __nv_bfloat16& l) {
    h = __float2bfloat16(x);
    l = __float2bfloat16(x - __bfloat162float(h));
}

// split a float4 and store 4 consecutive bf16 to hi/lo smem (4B-aligned)
__device__ __forceinline__ void split4_store(float4 v, __nv_bfloat16* H, __nv_bfloat16* L) {
    __nv_bfloat16 h0,h1,h2,h3,l0,l1,l2,l3;
    split1(v.x,h0,l0); split1(v.y,h1,l1); split1(v.z,h2,l2); split1(v.w,h3,l3);
    __nv_bfloat162 a; a.x=h0; a.y=h1; ((__nv_bfloat162*)H)[0]=a;
    __nv_bfloat162 b; b.x=h2; b.y=h3; ((__nv_bfloat162*)H)[1]=b;
    __nv_bfloat162 c; c.x=l0; c.y=l1; ((__nv_bfloat162*)L)[0]=c;
    __nv_bfloat162 d; d.x=l2; d.y=l3; ((__nv_bfloat162*)L)[1]=d;
}

// ---------------------------------------------------------------------------
// QKV projection GEMM (tensor cores, split-bf16 x3)
// BM=128, BN=64, BK=32; 256 threads = 8 warps (4m x 2n); warp tile 32x32
// ---------------------------------------------------------------------------
#define ASTRIDE 40   // bf16 elems per smem row (32 data + 8 pad)

__global__ __launch_bounds__(256) void qkv_gemm(
    const float* __restrict__ X,
    const float* __restrict__ Wq, const float* __restrict__ Wk, const float* __restrict__ Wv,
    const float* __restrict__ bq, const float* __restrict__ bk, const float* __restrict__ bv)
{
    __shared__ __nv_bfloat16 Ah[128*ASTRIDE], Al[128*ASTRIDE];
    __shared__ __nv_bfloat16 Bh[64*ASTRIDE],  Bl[64*ASTRIDE];

    const int tid  = threadIdx.x;
    const int lane = tid & 31;
    const int warp = tid >> 5;
    const int wm = warp & 3;            // 0..3
    const int wn = warp >> 2;           // 0..1
    const int bx = blockIdx.x, by = blockIdx.y;
    const int n0 = bx * 64;

    const float* W; const float* bias; int noff;
    if (n0 < 1024)      { W = Wq; bias = bq; noff = 0;    }
    else if (n0 < 1280) { W = Wk; bias = bk; noff = 1024; }
    else                { W = Wv; bias = bv; noff = 1280; }

    float c[2][4][4];
    #pragma unroll
    for (int i=0;i<2;i++) for (int j=0;j<4;j++) for (int e=0;e<4;e++) c[i][j][e]=0.f;

    for (int kt = 0; kt < HIDD; kt += 32) {
        __syncthreads();
        // A tile: 128x32 floats -> 1024 float4, 256 thr -> 4 each
        #pragma unroll
        for (int p = 0; p < 4; p++) {
            int idx = tid + p*256;
            int row = idx >> 3, c4 = (idx & 7) * 4;
            float4 v = *(const float4*)&X[(size_t)(by*128 + row)*HIDD + kt + c4];
            split4_store(v, &Ah[row*ASTRIDE + c4], &Al[row*ASTRIDE + c4]);
        }
        // B tile: 64x32 -> 512 float4 -> 2 each
        #pragma unroll
        for (int p = 0; p < 2; p++) {
            int idx = tid + p*256;
            int row = idx >> 3, c4 = (idx & 7) * 4;
            float4 v = *(const float4*)&W[(size_t)(n0 - noff + row)*HIDD + kt + c4];
            split4_store(v, &Bh[row*ASTRIDE + c4], &Bl[row*ASTRIDE + c4]);
        }
        __syncthreads();

        #pragma unroll
        for (int ks = 0; ks < 2; ks++) {
            uint32_t ah[2][4], al[2][4], bh[4][2], bl[4][2];
            int col = ks*16 + (lane & 3)*2;
            #pragma unroll
            for (int mi = 0; mi < 2; mi++) {
                int r = wm*32 + mi*16 + (lane >> 2);
                ah[mi][0] = *(uint32_t*)&Ah[ r     *ASTRIDE + col    ];
                ah[mi][1] = *(uint32_t*)&Ah[(r+8)  *ASTRIDE + col    ];
                ah[mi][2] = *(uint32_t*)&Ah[ r     *ASTRIDE + col + 8];
                ah[mi][3] = *(uint32_t*)&Ah[(r+8)  *ASTRIDE + col + 8];
                al[mi][0] = *(uint32_t*)&Al[ r     *ASTRIDE + col    ];
                al[mi][1] = *(uint32_t*)&Al[(r+8)  *ASTRIDE + col    ];
                al[mi][2] = *(uint32_t*)&Al[ r     *ASTRIDE + col + 8];
                al[mi][3] = *(uint32_t*)&Al[(r+8)  *ASTRIDE + col + 8];
            }
            #pragma unroll
            for (int ni = 0; ni < 4; ni++) {
                int n = wn*32 + ni*8 + (lane >> 2);
                bh[ni][0] = *(uint32_t*)&Bh[n*ASTRIDE + col    ];
                bh[ni][1] = *(uint32_t*)&Bh[n*ASTRIDE + col + 8];
                bl[ni][0] = *(uint32_t*)&Bl[n*ASTRIDE + col    ];
                bl[ni][1] = *(uint32_t*)&Bl[n*ASTRIDE + col + 8];
            }
            #pragma unroll
            for (int mi = 0; mi < 2; mi++)
                #pragma unroll
                for (int ni = 0; ni < 4; ni++) {
                    mma16816(c[mi][ni], ah[mi], bh[ni]);
                    mma16816(c[mi][ni], ah[mi], bl[ni]);
                    mma16816(c[mi][ni], al[mi], bh[ni]);
                }
        }
    }

    // epilogue: bias + scatter into [B, heads, S, D]
    #pragma unroll
    for (int mi = 0; mi < 2; mi++) {
        #pragma unroll
        for (int ni = 0; ni < 4; ni++) {
            #pragma unroll
            for (int e = 0; e < 4; e++) {
                int m = by*128 + wm*32 + mi*16 + (lane >> 2) + ((e >= 2) ? 8 : 0);
                int n = n0 + wn*32 + ni*8 + 2*(lane & 3) + (e & 1);
                int b_ = m >> 11, s = m & 2047;
                float val = c[mi][ni][e] + bias[n - noff];
                if (n < 1024) {
                    int h = n >> 6, d = n & 63;
                    g_q[(((size_t)b_*NH + h)*SS + s)*HD + d] = val;
                } else if (n < 1280) {
                    int nn = n - 1024; int h = nn >> 6, d = nn & 63;
                    g_k[(((size_t)b_*NKV + h)*SS + s)*HD + d] = val;
                } else {
                    int nn = n - 1280; int h = nn >> 6, d = nn & 63;
                    g_v[(((size_t)b_*NKV + h)*SS + s)*HD + d] = val;
                }
            }
        }
    }
}

// ---------------------------------------------------------------------------
// RoPE (duplicated-half): in place on g_q / g_k
// ---------------------------------------------------------------------------
__global__ void rope_kernel(int which, const float* __restrict__ cos_t,
                            const float* __restrict__ sin_t, int total)
{
    int idx = blockIdx.x * blockDim.x + threadIdx.x;
    if (idx >= total) return;
    float* buf = which ? g_k : g_q;
    int d  = idx & 31;
    int s  = (idx >> 5) & 2047;
    int bh = idx >> 16;
    float* p = buf + ((size_t)bh*SS + s)*HD;
    float x1 = p[d], x2 = p[d+32];
    float c1 = cos_t[s*HD + d],      s1 = sin_t[s*HD + d];
    float c2 = cos_t[s*HD + d + 32], s2 = sin_t[s*HD + d + 32];
    p[d]    = x1*c1 - x2*s1;
    p[d+32] = x2*c2 + x1*s2;
}

// ---------------------------------------------------------------------------
// Flash attention (tensor cores). Block: 128 thr (4 warps), 64 q-rows,
// key tiles of 32. Q/K split-bf16 x3, P split x3 (in-register, FA2 layout).
// ---------------------------------------------------------------------------
#define QSTR 72      // Q/K smem stride (64 data + 8 pad), bf16
#define VSTR 40      // V^T smem stride (32 keys + 8 pad), bf16

__global__ __launch_bounds__(128) void flash_kernel()
{
    __shared__ __nv_bfloat16 Qh[64*QSTR], Ql[64*QSTR];
    __shared__ __nv_bfloat16 Kh[32*QSTR], Kl[32*QSTR];
    __shared__ __nv_bfloat16 Vh[64*VSTR], Vl[64*VSTR];   // transposed: [d][key]

    const int b  = blockIdx.z;
    const int h  = blockIdx.y;
    const int qt = blockIdx.x;
    const int tid  = threadIdx.x;
    const int lane = tid & 31;
    const int warp = tid >> 5;
    const int hk = h / GROUPS;

    const float* qbase = g_q + (((size_t)b*NH  + h )*SS + qt*64)*HD;
    const float* kbase = g_k + (((size_t)b*NKV + hk)*SS)*HD;
    const float* vbase = g_v + (((size_t)b*NKV + hk)*SS)*HD;

    // load + scale + split Q: 64x64 floats = 1024 float4, 128 thr -> 8 each
    #pragma unroll
    for (int p = 0; p < 8; p++) {
        int idx = tid + p*128;
        int row = idx >> 4, c4 = (idx & 15) * 4;
        float4 v = *(const float4*)&qbase[(size_t)row*HD + c4];
        v.x *= SCALE_F; v.y *= SCALE_F; v.z *= SCALE_F; v.w *= SCALE_F;
        split4_store(v, &Qh[row*QSTR + c4], &Ql[row*QSTR + c4]);
    }
    __syncthreads();

    // preload Q fragments (warp owns 16 rows)
    uint32_t qh[4][4], ql[4][4];
    {
        int r = warp*16 + (lane >> 2);
        #pragma unroll
        for (int kk = 0; kk < 4; kk++) {
            int col = kk*16 + (lane & 3)*2;
            qh[kk][0] = *(uint32_t*)&Qh[ r   *QSTR + col    ];
            qh[kk][1] = *(uint32_t*)&Qh[(r+8)*QSTR + col    ];
            qh[kk][2] = *(uint32_t*)&Qh[ r   *QSTR + col + 8];
            qh[kk][3] = *(uint32_t*)&Qh[(r+8)*QSTR + col + 8];
            ql[kk][0] = *(uint32_t*)&Ql[ r   *QSTR + col    ];
            ql[kk][1] = *(uint32_t*)&Ql[(r+8)*QSTR + col    ];
            ql[kk][2] = *(uint32_t*)&Ql[ r   *QSTR + col + 8];
            ql[kk][3] = *(uint32_t*)&Ql[(r+8)*QSTR + col + 8];
        }
    }

    float o[8][4];
    #pragma unroll
    for (int i = 0; i < 8; i++) for (int j = 0; j < 4; j++) o[i][j] = 0.f;
    float m0 = -1e30f, m1 = -1e30f, l0 = 0.f, l1 = 0.f;

    for (int t = 0; t < SS/32; t++) {
        __syncthreads();
        // K tile 32x64 = 512 float4, 4 per thread
        #pragma unroll
        for (int p = 0; p < 4; p++) {
            int idx = tid + p*128;
            int row = idx >> 4, c4 = (idx & 15) * 4;
            float4 v = *(const float4*)&kbase[((size_t)t*32 + row)*HD + c4];
            split4_store(v, &Kh[row*QSTR + c4], &Kl[row*QSTR + c4]);
        }
        // V tile 32x64 -> transposed [d][key]
        #pragma unroll
        for (int p = 0; p < 4; p++) {
            int idx = tid + p*128;
            int key = idx >> 4, c4 = (idx & 15) * 4;
            float4 v = *(const float4*)&vbase[((size_t)t*32 + key)*HD + c4];
            __nv_bfloat16 hh, ll;
            split1(v.x, hh, ll); Vh[(c4+0)*VSTR + key] = hh; Vl[(c4+0)*VSTR + key] = ll;
            split1(v.y, hh, ll); Vh[(c4+1)*VSTR + key] = hh; Vl[(c4+1)*VSTR + key] = ll;
            split1(v.z, hh, ll); Vh[(c4+2)*VSTR + key] = hh; Vl[(c4+2)*VSTR + key] = ll;
            split1(v.w, hh, ll); Vh[(c4+3)*VSTR + key] = hh; Vl[(c4+3)*VSTR + key] = ll;
        }
        __syncthreads();

        // S = Q K^T : 16 rows x 32 keys per warp; 4 n-tiles, 4 k-steps
        float s[4][4];
        #pragma unroll
        for (int i = 0; i < 4; i++) for (int j = 0; j < 4; j++) s[i][j] = 0.f;
        #pragma unroll
        for (int kk = 0; kk < 4; kk++) {
            int col = kk*16 + (lane & 3)*2;
            #pragma unroll
            for (int nt = 0; nt < 4; nt++) {
                int n = nt*8 + (lane >> 2);
                uint32_t bhf[2], blf[2];
                bhf[0] = *(uint32_t*)&Kh[n*QSTR + col    ];
                bhf[1] = *(uint32_t*)&Kh[n*QSTR + col + 8];
                blf[0] = *(uint32_t*)&Kl[n*QSTR + col    ];
                blf[1] = *(uint32_t*)&Kl[n*QSTR + col + 8];
                mma16816(s[nt], qh[kk], bhf);
                mma16816(s[nt], qh[kk], blf);
                mma16816(s[nt], ql[kk], bhf);
            }
        }

        // online softmax (rows r0 = lane>>2, r1 = r0+8)
        float mx0 = -1e30f, mx1 = -1e30f;
        #pragma unroll
        for (int nt = 0; nt < 4; nt++) {
            mx0 = fmaxf(mx0, fmaxf(s[nt][0], s[nt][1]));
            mx1 = fmaxf(mx1, fmaxf(s[nt][2], s[nt][3]));
        }
        mx0 = fmaxf(mx0, __shfl_xor_sync(0xffffffffu, mx0, 1));
        mx0 = fmaxf(mx0, __shfl_xor_sync(0xffffffffu, mx0, 2));
        mx1 = fmaxf(mx1, __shfl_xor_sync(0xffffffffu, mx1, 1));
        mx1 = fmaxf(mx1, __shfl_xor_sync(0xffffffffu, mx1, 2));
        float nm0 = fmaxf(m0, mx0), nm1 = fmaxf(m1, mx1);
        float cr0 = __expf(m0 - nm0), cr1 = __expf(m1 - nm1);
        m0 = nm0; m1 = nm1;
        float sp0 = 0.f, sp1 = 0.f;
        #pragma unroll
        for (int nt = 0; nt < 4; nt++) {
            s[nt][0] = __expf(s[nt][0] - m0); sp0 += s[nt][0];
            s[nt][1] = __expf(s[nt][1] - m0); sp0 += s[nt][1];
            s[nt][2] = __expf(s[nt][2] - m1); sp1 += s[nt][2];
            s[nt][3] = __expf(s[nt][3] - m1); sp1 += s[nt][3];
        }
        l0 = l0*cr0 + sp0;
        l1 = l1*cr1 + sp1;
        #pragma unroll
        for (int nb = 0; nb < 8; nb++) {
            o[nb][0] *= cr0; o[nb][1] *= cr0;
            o[nb][2] *= cr1; o[nb][3] *= cr1;
        }

        // P V : P fragments come straight from s[][] (C-frag == A-frag layout)
        #pragma unroll
        for (int kk = 0; kk < 2; kk++) {
            uint32_t pah[4], pal[4];
            #pragma unroll
            for (int half = 0; half < 2; half++) {   // half 0: rows r0 (c0,c1); 1: rows r1 (c2,c3)
                int nt0 = 2*kk, nt1 = 2*kk + 1;
                float v0 = s[nt0][half*2], v1 = s[nt0][half*2+1];
                float w0 = s[nt1][half*2], w1 = s[nt1][half*2+1];
                __nv_bfloat16 h0,h1,h2,h3,l0_,l1_,l2_,l3_;
                split1(v0,h0,l0_); split1(v1,h1,l1_);
                split1(w0,h2,l2_); split1(w1,h3,l3_);
                __nv_bfloat162 t;
                t.x=h0; t.y=h1; pah[half]   = *(uint32_t*)&t;
                t.x=h2; t.y=h3; pah[half+2] = *(uint32_t*)&t;
                t.x=l0_;t.y=l1_;pal[half]   = *(uint32_t*)&t;
                t.x=l2_;t.y=l3_;pal[half+2] = *(uint32_t*)&t;
            }
            int col = kk*16 + (lane & 3)*2;
            #pragma unroll
            for (int nb = 0; nb < 8; nb++) {
                int d = nb*8 + (lane >> 2);
                uint32_t bhf[2], blf[2];
                bhf[0] = *(uint32_t*)&Vh[d*VSTR + col    ];
                bhf[1] = *(uint32_t*)&Vh[d*VSTR + col + 8];
                blf[0] = *(uint32_t*)&Vl[d*VSTR + col    ];
                blf[1] = *(uint32_t*)&Vl[d*VSTR + col + 8];
                mma16816(o[nb], pah, bhf);
                mma16816(o[nb], pah, blf);
                mma16816(o[nb], pal, bhf);
            }
        }
    }

    // finalize: full row sums, normalize, store
    l0 += __shfl_xor_sync(0xffffffffu, l0, 1);
    l0 += __shfl_xor_sync(0xffffffffu, l0, 2);
    l1 += __shfl_xor_sync(0xffffffffu, l1, 1);
    l1 += __shfl_xor_sync(0xffffffffu, l1, 2);
    float inv0 = 1.f / l0, inv1 = 1.f / l1;

    int r0 = qt*64 + warp*16 + (lane >> 2);
    float* out0 = g_ao + ((size_t)b*SS + r0    )*(NH*HD) + h*HD;
    float* out1 = g_ao + ((size_t)b*SS + r0 + 8)*(NH*HD) + h*HD;
    #pragma unroll
    for (int nb = 0; nb < 8; nb++) {
        int d = nb*8 + 2*(lane & 3);
        out0[d]   = o[nb][0]*inv0;
        out0[d+1] = o[nb][1]*inv0;
        out1[d]   = o[nb][2]*inv1;
        out1[d+1] = o[nb][3]*inv1;
    }
}

// ---------------------------------------------------------------------------
// O-proj GEMM: g_ao[8192,1024] @ Wo^T + bo -> d_out (same scheme as qkv)
// ---------------------------------------------------------------------------
__global__ __launch_bounds__(256) void oproj_gemm(
    const float* __restrict__ Wo, const float* __restrict__ bo,
    float* __restrict__ C)
{
    __shared__ __nv_bfloat16 Ah[128*ASTRIDE], Al[128*ASTRIDE];
    __shared__ __nv_bfloat16 Bh[64*ASTRIDE],  Bl[64*ASTRIDE];

    const int tid  = threadIdx.x;
    const int lane = tid & 31;
    const int warp = tid >> 5;
    const int wm = warp & 3;
    const int wn = warp >> 2;
    const int bx = blockIdx.x, by = blockIdx.y;
    const int n0 = bx * 64;
    const float* A = g_ao;

    float c[2][4][4];
    #pragma unroll
    for (int i=0;i<2;i++) for (int j=0;j<4;j++) for (int e=0;e<4;e++) c[i][j][e]=0.f;

    for (int kt = 0; kt < HIDD; kt += 32) {
        __syncthreads();
        #pragma unroll
        for (int p = 0; p < 4; p++) {
            int idx = tid + p*256;
            int row = idx >> 3, c4 = (idx & 7) * 4;
            float4 v = *(const float4*)&A[(size_t)(by*128 + row)*HIDD + kt + c4];
            split4_store(v, &Ah[row*ASTRIDE + c4], &Al[row*ASTRIDE + c4]);
        }
        #pragma unroll
        for (int p = 0; p < 2; p++) {
            int idx = tid + p*256;
            int row = idx >> 3, c4 = (idx & 7) * 4;
            float4 v = *(const float4*)&Wo[(size_t)(n0 + row)*HIDD + kt + c4];
            split4_store(v, &Bh[row*ASTRIDE + c4], &Bl[row*ASTRIDE + c4]);
        }
        __syncthreads();

        #pragma unroll
        for (int ks = 0; ks < 2; ks++) {
            uint32_t ah[2][4], al[2][4], bh[4][2], bl[4][2];
            int col = ks*16 + (lane & 3)*2;
            #pragma unroll
            for (int mi = 0; mi < 2; mi++) {
                int r = wm*32 + mi*16 + (lane >> 2);
                ah[mi][0] = *(uint32_t*)&Ah[ r   *ASTRIDE + col    ];
                ah[mi][1] = *(uint32_t*)&Ah[(r+8)*ASTRIDE + col    ];
                ah[mi][2] = *(uint32_t*)&Ah[ r   *ASTRIDE + col + 8];
                ah[mi][3] = *(uint32_t*)&Ah[(r+8)*ASTRIDE + col + 8];
                al[mi][0] = *(uint32_t*)&Al[ r   *ASTRIDE + col    ];
                al[mi][1] = *(uint32_t*)&Al[(r+8)*ASTRIDE + col    ];
                al[mi][2] = *(uint32_t*)&Al[ r   *ASTRIDE + col + 8];
                al[mi][3] = *(uint32_t*)&Al[(r+8)*ASTRIDE + col + 8];
            }
            #pragma unroll
            for (int ni = 0; ni < 4; ni++) {
                int n = wn*32 + ni*8 + (lane >> 2);
                bh[ni][0] = *(uint32_t*)&Bh[n*ASTRIDE + col    ];
                bh[ni][1] = *(uint32_t*)&Bh[n*ASTRIDE + col + 8];
                bl[ni][0] = *(uint32_t*)&Bl[n*ASTRIDE + col    ];
                bl[ni][1] = *(uint32_t*)&Bl[n*ASTRIDE + col + 8];
            }
            #pragma unroll
            for (int mi = 0; mi < 2; mi++)
                #pragma unroll
                for (int ni = 0; ni < 4; ni++) {
                    mma16816(c[mi][ni], ah[mi], bh[ni]);
                    mma16816(c[mi][ni], ah[mi], bl[ni]);
                    mma16816(c[mi][ni], al[mi], bh[ni]);
                }
        }
    }

    #pragma unroll
    for (int mi = 0; mi < 2; mi++)
        #pragma unroll
        for (int ni = 0; ni < 4; ni++)
            #pragma unroll
            for (int e = 0; e < 4; e++) {
                int m = by*128 + wm*32 + mi*16 + (lane >> 2) + ((e >= 2) ? 8 : 0);
                int n = n0 + wn*32 + ni*8 + 2*(lane & 3) + (e & 1);
                C[(size_t)m*HIDD + n] = c[mi][ni][e] + bo[n];
            }
}

// ---------------------------------------------------------------------------
extern "C" void kernel_launch(void* const* d_in, const int* in_sizes, int n_in,
                              void* d_out, int out_size)
{
    const float* X    = (const float*)d_in[0];
    const float* cosp = (const float*)d_in[1];
    const float* sinp = (const float*)d_in[2];
    const float* Wq   = (const float*)d_in[3];
    const float* bq   = (const float*)d_in[4];
    const float* Wk   = (const float*)d_in[5];
    const float* bk   = (const float*)d_in[6];
    const float* Wv   = (const float*)d_in[7];
    const float* bv   = (const float*)d_in[8];
    const float* Wo   = (const float*)d_in[9];
    const float* bo   = (const float*)d_in[10];
    float* out = (float*)d_out;

    // 1. QKV projection (M=8192, N=1536, K=1024)
    dim3 g1(1536/64, 8192/128);
    qkv_gemm<<<g1, 256>>>(X, Wq, Wk, Wv, bq, bk, bv);

    // 2. RoPE
    int tq = BB*NH *SS*32;
    int tk = BB*NKV*SS*32;
    rope_kernel<<<(tq + 255)/256, 256>>>(0, cosp, sinp, tq);
    rope_kernel<<<(tk + 255)/256, 256>>>(1, cosp, sinp, tk);

    // 3. Flash attention (tensor cores)
    dim3 g3(SS/64, NH, BB);
    flash_kernel<<<g3, 128>>>();

    // 4. Output projection (M=8192, N=1024, K=1024)
    dim3 g4(1024/64, 8192/128);
    oproj_gemm<<<g4, 256>>>(Wo, bo, out);
}

// round 5
// speedup vs baseline: 3.1501x; 1.2991x over previous
#include <cuda_runtime.h>
#include <cuda_bf16.h>
#include <cstdint>

#define BB   4
#define SS   2048
#define HIDD 1024
#define NH   16
#define NKV  4
#define HD   64
#define GROUPS 4
#define SCALE_F 0.125f

// ---------------- scratch (__device__ globals, allocation-free) -------------
__device__ float g_q[BB*NH*SS*HD];
__device__ float g_k[BB*NKV*SS*HD];
__device__ __nv_bfloat16 g_qh[BB*NH*SS*HD],  g_ql[BB*NH*SS*HD];
__device__ __nv_bfloat16 g_kh[BB*NKV*SS*HD], g_kl[BB*NKV*SS*HD];
__device__ __nv_bfloat16 g_vh[BB*NKV*SS*HD], g_vl[BB*NKV*SS*HD];
__device__ __nv_bfloat16 g_xh[BB*SS*HIDD],   g_xl[BB*SS*HIDD];
__device__ __nv_bfloat16 g_aoh[BB*SS*NH*HD], g_aol[BB*SS*NH*HD];
__device__ __nv_bfloat16 g_wqh[NH*HD*HIDD],  g_wql[NH*HD*HIDD];
__device__ __nv_bfloat16 g_wkh[NKV*HD*HIDD], g_wkl[NKV*HD*HIDD];
__device__ __nv_bfloat16 g_wvh[NKV*HD*HIDD], g_wvl[NKV*HD*HIDD];
__device__ __nv_bfloat16 g_woh[HIDD*NH*HD],  g_wol[HIDD*NH*HD];

// ---------------- helpers ---------------------------------------------------
__device__ __forceinline__ uint32_t s2u(const void* p) {
    return (uint32_t)__cvta_generic_to_shared(p);
}
__device__ __forceinline__ void mma16816(float* c, const uint32_t* a, const uint32_t* b) {
    asm volatile(
        "mma.sync.aligned.m16n8k16.row.col.f32.bf16.bf16.f32 "
        "{%0,%1,%2,%3}, {%4,%5,%6,%7}, {%8,%9}, {%0,%1,%2,%3};"
        : "+f"(c[0]), "+f"(c[1]), "+f"(c[2]), "+f"(c[3])
        : "r"(a[0]), "r"(a[1]), "r"(a[2]), "r"(a[3]), "r"(b[0]), "r"(b[1]));
}
__device__ __forceinline__ void ldsm4(uint32_t* r, uint32_t addr) {
    asm volatile("ldmatrix.sync.aligned.m8n8.x4.shared.b16 {%0,%1,%2,%3}, [%4];"
        : "=r"(r[0]), "=r"(r[1]), "=r"(r[2]), "=r"(r[3]) : "r"(addr));
}
__device__ __forceinline__ void ldsm4t(uint32_t* r, uint32_t addr) {
    asm volatile("ldmatrix.sync.aligned.m8n8.x4.trans.shared.b16 {%0,%1,%2,%3}, [%4];"
        : "=r"(r[0]), "=r"(r[1]), "=r"(r[2]), "=r"(r[3]) : "r"(addr));
}
__device__ __forceinline__ void cpa16(void* dst, const void* src) {
    asm volatile("cp.async.cg.shared.global [%0], [%1], 16;" :: "r"(s2u(dst)), "l"(src));
}
__device__ __forceinline__ void cpa_wait() {
    asm volatile("cp.async.commit_group;");
    asm volatile("cp.async.wait_group 0;" ::: "memory");
}
__device__ __forceinline__ void split1(float x, __nv_bfloat16& h, __nv_bfloat16& l) {
    h = __float2bfloat16(x);
    l = __float2bfloat16(x - __bfloat162float(h));
}
__device__ __forceinline__ uint32_t packbf2(__nv_bfloat16 a, __nv_bfloat16 b) {
    __nv_bfloat162 t; t.x = a; t.y = b;
    return *(uint32_t*)&t;
}
__device__ __forceinline__ void split4_store(float4 v, __nv_bfloat16* H, __nv_bfloat16* L) {
    __nv_bfloat16 h0,h1,h2,h3,l0,l1,l2,l3;
    split1(v.x,h0,l0); split1(v.y,h1,l1); split1(v.z,h2,l2); split1(v.w,h3,l3);
    ((__nv_bfloat162*)H)[0] = __nv_bfloat162(h0,h1);
    ((__nv_bfloat162*)H)[1] = __nv_bfloat162(h2,h3);
    ((__nv_bfloat162*)L)[0] = __nv_bfloat162(l0,l1);
    ((__nv_bfloat162*)L)[1] = __nv_bfloat162(l2,l3);
}

// ---------------- generic fp32 -> (hi,lo) bf16 split ------------------------
__global__ void split_kernel(const float* __restrict__ src, int which, int n4) {
    int i = blockIdx.x * blockDim.x + threadIdx.x;
    if (i >= n4) return;
    __nv_bfloat16 *h, *l;
    switch (which) {
        case 0: h = g_xh;  l = g_xl;  break;
        case 1: h = g_wqh; l = g_wql; break;
        case 2: h = g_wkh; l = g_wkl; break;
        case 3: h = g_wvh; l = g_wvl; break;
        default: h = g_woh; l = g_wol; break;
    }
    float4 v = *(const float4*)&src[(size_t)i*4];
    split4_store(v, &h[(size_t)i*4], &l[(size_t)i*4]);
}

// ---------------- QKV GEMM (BM128 BN64 BK32, 8 warps, ldmatrix) -------------
#define GSTR 40   // smem stride: 32 + 8 pad bf16 (80B, conflict-free for ldsm)

__global__ __launch_bounds__(256) void qkv_gemm(
    const float* __restrict__ bq, const float* __restrict__ bk, const float* __restrict__ bv)
{
    __shared__ __nv_bfloat16 Ah[128*GSTR], Al[128*GSTR];
    __shared__ __nv_bfloat16 Bh[64*GSTR],  Bl[64*GSTR];

    const int tid = threadIdx.x, lane = tid & 31, warp = tid >> 5;
    const int wm = warp & 3, wn = warp >> 2;
    const int gi = lane >> 3, ii = lane & 7;
    const int bx = blockIdx.x, by = blockIdx.y;
    const int n0 = bx * 64;

    const __nv_bfloat16 *Wh, *Wl; const float* bias; int noff;
    if (n0 < 1024)      { Wh = g_wqh; Wl = g_wql; bias = bq; noff = 0;    }
    else if (n0 < 1280) { Wh = g_wkh; Wl = g_wkl; bias = bk; noff = 1024; }
    else                { Wh = g_wvh; Wl = g_wvl; bias = bv; noff = 1280; }

    float c[2][4][4];
    #pragma unroll
    for (int i=0;i<2;i++) for (int j=0;j<4;j++) for (int e=0;e<4;e++) c[i][j][e]=0.f;

    for (int kt = 0; kt < HIDD; kt += 32) {
        __syncthreads();
        // A: 128 rows x 4 chunks(16B) per array; 512 chunks / 256 thr = 2 each
        #pragma unroll
        for (int p = 0; p < 2; p++) {
            int cidx = tid + p*256;
            int row = cidx >> 2, ch = cidx & 3;
            size_t so = (size_t)(by*128 + row)*HIDD + kt + ch*8;
            cpa16(&Ah[row*GSTR + ch*8], &g_xh[so]);
            cpa16(&Al[row*GSTR + ch*8], &g_xl[so]);
        }
        // B: 64 rows x 4 chunks; 256 chunks -> 1 each
        {
            int row = tid >> 2, ch = tid & 3;
            size_t so = (size_t)(n0 - noff + row)*HIDD + kt + ch*8;
            cpa16(&Bh[row*GSTR + ch*8], &Wh[so]);
            cpa16(&Bl[row*GSTR + ch*8], &Wl[so]);
        }
        cpa_wait();
        __syncthreads();

        #pragma unroll
        for (int ks = 0; ks < 2; ks++) {
            uint32_t ah[2][4], al[2][4], bhf[2][4], blf[2][4];
            #pragma unroll
            for (int mi = 0; mi < 2; mi++) {
                int row = wm*32 + mi*16 + ii + (gi & 1)*8;
                int col = ks*16 + (gi >> 1)*8;
                ldsm4(ah[mi], s2u(&Ah[row*GSTR + col]));
                ldsm4(al[mi], s2u(&Al[row*GSTR + col]));
            }
            #pragma unroll
            for (int ng = 0; ng < 2; ng++) {
                int row = wn*32 + ng*16 + ii + (gi >> 1)*8;
                int col = ks*16 + (gi & 1)*8;
                ldsm4(bhf[ng], s2u(&Bh[row*GSTR + col]));
                ldsm4(blf[ng], s2u(&Bl[row*GSTR + col]));
            }
            #pragma unroll
            for (int mi = 0; mi < 2; mi++)
                #pragma unroll
                for (int ng = 0; ng < 2; ng++) {
                    mma16816(c[mi][2*ng],   ah[mi], &bhf[ng][0]);
                    mma16816(c[mi][2*ng],   ah[mi], &blf[ng][0]);
                    mma16816(c[mi][2*ng],   al[mi], &bhf[ng][0]);
                    mma16816(c[mi][2*ng+1], ah[mi], &bhf[ng][2]);
                    mma16816(c[mi][2*ng+1], ah[mi], &blf[ng][2]);
                    mma16816(c[mi][2*ng+1], al[mi], &bhf[ng][2]);
                }
        }
    }

    // epilogue: bias + scatter. Q/K -> fp32 (rope next); V -> split bf16.
    #pragma unroll
    for (int mi = 0; mi < 2; mi++)
        #pragma unroll
        for (int ni = 0; ni < 4; ni++)
            #pragma unroll
            for (int e = 0; e < 4; e++) {
                int m = by*128 + wm*32 + mi*16 + (lane >> 2) + ((e >= 2) ? 8 : 0);
                int n = n0 + wn*32 + ni*8 + 2*(lane & 3) + (e & 1);
                int b_ = m >> 11, s = m & 2047;
                float val = c[mi][ni][e] + bias[n - noff];
                if (n < 1024) {
                    int h = n >> 6, d = n & 63;
                    g_q[(((size_t)b_*NH + h)*SS + s)*HD + d] = val;
                } else if (n < 1280) {
                    int nn = n - 1024; int h = nn >> 6, d = nn & 63;
                    g_k[(((size_t)b_*NKV + h)*SS + s)*HD + d] = val;
                } else {
                    int nn = n - 1280; int h = nn >> 6, d = nn & 63;
                    size_t off = (((size_t)b_*NKV + h)*SS + s)*HD + d;
                    __nv_bfloat16 hh, ll; split1(val, hh, ll);
                    g_vh[off] = hh; g_vl[off] = ll;
                }
            }
}

// ---------------- RoPE + split (q: scaled; k: unscaled) ---------------------
__global__ void rope_split(int which, const float* __restrict__ cos_t,
                           const float* __restrict__ sin_t, int total)
{
    int idx = blockIdx.x * blockDim.x + threadIdx.x;
    if (idx >= total) return;
    int d  = idx & 31;
    int s  = (idx >> 5) & 2047;
    int bh = idx >> 16;
    const float* src = which ? g_k : g_q;
    __nv_bfloat16* dh = which ? g_kh : g_qh;
    __nv_bfloat16* dl = which ? g_kl : g_ql;
    float scale = which ? 1.0f : SCALE_F;
    size_t base = ((size_t)bh*SS + s)*HD;
    float x1 = src[base + d], x2 = src[base + d + 32];
    float c1 = cos_t[s*HD + d],      s1 = sin_t[s*HD + d];
    float c2 = cos_t[s*HD + d + 32], s2 = sin_t[s*HD + d + 32];
    float y1 = (x1*c1 - x2*s1) * scale;
    float y2 = (x2*c2 + x1*s2) * scale;
    __nv_bfloat16 hh, ll;
    split1(y1, hh, ll); dh[base + d]      = hh; dl[base + d]      = ll;
    split1(y2, hh, ll); dh[base + d + 32] = hh; dl[base + d + 32] = ll;
}

// ---------------- flash attention (64 q-rows, 64-key tiles, ldmatrix) -------
#define FSTR 72   // 64 + 8 pad bf16 (144B stride, conflict-free for ldsm)

__global__ __launch_bounds__(128) void flash_kernel()
{
    __shared__ __nv_bfloat16 Kh[64*FSTR], Kl[64*FSTR];
    __shared__ __nv_bfloat16 Vh[64*FSTR], Vl[64*FSTR];

    const int b = blockIdx.z, h = blockIdx.y, qt = blockIdx.x;
    const int tid = threadIdx.x, lane = tid & 31, warp = tid >> 5;
    const int hk = h / GROUPS;
    const int gi = lane >> 3, ii = lane & 7;

    const __nv_bfloat16* qhg = g_qh + (((size_t)b*NH  + h )*SS + qt*64)*HD;
    const __nv_bfloat16* qlg = g_ql + (((size_t)b*NH  + h )*SS + qt*64)*HD;
    const __nv_bfloat16* khg = g_kh + (((size_t)b*NKV + hk)*SS)*HD;
    const __nv_bfloat16* klg = g_kl + (((size_t)b*NKV + hk)*SS)*HD;
    const __nv_bfloat16* vhg = g_vh + (((size_t)b*NKV + hk)*SS)*HD;
    const __nv_bfloat16* vlg = g_vl + (((size_t)b*NKV + hk)*SS)*HD;

    // stage Q tile through K smem, grab fragments
    #pragma unroll
    for (int p = 0; p < 4; p++) {
        int cidx = tid + p*128;               // 0..511
        int row = cidx >> 3, ch = cidx & 7;
        size_t so = (size_t)row*HD + ch*8;
        cpa16(&Kh[row*FSTR + ch*8], qhg + so);
        cpa16(&Kl[row*FSTR + ch*8], qlg + so);
    }
    cpa_wait();
    __syncthreads();

    uint32_t qh[4][4], ql[4][4];
    #pragma unroll
    for (int kk = 0; kk < 4; kk++) {
        int row = warp*16 + ii + (gi & 1)*8;
        int col = kk*16 + (gi >> 1)*8;
        ldsm4(qh[kk], s2u(&Kh[row*FSTR + col]));
        ldsm4(ql[kk], s2u(&Kl[row*FSTR + col]));
    }
    __syncthreads();

    float o[8][4];
    #pragma unroll
    for (int i = 0; i < 8; i++) for (int j = 0; j < 4; j++) o[i][j] = 0.f;
    float m0 = -1e30f, m1 = -1e30f, l0 = 0.f, l1 = 0.f;

    for (int t = 0; t < SS/64; t++) {
        // load K/V tile (prev readers done: sync at loop end / Q-stage sync)
        #pragma unroll
        for (int p = 0; p < 4; p++) {
            int cidx = tid + p*128;
            int row = cidx >> 3, ch = cidx & 7;
            size_t so = ((size_t)t*64 + row)*HD + ch*8;
            cpa16(&Kh[row*FSTR + ch*8], khg + so);
            cpa16(&Kl[row*FSTR + ch*8], klg + so);
            cpa16(&Vh[row*FSTR + ch*8], vhg + so);
            cpa16(&Vl[row*FSTR + ch*8], vlg + so);
        }
        cpa_wait();
        __syncthreads();

        // S = Q K^T  (16 q-rows x 64 keys per warp)
        float s[8][4];
        #pragma unroll
        for (int i = 0; i < 8; i++) for (int j = 0; j < 4; j++) s[i][j] = 0.f;
        #pragma unroll
        for (int kk = 0; kk < 4; kk++) {
            int col = kk*16 + (gi & 1)*8;
            #pragma unroll
            for (int ng = 0; ng < 4; ng++) {
                int row = ng*16 + ii + (gi >> 1)*8;
                uint32_t bh[4], bl[4];
                ldsm4(bh, s2u(&Kh[row*FSTR + col]));
                ldsm4(bl, s2u(&Kl[row*FSTR + col]));
                mma16816(s[2*ng],   qh[kk], &bh[0]);
                mma16816(s[2*ng],   qh[kk], &bl[0]);
                mma16816(s[2*ng],   ql[kk], &bh[0]);
                mma16816(s[2*ng+1], qh[kk], &bh[2]);
                mma16816(s[2*ng+1], qh[kk], &bl[2]);
                mma16816(s[2*ng+1], ql[kk], &bh[2]);
            }
        }

        // online softmax (row r0 = lane>>2 : c0,c1 ; row r0+8 : c2,c3)
        float mx0 = -1e30f, mx1 = -1e30f;
        #pragma unroll
        for (int nt = 0; nt < 8; nt++) {
            mx0 = fmaxf(mx0, fmaxf(s[nt][0], s[nt][1]));
            mx1 = fmaxf(mx1, fmaxf(s[nt][2], s[nt][3]));
        }
        mx0 = fmaxf(mx0, __shfl_xor_sync(0xffffffffu, mx0, 1));
        mx0 = fmaxf(mx0, __shfl_xor_sync(0xffffffffu, mx0, 2));
        mx1 = fmaxf(mx1, __shfl_xor_sync(0xffffffffu, mx1, 1));
        mx1 = fmaxf(mx1, __shfl_xor_sync(0xffffffffu, mx1, 2));
        float nm0 = fmaxf(m0, mx0), nm1 = fmaxf(m1, mx1);
        float cr0 = __expf(m0 - nm0), cr1 = __expf(m1 - nm1);
        m0 = nm0; m1 = nm1;
        float sp0 = 0.f, sp1 = 0.f;
        #pragma unroll
        for (int nt = 0; nt < 8; nt++) {
            s[nt][0] = __expf(s[nt][0] - m0); sp0 += s[nt][0];
            s[nt][1] = __expf(s[nt][1] - m0); sp0 += s[nt][1];
            s[nt][2] = __expf(s[nt][2] - m1); sp1 += s[nt][2];
            s[nt][3] = __expf(s[nt][3] - m1); sp1 += s[nt][3];
        }
        l0 = l0*cr0 + sp0;
        l1 = l1*cr1 + sp1;
        #pragma unroll
        for (int nb = 0; nb < 8; nb++) {
            o[nb][0] *= cr0; o[nb][1] *= cr0;
            o[nb][2] *= cr1; o[nb][3] *= cr1;
        }

        // O += P V  (P fragments built in-register from s)
        #pragma unroll
        for (int ks = 0; ks < 4; ks++) {
            uint32_t pah[4], pal[4];
            {
                const float* s0 = s[2*ks];
                const float* s1 = s[2*ks+1];
                __nv_bfloat16 h0,h1,l0_,l1_;
                split1(s0[0],h0,l0_); split1(s0[1],h1,l1_);
                pah[0] = packbf2(h0,h1); pal[0] = packbf2(l0_,l1_);
                split1(s0[2],h0,l0_); split1(s0[3],h1,l1_);
                pah[1] = packbf2(h0,h1); pal[1] = packbf2(l0_,l1_);
                split1(s1[0],h0,l0_); split1(s1[1],h1,l1_);
                pah[2] = packbf2(h0,h1); pal[2] = packbf2(l0_,l1_);
                split1(s1[2],h0,l0_); split1(s1[3],h1,l1_);
                pah[3] = packbf2(h0,h1); pal[3] = packbf2(l0_,l1_);
            }
            #pragma unroll
            for (int dg = 0; dg < 4; dg++) {
                int row = ks*16 + ii + (gi & 1)*8;   // key
                int col = dg*16 + (gi >> 1)*8;       // d
                uint32_t bh[4], bl[4];
                ldsm4t(bh, s2u(&Vh[row*FSTR + col]));
                ldsm4t(bl, s2u(&Vl[row*FSTR + col]));
                mma16816(o[2*dg],   pah, &bh[0]);
                mma16816(o[2*dg],   pah, &bl[0]);
                mma16816(o[2*dg],   pal, &bh[0]);
                mma16816(o[2*dg+1], pah, &bh[2]);
                mma16816(o[2*dg+1], pah, &bl[2]);
                mma16816(o[2*dg+1], pal, &bh[2]);
            }
        }
        __syncthreads();
    }

    // finalize
    l0 += __shfl_xor_sync(0xffffffffu, l0, 1);
    l0 += __shfl_xor_sync(0xffffffffu, l0, 2);
    l1 += __shfl_xor_sync(0xffffffffu, l1, 1);
    l1 += __shfl_xor_sync(0xffffffffu, l1, 2);
    float inv0 = 1.f / l0, inv1 = 1.f / l1;

    int r0 = qt*64 + warp*16 + (lane >> 2);
    size_t o0 = ((size_t)b*SS + r0    )*(NH*HD) + h*HD;
    size_t o1 = ((size_t)b*SS + r0 + 8)*(NH*HD) + h*HD;
    #pragma unroll
    for (int nb = 0; nb < 8; nb++) {
        int d = nb*8 + 2*(lane & 3);
        __nv_bfloat16 h0,h1,l0_,l1_;
        split1(o[nb][0]*inv0, h0, l0_); split1(o[nb][1]*inv0, h1, l1_);
        *(__nv_bfloat162*)&g_aoh[o0 + d] = __nv_bfloat162(h0,h1);
        *(__nv_bfloat162*)&g_aol[o0 + d] = __nv_bfloat162(l0_,l1_);
        split1(o[nb][2]*inv1, h0, l0_); split1(o[nb][3]*inv1, h1, l1_);
        *(__nv_bfloat162*)&g_aoh[o1 + d] = __nv_bfloat162(h0,h1);
        *(__nv_bfloat162*)&g_aol[o1 + d] = __nv_bfloat162(l0_,l1_);
    }
}

// ---------------- O-proj GEMM ----------------------------------------------
__global__ __launch_bounds__(256) void oproj_gemm(
    const float* __restrict__ bo, float* __restrict__ C)
{
    __shared__ __nv_bfloat16 Ah[128*GSTR], Al[128*GSTR];
    __shared__ __nv_bfloat16 Bh[64*GSTR],  Bl[64*GSTR];

    const int tid = threadIdx.x, lane = tid & 31, warp = tid >> 5;
    const int wm = warp & 3, wn = warp >> 2;
    const int gi = lane >> 3, ii = lane & 7;
    const int bx = blockIdx.x, by = blockIdx.y;
    const int n0 = bx * 64;

    float c[2][4][4];
    #pragma unroll
    for (int i=0;i<2;i++) for (int j=0;j<4;j++) for (int e=0;e<4;e++) c[i][j][e]=0.f;

    for (int kt = 0; kt < HIDD; kt += 32) {
        __syncthreads();
        #pragma unroll
        for (int p = 0; p < 2; p++) {
            int cidx = tid + p*256;
            int row = cidx >> 2, ch = cidx & 3;
            size_t so = (size_t)(by*128 + row)*HIDD + kt + ch*8;
            cpa16(&Ah[row*GSTR + ch*8], &g_aoh[so]);
            cpa16(&Al[row*GSTR + ch*8], &g_aol[so]);
        }
        {
            int row = tid >> 2, ch = tid & 3;
            size_t so = (size_t)(n0 + row)*HIDD + kt + ch*8;
            cpa16(&Bh[row*GSTR + ch*8], &g_woh[so]);
            cpa16(&Bl[row*GSTR + ch*8], &g_wol[so]);
        }
        cpa_wait();
        __syncthreads();

        #pragma unroll
        for (int ks = 0; ks < 2; ks++) {
            uint32_t ah[2][4], al[2][4], bhf[2][4], blf[2][4];
            #pragma unroll
            for (int mi = 0; mi < 2; mi++) {
                int row = wm*32 + mi*16 + ii + (gi & 1)*8;
                int col = ks*16 + (gi >> 1)*8;
                ldsm4(ah[mi], s2u(&Ah[row*GSTR + col]));
                ldsm4(al[mi], s2u(&Al[row*GSTR + col]));
            }
            #pragma unroll
            for (int ng = 0; ng < 2; ng++) {
                int row = wn*32 + ng*16 + ii + (gi >> 1)*8;
                int col = ks*16 + (gi & 1)*8;
                ldsm4(bhf[ng], s2u(&Bh[row*GSTR + col]));
                ldsm4(blf[ng], s2u(&Bl[row*GSTR + col]));
            }
            #pragma unroll
            for (int mi = 0; mi < 2; mi++)
                #pragma unroll
                for (int ng = 0; ng < 2; ng++) {
                    mma16816(c[mi][2*ng],   ah[mi], &bhf[ng][0]);
                    mma16816(c[mi][2*ng],   ah[mi], &blf[ng][0]);
                    mma16816(c[mi][2*ng],   al[mi], &bhf[ng][0]);
                    mma16816(c[mi][2*ng+1], ah[mi], &bhf[ng][2]);
                    mma16816(c[mi][2*ng+1], ah[mi], &blf[ng][2]);
                    mma16816(c[mi][2*ng+1], al[mi], &bhf[ng][2]);
                }
        }
    }

    #pragma unroll
    for (int mi = 0; mi < 2; mi++)
        #pragma unroll
        for (int ni = 0; ni < 4; ni++)
            #pragma unroll
            for (int e = 0; e < 4; e++) {
                int m = by*128 + wm*32 + mi*16 + (lane >> 2) + ((e >= 2) ? 8 : 0);
                int n = n0 + wn*32 + ni*8 + 2*(lane & 3) + (e & 1);
                C[(size_t)m*HIDD + n] = c[mi][ni][e] + bo[n];
            }
}

// ---------------------------------------------------------------------------
extern "C" void kernel_launch(void* const* d_in, const int* in_sizes, int n_in,
                              void* d_out, int out_size)
{
    const float* X    = (const float*)d_in[0];
    const float* cosp = (const float*)d_in[1];
    const float* sinp = (const float*)d_in[2];
    const float* Wq   = (const float*)d_in[3];
    const float* bq   = (const float*)d_in[4];
    const float* Wk   = (const float*)d_in[5];
    const float* bk   = (const float*)d_in[6];
    const float* Wv   = (const float*)d_in[7];
    const float* bv   = (const float*)d_in[8];
    const float* Wo   = (const float*)d_in[9];
    const float* bo   = (const float*)d_in[10];
    float* out = (float*)d_out;

    // 0. pre-split X and weights to (hi,lo) bf16
    int nx = BB*SS*HIDD/4;
    split_kernel<<<(nx+255)/256, 256>>>(X, 0, nx);
    int nwq = NH*HD*HIDD/4;
    split_kernel<<<(nwq+255)/256, 256>>>(Wq, 1, nwq);
    int nwk = NKV*HD*HIDD/4;
    split_kernel<<<(nwk+255)/256, 256>>>(Wk, 2, nwk);
    split_kernel<<<(nwk+255)/256, 256>>>(Wv, 3, nwk);
    split_kernel<<<(nwq+255)/256, 256>>>(Wo, 4, nwq);

    // 1. QKV projection
    dim3 g1(1536/64, 8192/128);
    qkv_gemm<<<g1, 256>>>(bq, bk, bv);

    // 2. RoPE + split (q scaled)
    int tq = BB*NH *SS*32;
    int tk = BB*NKV*SS*32;
    rope_split<<<(tq+255)/256, 256>>>(0, cosp, sinp, tq);
    rope_split<<<(tk+255)/256, 256>>>(1, cosp, sinp, tk);

    // 3. flash attention
    dim3 g3(SS/64, NH, BB);
    flash_kernel<<<g3, 128>>>();

    // 4. O-proj
    dim3 g4(1024/64, 8192/128);
    oproj_gemm<<<g4, 256>>>(bo, out);
}

// round 6
// speedup vs baseline: 3.4888x; 1.1075x over previous
#include <cuda_runtime.h>
#include <cuda_bf16.h>
#include <cstdint>

#define BB   4
#define SS   2048
#define HIDD 1024
#define NH   16
#define NKV  4
#define HD   64
#define GROUPS 4
#define SCALE_F 0.125f

// ---------------- scratch (__device__ globals, allocation-free) -------------
__device__ float g_q[BB*NH*SS*HD];
__device__ float g_k[BB*NKV*SS*HD];
__device__ __nv_bfloat16 g_qh[BB*NH*SS*HD],  g_ql[BB*NH*SS*HD];
__device__ __nv_bfloat16 g_kh[BB*NKV*SS*HD], g_kl[BB*NKV*SS*HD];
__device__ __nv_bfloat16 g_vh[BB*NKV*SS*HD], g_vl[BB*NKV*SS*HD];
__device__ __nv_bfloat16 g_xh[BB*SS*HIDD],   g_xl[BB*SS*HIDD];
__device__ __nv_bfloat16 g_aoh[BB*SS*NH*HD], g_aol[BB*SS*NH*HD];
__device__ __nv_bfloat16 g_wqh[NH*HD*HIDD],  g_wql[NH*HD*HIDD];
__device__ __nv_bfloat16 g_wkh[NKV*HD*HIDD], g_wkl[NKV*HD*HIDD];
__device__ __nv_bfloat16 g_wvh[NKV*HD*HIDD], g_wvl[NKV*HD*HIDD];
__device__ __nv_bfloat16 g_woh[HIDD*NH*HD],  g_wol[HIDD*NH*HD];

// ---------------- helpers ---------------------------------------------------
__device__ __forceinline__ uint32_t s2u(const void* p) {
    return (uint32_t)__cvta_generic_to_shared(p);
}
__device__ __forceinline__ void mma16816(float* c, const uint32_t* a, const uint32_t* b) {
    asm volatile(
        "mma.sync.aligned.m16n8k16.row.col.f32.bf16.bf16.f32 "
        "{%0,%1,%2,%3}, {%4,%5,%6,%7}, {%8,%9}, {%0,%1,%2,%3};"
        : "+f"(c[0]), "+f"(c[1]), "+f"(c[2]), "+f"(c[3])
        : "r"(a[0]), "r"(a[1]), "r"(a[2]), "r"(a[3]), "r"(b[0]), "r"(b[1]));
}
__device__ __forceinline__ void ldsm4(uint32_t* r, uint32_t addr) {
    asm volatile("ldmatrix.sync.aligned.m8n8.x4.shared.b16 {%0,%1,%2,%3}, [%4];"
        : "=r"(r[0]), "=r"(r[1]), "=r"(r[2]), "=r"(r[3]) : "r"(addr));
}
__device__ __forceinline__ void ldsm4t(uint32_t* r, uint32_t addr) {
    asm volatile("ldmatrix.sync.aligned.m8n8.x4.trans.shared.b16 {%0,%1,%2,%3}, [%4];"
        : "=r"(r[0]), "=r"(r[1]), "=r"(r[2]), "=r"(r[3]) : "r"(addr));
}
__device__ __forceinline__ void cpa16(void* dst, const void* src) {
    asm volatile("cp.async.cg.shared.global [%0], [%1], 16;" :: "r"(s2u(dst)), "l"(src));
}
__device__ __forceinline__ void cpa_commit() {
    asm volatile("cp.async.commit_group;");
}
__device__ __forceinline__ void cpa_wait0() {
    asm volatile("cp.async.wait_group 0;" ::: "memory");
}
__device__ __forceinline__ void split1(float x, __nv_bfloat16& h, __nv_bfloat16& l) {
    h = __float2bfloat16(x);
    l = __float2bfloat16(x - __bfloat162float(h));
}
__device__ __forceinline__ uint32_t packbf2(__nv_bfloat16 a, __nv_bfloat16 b) {
    __nv_bfloat162 t; t.x = a; t.y = b;
    return *(uint32_t*)&t;
}
__device__ __forceinline__ void split4_store(float4 v, __nv_bfloat16* H, __nv_bfloat16* L) {
    __nv_bfloat16 h0,h1,h2,h3,l0,l1,l2,l3;
    split1(v.x,h0,l0); split1(v.y,h1,l1); split1(v.z,h2,l2); split1(v.w,h3,l3);
    ((__nv_bfloat162*)H)[0] = __nv_bfloat162(h0,h1);
    ((__nv_bfloat162*)H)[1] = __nv_bfloat162(h2,h3);
    ((__nv_bfloat162*)L)[0] = __nv_bfloat162(l0,l1);
    ((__nv_bfloat162*)L)[1] = __nv_bfloat162(l2,l3);
}

// ---------------- generic fp32 -> (hi,lo) bf16 split ------------------------
__global__ void split_kernel(const float* __restrict__ src, int which, int n4) {
    int i = blockIdx.x * blockDim.x + threadIdx.x;
    if (i >= n4) return;
    __nv_bfloat16 *h, *l;
    switch (which) {
        case 0: h = g_xh;  l = g_xl;  break;
        case 1: h = g_wqh; l = g_wql; break;
        case 2: h = g_wkh; l = g_wkl; break;
        case 3: h = g_wvh; l = g_wvl; break;
        default: h = g_woh; l = g_wol; break;
    }
    float4 v = *(const float4*)&src[(size_t)i*4];
    split4_store(v, &h[(size_t)i*4], &l[(size_t)i*4]);
}

// ---------------- GEMM common (BM128 BN64 BK32, 2-stage pipeline) -----------
#define GSTR 40
#define G_AO  0        // Ah offset (elems)
#define G_AL  5120
#define G_BH  10240
#define G_BL  12800
#define G_STAGE_E 15360  // elems per stage (30720 B)

__device__ __forceinline__ void load_gemm_tile(__nv_bfloat16* st,
    const __nv_bfloat16* Ahg, const __nv_bfloat16* Alg,
    const __nv_bfloat16* Bhg, const __nv_bfloat16* Blg,
    int arow0, int brow0, int kt, int tid)
{
    #pragma unroll
    for (int p = 0; p < 2; p++) {
        int cidx = tid + p*256;
        int row = cidx >> 2, ch = (cidx & 3)*8;
        size_t so = (size_t)(arow0 + row)*HIDD + kt + ch;
        cpa16(&st[G_AO + row*GSTR + ch], Ahg + so);
        cpa16(&st[G_AL + row*GSTR + ch], Alg + so);
    }
    {
        int row = tid >> 2, ch = (tid & 3)*8;
        size_t so = (size_t)(brow0 + row)*HIDD + kt + ch;
        cpa16(&st[G_BH + row*GSTR + ch], Bhg + so);
        cpa16(&st[G_BL + row*GSTR + ch], Blg + so);
    }
    cpa_commit();
}

// computes one 32-k-step of MMAs from stage st into c
__device__ __forceinline__ void gemm_compute(const __nv_bfloat16* st,
    float c[2][4][4], int wm, int wn, int gi, int ii)
{
    #pragma unroll
    for (int ks = 0; ks < 2; ks++) {
        uint32_t ah[2][4], al[2][4], bhf[2][4], blf[2][4];
        #pragma unroll
        for (int mi = 0; mi < 2; mi++) {
            int row = wm*32 + mi*16 + ii + (gi & 1)*8;
            int col = ks*16 + (gi >> 1)*8;
            ldsm4(ah[mi], s2u(&st[G_AO + row*GSTR + col]));
            ldsm4(al[mi], s2u(&st[G_AL + row*GSTR + col]));
        }
        #pragma unroll
        for (int ng = 0; ng < 2; ng++) {
            int row = wn*32 + ng*16 + ii + (gi >> 1)*8;
            int col = ks*16 + (gi & 1)*8;
            ldsm4(bhf[ng], s2u(&st[G_BH + row*GSTR + col]));
            ldsm4(blf[ng], s2u(&st[G_BL + row*GSTR + col]));
        }
        #pragma unroll
        for (int mi = 0; mi < 2; mi++)
            #pragma unroll
            for (int ng = 0; ng < 2; ng++) {
                mma16816(c[mi][2*ng],   ah[mi], &bhf[ng][0]);
                mma16816(c[mi][2*ng],   ah[mi], &blf[ng][0]);
                mma16816(c[mi][2*ng],   al[mi], &bhf[ng][0]);
                mma16816(c[mi][2*ng+1], ah[mi], &bhf[ng][2]);
                mma16816(c[mi][2*ng+1], ah[mi], &blf[ng][2]);
                mma16816(c[mi][2*ng+1], al[mi], &bhf[ng][2]);
            }
    }
}

// ---------------- QKV GEMM ---------------------------------------------------
__global__ __launch_bounds__(256) void qkv_gemm(
    const float* __restrict__ bq, const float* __restrict__ bk, const float* __restrict__ bv)
{
    extern __shared__ __nv_bfloat16 gsm[];
    const int tid = threadIdx.x, lane = tid & 31, warp = tid >> 5;
    const int wm = warp & 3, wn = warp >> 2;
    const int gi = lane >> 3, ii = lane & 7;
    const int bx = blockIdx.x, by = blockIdx.y;
    const int n0 = bx * 64;

    const __nv_bfloat16 *Wh, *Wl; const float* bias; int noff;
    if (n0 < 1024)      { Wh = g_wqh; Wl = g_wql; bias = bq; noff = 0;    }
    else if (n0 < 1280) { Wh = g_wkh; Wl = g_wkl; bias = bk; noff = 1024; }
    else                { Wh = g_wvh; Wl = g_wvl; bias = bv; noff = 1280; }

    float c[2][4][4];
    #pragma unroll
    for (int i=0;i<2;i++) for (int j=0;j<4;j++) for (int e=0;e<4;e++) c[i][j][e]=0.f;

    load_gemm_tile(gsm, g_xh, g_xl, Wh, Wl, by*128, n0 - noff, 0, tid);

    for (int t = 0; t < 32; t++) {
        cpa_wait0();
        __syncthreads();
        if (t < 31)
            load_gemm_tile(gsm + ((t+1)&1)*G_STAGE_E, g_xh, g_xl, Wh, Wl,
                           by*128, n0 - noff, (t+1)*32, tid);
        gemm_compute(gsm + (t&1)*G_STAGE_E, c, wm, wn, gi, ii);
    }

    // epilogue: bias + scatter. Q/K -> fp32 (rope next); V -> split bf16.
    #pragma unroll
    for (int mi = 0; mi < 2; mi++)
        #pragma unroll
        for (int ni = 0; ni < 4; ni++)
            #pragma unroll
            for (int e = 0; e < 4; e++) {
                int m = by*128 + wm*32 + mi*16 + (lane >> 2) + ((e >= 2) ? 8 : 0);
                int n = n0 + wn*32 + ni*8 + 2*(lane & 3) + (e & 1);
                int b_ = m >> 11, s = m & 2047;
                float val = c[mi][ni][e] + bias[n - noff];
                if (n < 1024) {
                    int h = n >> 6, d = n & 63;
                    g_q[(((size_t)b_*NH + h)*SS + s)*HD + d] = val;
                } else if (n < 1280) {
                    int nn = n - 1024; int h = nn >> 6, d = nn & 63;
                    g_k[(((size_t)b_*NKV + h)*SS + s)*HD + d] = val;
                } else {
                    int nn = n - 1280; int h = nn >> 6, d = nn & 63;
                    size_t off = (((size_t)b_*NKV + h)*SS + s)*HD + d;
                    __nv_bfloat16 hh, ll; split1(val, hh, ll);
                    g_vh[off] = hh; g_vl[off] = ll;
                }
            }
}

// ---------------- RoPE + split (q: scaled; k: unscaled) ---------------------
__global__ void rope_split(int which, const float* __restrict__ cos_t,
                           const float* __restrict__ sin_t, int total)
{
    int idx = blockIdx.x * blockDim.x + threadIdx.x;
    if (idx >= total) return;
    int d  = idx & 31;
    int s  = (idx >> 5) & 2047;
    int bh = idx >> 16;
    const float* src = which ? g_k : g_q;
    __nv_bfloat16* dh = which ? g_kh : g_qh;
    __nv_bfloat16* dl = which ? g_kl : g_ql;
    float scale = which ? 1.0f : SCALE_F;
    size_t base = ((size_t)bh*SS + s)*HD;
    float x1 = src[base + d], x2 = src[base + d + 32];
    float c1 = cos_t[s*HD + d],      s1 = sin_t[s*HD + d];
    float c2 = cos_t[s*HD + d + 32], s2 = sin_t[s*HD + d + 32];
    float y1 = (x1*c1 - x2*s1) * scale;
    float y2 = (x2*c2 + x1*s2) * scale;
    __nv_bfloat16 hh, ll;
    split1(y1, hh, ll); dh[base + d]      = hh; dl[base + d]      = ll;
    split1(y2, hh, ll); dh[base + d + 32] = hh; dl[base + d + 32] = ll;
}

// ---------------- flash attention (64 q-rows, 64-key tiles, 2-stage) --------
#define FSTR 72
#define F_ARR (64*FSTR)           // elems per array
#define F_STAGE_E (4*F_ARR)       // elems per stage (Kh,Kl,Vh,Vl)

__device__ __forceinline__ void load_kv_tile(__nv_bfloat16* st,
    const __nv_bfloat16* khg, const __nv_bfloat16* klg,
    const __nv_bfloat16* vhg, const __nv_bfloat16* vlg, int t, int tid)
{
    #pragma unroll
    for (int p = 0; p < 4; p++) {
        int cidx = tid + p*128;
        int row = cidx >> 3, ch = (cidx & 7)*8;
        size_t so = ((size_t)t*64 + row)*HD + ch;
        cpa16(&st[            row*FSTR + ch], khg + so);
        cpa16(&st[  F_ARR   + row*FSTR + ch], klg + so);
        cpa16(&st[2*F_ARR   + row*FSTR + ch], vhg + so);
        cpa16(&st[3*F_ARR   + row*FSTR + ch], vlg + so);
    }
    cpa_commit();
}

__global__ __launch_bounds__(128) void flash_kernel()
{
    extern __shared__ __nv_bfloat16 fsm[];

    const int b = blockIdx.z, h = blockIdx.y, qt = blockIdx.x;
    const int tid = threadIdx.x, lane = tid & 31, warp = tid >> 5;
    const int hk = h / GROUPS;
    const int gi = lane >> 3, ii = lane & 7;

    const __nv_bfloat16* qhg = g_qh + (((size_t)b*NH  + h )*SS + qt*64)*HD;
    const __nv_bfloat16* qlg = g_ql + (((size_t)b*NH  + h )*SS + qt*64)*HD;
    const __nv_bfloat16* khg = g_kh + (((size_t)b*NKV + hk)*SS)*HD;
    const __nv_bfloat16* klg = g_kl + (((size_t)b*NKV + hk)*SS)*HD;
    const __nv_bfloat16* vhg = g_vh + (((size_t)b*NKV + hk)*SS)*HD;
    const __nv_bfloat16* vlg = g_vl + (((size_t)b*NKV + hk)*SS)*HD;

    // ---- stage Q through stage-0 smem, grab fragments ----
    {
        __nv_bfloat16* Qh = fsm;
        __nv_bfloat16* Ql = fsm + F_ARR;
        #pragma unroll
        for (int p = 0; p < 4; p++) {
            int cidx = tid + p*128;
            int row = cidx >> 3, ch = (cidx & 7)*8;
            size_t so = (size_t)row*HD + ch;
            cpa16(&Qh[row*FSTR + ch], qhg + so);
            cpa16(&Ql[row*FSTR + ch], qlg + so);
        }
        cpa_commit();
        cpa_wait0();
        __syncthreads();
    }

    uint32_t qh[4][4], ql[4][4];
    #pragma unroll
    for (int kk = 0; kk < 4; kk++) {
        int row = warp*16 + ii + (gi & 1)*8;
        int col = kk*16 + (gi >> 1)*8;
        ldsm4(qh[kk], s2u(&fsm[         row*FSTR + col]));
        ldsm4(ql[kk], s2u(&fsm[F_ARR + row*FSTR + col]));
    }
    __syncthreads();

    // prologue: tile 0 into stage 0
    load_kv_tile(fsm, khg, klg, vhg, vlg, 0, tid);

    float o[8][4];
    #pragma unroll
    for (int i = 0; i < 8; i++) for (int j = 0; j < 4; j++) o[i][j] = 0.f;
    float m0 = -1e30f, m1 = -1e30f, l0 = 0.f, l1 = 0.f;

    for (int t = 0; t < SS/64; t++) {
        cpa_wait0();
        __syncthreads();
        if (t < SS/64 - 1)
            load_kv_tile(fsm + ((t+1)&1)*F_STAGE_E, khg, klg, vhg, vlg, t+1, tid);

        const __nv_bfloat16* Kh = fsm + (t&1)*F_STAGE_E;
        const __nv_bfloat16* Kl = Kh + F_ARR;
        const __nv_bfloat16* Vh = Kh + 2*F_ARR;
        const __nv_bfloat16* Vl = Kh + 3*F_ARR;

        // S = Q K^T  (16 q-rows x 64 keys per warp)
        float s[8][4];
        #pragma unroll
        for (int i = 0; i < 8; i++) for (int j = 0; j < 4; j++) s[i][j] = 0.f;
        #pragma unroll
        for (int kk = 0; kk < 4; kk++) {
            int col = kk*16 + (gi & 1)*8;
            #pragma unroll
            for (int ng = 0; ng < 4; ng++) {
                int row = ng*16 + ii + (gi >> 1)*8;
                uint32_t bh[4], bl[4];
                ldsm4(bh, s2u(&Kh[row*FSTR + col]));
                ldsm4(bl, s2u(&Kl[row*FSTR + col]));
                mma16816(s[2*ng],   qh[kk], &bh[0]);
                mma16816(s[2*ng],   qh[kk], &bl[0]);
                mma16816(s[2*ng],   ql[kk], &bh[0]);
                mma16816(s[2*ng+1], qh[kk], &bh[2]);
                mma16816(s[2*ng+1], qh[kk], &bl[2]);
                mma16816(s[2*ng+1], ql[kk], &bh[2]);
            }
        }

        // online softmax
        float mx0 = -1e30f, mx1 = -1e30f;
        #pragma unroll
        for (int nt = 0; nt < 8; nt++) {
            mx0 = fmaxf(mx0, fmaxf(s[nt][0], s[nt][1]));
            mx1 = fmaxf(mx1, fmaxf(s[nt][2], s[nt][3]));
        }
        mx0 = fmaxf(mx0, __shfl_xor_sync(0xffffffffu, mx0, 1));
        mx0 = fmaxf(mx0, __shfl_xor_sync(0xffffffffu, mx0, 2));
        mx1 = fmaxf(mx1, __shfl_xor_sync(0xffffffffu, mx1, 1));
        mx1 = fmaxf(mx1, __shfl_xor_sync(0xffffffffu, mx1, 2));
        float nm0 = fmaxf(m0, mx0), nm1 = fmaxf(m1, mx1);
        float cr0 = __expf(m0 - nm0), cr1 = __expf(m1 - nm1);
        m0 = nm0; m1 = nm1;
        float sp0 = 0.f, sp1 = 0.f;
        #pragma unroll
        for (int nt = 0; nt < 8; nt++) {
            s[nt][0] = __expf(s[nt][0] - m0); sp0 += s[nt][0];
            s[nt][1] = __expf(s[nt][1] - m0); sp0 += s[nt][1];
            s[nt][2] = __expf(s[nt][2] - m1); sp1 += s[nt][2];
            s[nt][3] = __expf(s[nt][3] - m1); sp1 += s[nt][3];
        }
        l0 = l0*cr0 + sp0;
        l1 = l1*cr1 + sp1;
        #pragma unroll
        for (int nb = 0; nb < 8; nb++) {
            o[nb][0] *= cr0; o[nb][1] *= cr0;
            o[nb][2] *= cr1; o[nb][3] *= cr1;
        }

        // O += P V
        #pragma unroll
        for (int ks = 0; ks < 4; ks++) {
            uint32_t pah[4], pal[4];
            {
                const float* s0 = s[2*ks];
                const float* s1 = s[2*ks+1];
                __nv_bfloat16 h0,h1,l0_,l1_;
                split1(s0[0],h0,l0_); split1(s0[1],h1,l1_);
                pah[0] = packbf2(h0,h1); pal[0] = packbf2(l0_,l1_);
                split1(s0[2],h0,l0_); split1(s0[3],h1,l1_);
                pah[1] = packbf2(h0,h1); pal[1] = packbf2(l0_,l1_);
                split1(s1[0],h0,l0_); split1(s1[1],h1,l1_);
                pah[2] = packbf2(h0,h1); pal[2] = packbf2(l0_,l1_);
                split1(s1[2],h0,l0_); split1(s1[3],h1,l1_);
                pah[3] = packbf2(h0,h1); pal[3] = packbf2(l0_,l1_);
            }
            #pragma unroll
            for (int dg = 0; dg < 4; dg++) {
                int row = ks*16 + ii + (gi & 1)*8;
                int col = dg*16 + (gi >> 1)*8;
                uint32_t bh[4], bl[4];
                ldsm4t(bh, s2u(&Vh[row*FSTR + col]));
                ldsm4t(bl, s2u(&Vl[row*FSTR + col]));
                mma16816(o[2*dg],   pah, &bh[0]);
                mma16816(o[2*dg],   pah, &bl[0]);
                mma16816(o[2*dg],   pal, &bh[0]);
                mma16816(o[2*dg+1], pah, &bh[2]);
                mma16816(o[2*dg+1], pah, &bl[2]);
                mma16816(o[2*dg+1], pal, &bh[2]);
            }
        }
    }

    // finalize
    l0 += __shfl_xor_sync(0xffffffffu, l0, 1);
    l0 += __shfl_xor_sync(0xffffffffu, l0, 2);
    l1 += __shfl_xor_sync(0xffffffffu, l1, 1);
    l1 += __shfl_xor_sync(0xffffffffu, l1, 2);
    float inv0 = 1.f / l0, inv1 = 1.f / l1;

    int r0 = qt*64 + warp*16 + (lane >> 2);
    size_t o0 = ((size_t)b*SS + r0    )*(NH*HD) + h*HD;
    size_t o1 = ((size_t)b*SS + r0 + 8)*(NH*HD) + h*HD;
    #pragma unroll
    for (int nb = 0; nb < 8; nb++) {
        int d = nb*8 + 2*(lane & 3);
        __nv_bfloat16 h0,h1,l0_,l1_;
        split1(o[nb][0]*inv0, h0, l0_); split1(o[nb][1]*inv0, h1, l1_);
        *(__nv_bfloat162*)&g_aoh[o0 + d] = __nv_bfloat162(h0,h1);
        *(__nv_bfloat162*)&g_aol[o0 + d] = __nv_bfloat162(l0_,l1_);
        split1(o[nb][2]*inv1, h0, l0_); split1(o[nb][3]*inv1, h1, l1_);
        *(__nv_bfloat162*)&g_aoh[o1 + d] = __nv_bfloat162(h0,h1);
        *(__nv_bfloat162*)&g_aol[o1 + d] = __nv_bfloat162(l0_,l1_);
    }
}

// ---------------- O-proj GEMM ----------------------------------------------
__global__ __launch_bounds__(256) void oproj_gemm(
    const float* __restrict__ bo, float* __restrict__ C)
{
    extern __shared__ __nv_bfloat16 gsm[];
    const int tid = threadIdx.x, lane = tid & 31, warp = tid >> 5;
    const int wm = warp & 3, wn = warp >> 2;
    const int gi = lane >> 3, ii = lane & 7;
    const int bx = blockIdx.x, by = blockIdx.y;
    const int n0 = bx * 64;

    float c[2][4][4];
    #pragma unroll
    for (int i=0;i<2;i++) for (int j=0;j<4;j++) for (int e=0;e<4;e++) c[i][j][e]=0.f;

    load_gemm_tile(gsm, g_aoh, g_aol, g_woh, g_wol, by*128, n0, 0, tid);

    for (int t = 0; t < 32; t++) {
        cpa_wait0();
        __syncthreads();
        if (t < 31)
            load_gemm_tile(gsm + ((t+1)&1)*G_STAGE_E, g_aoh, g_aol, g_woh, g_wol,
                           by*128, n0, (t+1)*32, tid);
        gemm_compute(gsm + (t&1)*G_STAGE_E, c, wm, wn, gi, ii);
    }

    #pragma unroll
    for (int mi = 0; mi < 2; mi++)
        #pragma unroll
        for (int ni = 0; ni < 4; ni++)
            #pragma unroll
            for (int e = 0; e < 4; e++) {
                int m = by*128 + wm*32 + mi*16 + (lane >> 2) + ((e >= 2) ? 8 : 0);
                int n = n0 + wn*32 + ni*8 + 2*(lane & 3) + (e & 1);
                C[(size_t)m*HIDD + n] = c[mi][ni][e] + bo[n];
            }
}

// ---------------------------------------------------------------------------
extern "C" void kernel_launch(void* const* d_in, const int* in_sizes, int n_in,
                              void* d_out, int out_size)
{
    const float* X    = (const float*)d_in[0];
    const float* cosp = (const float*)d_in[1];
    const float* sinp = (const float*)d_in[2];
    const float* Wq   = (const float*)d_in[3];
    const float* bq   = (const float*)d_in[4];
    const float* Wk   = (const float*)d_in[5];
    const float* bk   = (const float*)d_in[6];
    const float* Wv   = (const float*)d_in[7];
    const float* bv   = (const float*)d_in[8];
    const float* Wo   = (const float*)d_in[9];
    const float* bo   = (const float*)d_in[10];
    float* out = (float*)d_out;

    const int gemm_smem  = 2 * G_STAGE_E * (int)sizeof(__nv_bfloat16);   // 61440
    const int flash_smem = 2 * F_STAGE_E * (int)sizeof(__nv_bfloat16);   // 73728
    cudaFuncSetAttribute(qkv_gemm,    cudaFuncAttributeMaxDynamicSharedMemorySize, gemm_smem);
    cudaFuncSetAttribute(oproj_gemm,  cudaFuncAttributeMaxDynamicSharedMemorySize, gemm_smem);
    cudaFuncSetAttribute(flash_kernel,cudaFuncAttributeMaxDynamicSharedMemorySize, flash_smem);

    // 0. pre-split X and weights to (hi,lo) bf16
    int nx = BB*SS*HIDD/4;
    split_kernel<<<(nx+255)/256, 256>>>(X, 0, nx);
    int nwq = NH*HD*HIDD/4;
    split_kernel<<<(nwq+255)/256, 256>>>(Wq, 1, nwq);
    int nwk = NKV*HD*HIDD/4;
    split_kernel<<<(nwk+255)/256, 256>>>(Wk, 2, nwk);
    split_kernel<<<(nwk+255)/256, 256>>>(Wv, 3, nwk);
    split_kernel<<<(nwq+255)/256, 256>>>(Wo, 4, nwq);

    // 1. QKV projection
    dim3 g1(1536/64, 8192/128);
    qkv_gemm<<<g1, 256, gemm_smem>>>(bq, bk, bv);

    // 2. RoPE + split (q scaled)
    int tq = BB*NH *SS*32;
    int tk = BB*NKV*SS*32;
    rope_split<<<(tq+255)/256, 256>>>(0, cosp, sinp, tq);
    rope_split<<<(tk+255)/256, 256>>>(1, cosp, sinp, tk);

    // 3. flash attention
    dim3 g3(SS/64, NH, BB);
    flash_kernel<<<g3, 128, flash_smem>>>();

    // 4. O-proj
    dim3 g4(1024/64, 8192/128);
    oproj_gemm<<<g4, 256, gemm_smem>>>(bo, out);
}

// round 7
// speedup vs baseline: 3.8121x; 1.0927x over previous
#include <cuda_runtime.h>
#include <cuda_bf16.h>
#include <cuda_fp16.h>
#include <cstdint>

#define BB   4
#define SS   2048
#define HIDD 1024
#define NH   16
#define NKV  4
#define HD   64
#define GROUPS 4
#define SCALE_F 0.125f

// ---------------- scratch (__device__ globals, allocation-free) -------------
__device__ float g_q[BB*NH*SS*HD];
__device__ float g_k[BB*NKV*SS*HD];
__device__ __nv_bfloat16 g_qh[BB*NH*SS*HD],  g_ql[BB*NH*SS*HD];
__device__ __nv_bfloat16 g_kh[BB*NKV*SS*HD], g_kl[BB*NKV*SS*HD];
__device__ __half        g_vh[BB*NKV*SS*HD], g_vl[BB*NKV*SS*HD];
__device__ __nv_bfloat16 g_xh[BB*SS*HIDD],   g_xl[BB*SS*HIDD];
__device__ __nv_bfloat16 g_aoh[BB*SS*NH*HD], g_aol[BB*SS*NH*HD];
__device__ __nv_bfloat16 g_wqh[NH*HD*HIDD],  g_wql[NH*HD*HIDD];
__device__ __nv_bfloat16 g_wkh[NKV*HD*HIDD], g_wkl[NKV*HD*HIDD];
__device__ __nv_bfloat16 g_wvh[NKV*HD*HIDD], g_wvl[NKV*HD*HIDD];
__device__ __nv_bfloat16 g_woh[HIDD*NH*HD],  g_wol[HIDD*NH*HD];

// ---------------- helpers ---------------------------------------------------
__device__ __forceinline__ uint32_t s2u(const void* p) {
    return (uint32_t)__cvta_generic_to_shared(p);
}
__device__ __forceinline__ void mma16816(float* c, const uint32_t* a, const uint32_t* b) {
    asm volatile(
        "mma.sync.aligned.m16n8k16.row.col.f32.bf16.bf16.f32 "
        "{%0,%1,%2,%3}, {%4,%5,%6,%7}, {%8,%9}, {%0,%1,%2,%3};"
        : "+f"(c[0]), "+f"(c[1]), "+f"(c[2]), "+f"(c[3])
        : "r"(a[0]), "r"(a[1]), "r"(a[2]), "r"(a[3]), "r"(b[0]), "r"(b[1]));
}
__device__ __forceinline__ void mma16816h(float* c, const uint32_t* a, const uint32_t* b) {
    asm volatile(
        "mma.sync.aligned.m16n8k16.row.col.f32.f16.f16.f32 "
        "{%0,%1,%2,%3}, {%4,%5,%6,%7}, {%8,%9}, {%0,%1,%2,%3};"
        : "+f"(c[0]), "+f"(c[1]), "+f"(c[2]), "+f"(c[3])
        : "r"(a[0]), "r"(a[1]), "r"(a[2]), "r"(a[3]), "r"(b[0]), "r"(b[1]));
}
__device__ __forceinline__ void ldsm4(uint32_t* r, uint32_t addr) {
    asm volatile("ldmatrix.sync.aligned.m8n8.x4.shared.b16 {%0,%1,%2,%3}, [%4];"
        : "=r"(r[0]), "=r"(r[1]), "=r"(r[2]), "=r"(r[3]) : "r"(addr));
}
__device__ __forceinline__ void ldsm4t(uint32_t* r, uint32_t addr) {
    asm volatile("ldmatrix.sync.aligned.m8n8.x4.trans.shared.b16 {%0,%1,%2,%3}, [%4];"
        : "=r"(r[0]), "=r"(r[1]), "=r"(r[2]), "=r"(r[3]) : "r"(addr));
}
__device__ __forceinline__ void cpa16(void* dst, const void* src) {
    asm volatile("cp.async.cg.shared.global [%0], [%1], 16;" :: "r"(s2u(dst)), "l"(src));
}
__device__ __forceinline__ void cpa_commit() {
    asm volatile("cp.async.commit_group;");
}
__device__ __forceinline__ void cpa_wait0() {
    asm volatile("cp.async.wait_group 0;" ::: "memory");
}
__device__ __forceinline__ void split1(float x, __nv_bfloat16& h, __nv_bfloat16& l) {
    h = __float2bfloat16(x);
    l = __float2bfloat16(x - __bfloat162float(h));
}
__device__ __forceinline__ void split1h(float x, __half& h, __half& l) {
    h = __float2half(x);
    l = __float2half(x - __half2float(h));
}
__device__ __forceinline__ uint32_t packh2(__half a, __half b) {
    __half2 t; t.x = a; t.y = b;
    return *(uint32_t*)&t;
}
__device__ __forceinline__ void split4_store(float4 v, __nv_bfloat16* H, __nv_bfloat16* L) {
    __nv_bfloat16 h0,h1,h2,h3,l0,l1,l2,l3;
    split1(v.x,h0,l0); split1(v.y,h1,l1); split1(v.z,h2,l2); split1(v.w,h3,l3);
    ((__nv_bfloat162*)H)[0] = __nv_bfloat162(h0,h1);
    ((__nv_bfloat162*)H)[1] = __nv_bfloat162(h2,h3);
    ((__nv_bfloat162*)L)[0] = __nv_bfloat162(l0,l1);
    ((__nv_bfloat162*)L)[1] = __nv_bfloat162(l2,l3);
}

// ---------------- fused fp32 -> (hi,lo) bf16 split for X + 4 weights --------
#define N4_X  (BB*SS*HIDD/4)        // 524288
#define N4_WQ (NH*HD*HIDD/4)        // 65536
#define N4_WK (NKV*HD*HIDD/4)       // 16384
__global__ void split_all(const float* __restrict__ X,  const float* __restrict__ Wq,
                          const float* __restrict__ Wk, const float* __restrict__ Wv,
                          const float* __restrict__ Wo)
{
    int i = blockIdx.x * blockDim.x + threadIdx.x;
    const float* src; __nv_bfloat16 *h, *l; int off;
    if (i < N4_X)                        { src = X;  h = g_xh;  l = g_xl;  off = i; }
    else if ((i -= N4_X)  < N4_WQ)       { src = Wq; h = g_wqh; l = g_wql; off = i; }
    else if ((i -= N4_WQ) < N4_WK)       { src = Wk; h = g_wkh; l = g_wkl; off = i; }
    else if ((i -= N4_WK) < N4_WK)       { src = Wv; h = g_wvh; l = g_wvl; off = i; }
    else if ((i -= N4_WK) < N4_WQ)       { src = Wo; h = g_woh; l = g_wol; off = i; }
    else return;
    float4 v = *(const float4*)&src[(size_t)off*4];
    split4_store(v, &h[(size_t)off*4], &l[(size_t)off*4]);
}

// ---------------- GEMM common (BM128 BN128 BK32, 2-stage pipeline) ----------
#define GSTR 40
#define G_AH  0
#define G_AL  5120
#define G_BH  10240
#define G_BL  15360
#define G_STAGE_E 20480   // elems per stage (40960 B)

__device__ __forceinline__ void load_gemm_tile(__nv_bfloat16* st,
    const __nv_bfloat16* Ahg, const __nv_bfloat16* Alg,
    const __nv_bfloat16* Bhg, const __nv_bfloat16* Blg,
    int arow0, int brow0, int kt, int tid)
{
    #pragma unroll
    for (int p = 0; p < 2; p++) {
        int cidx = tid + p*256;
        int row = cidx >> 2, ch = (cidx & 3)*8;
        size_t so = (size_t)(arow0 + row)*HIDD + kt + ch;
        cpa16(&st[G_AH + row*GSTR + ch], Ahg + so);
        cpa16(&st[G_AL + row*GSTR + ch], Alg + so);
    }
    #pragma unroll
    for (int p = 0; p < 2; p++) {
        int cidx = tid + p*256;
        int row = cidx >> 2, ch = (cidx & 3)*8;
        size_t so = (size_t)(brow0 + row)*HIDD + kt + ch;
        cpa16(&st[G_BH + row*GSTR + ch], Bhg + so);
        cpa16(&st[G_BL + row*GSTR + ch], Blg + so);
    }
    cpa_commit();
}

__device__ __forceinline__ void gemm_compute(const __nv_bfloat16* st,
    float c[4][4][4], int wm, int wn, int gi, int ii)
{
    #pragma unroll
    for (int ks = 0; ks < 2; ks++) {
        uint32_t ah[4][4], al[4][4], bh[2][4], bl[2][4];
        #pragma unroll
        for (int mi = 0; mi < 4; mi++) {
            int row = wm*64 + mi*16 + ii + (gi & 1)*8;
            int col = ks*16 + (gi >> 1)*8;
            ldsm4(ah[mi], s2u(&st[G_AH + row*GSTR + col]));
            ldsm4(al[mi], s2u(&st[G_AL + row*GSTR + col]));
        }
        #pragma unroll
        for (int ng = 0; ng < 2; ng++) {
            int row = wn*32 + ng*16 + ii + (gi >> 1)*8;
            int col = ks*16 + (gi & 1)*8;
            ldsm4(bh[ng], s2u(&st[G_BH + row*GSTR + col]));
            ldsm4(bl[ng], s2u(&st[G_BL + row*GSTR + col]));
        }
        #pragma unroll
        for (int mi = 0; mi < 4; mi++)
            #pragma unroll
            for (int ng = 0; ng < 2; ng++) {
                mma16816(c[mi][2*ng],   ah[mi], &bh[ng][0]);
                mma16816(c[mi][2*ng],   ah[mi], &bl[ng][0]);
                mma16816(c[mi][2*ng],   al[mi], &bh[ng][0]);
                mma16816(c[mi][2*ng+1], ah[mi], &bh[ng][2]);
                mma16816(c[mi][2*ng+1], ah[mi], &bl[ng][2]);
                mma16816(c[mi][2*ng+1], al[mi], &bh[ng][2]);
            }
    }
}

// ---------------- QKV GEMM ---------------------------------------------------
__global__ __launch_bounds__(256) void qkv_gemm(
    const float* __restrict__ bq, const float* __restrict__ bk, const float* __restrict__ bv)
{
    extern __shared__ __nv_bfloat16 gsm[];
    const int tid = threadIdx.x, lane = tid & 31, warp = tid >> 5;
    const int wm = warp >> 2, wn = warp & 3;
    const int gi = lane >> 3, ii = lane & 7;
    const int bx = blockIdx.x, by = blockIdx.y;
    const int n0 = bx * 128;

    const __nv_bfloat16 *Wh, *Wl; const float* bias; int noff;
    if (n0 < 1024)      { Wh = g_wqh; Wl = g_wql; bias = bq; noff = 0;    }
    else if (n0 < 1280) { Wh = g_wkh; Wl = g_wkl; bias = bk; noff = 1024; }
    else                { Wh = g_wvh; Wl = g_wvl; bias = bv; noff = 1280; }

    float c[4][4][4];
    #pragma unroll
    for (int i=0;i<4;i++) for (int j=0;j<4;j++) for (int e=0;e<4;e++) c[i][j][e]=0.f;

    load_gemm_tile(gsm, g_xh, g_xl, Wh, Wl, by*128, n0 - noff, 0, tid);

    for (int t = 0; t < 32; t++) {
        cpa_wait0();
        __syncthreads();
        if (t < 31)
            load_gemm_tile(gsm + ((t+1)&1)*G_STAGE_E, g_xh, g_xl, Wh, Wl,
                           by*128, n0 - noff, (t+1)*32, tid);
        gemm_compute(gsm + (t&1)*G_STAGE_E, c, wm, wn, gi, ii);
    }

    // epilogue: bias + scatter. Q/K -> fp32 (rope next); V -> split fp16.
    #pragma unroll
    for (int mi = 0; mi < 4; mi++)
        #pragma unroll
        for (int ni = 0; ni < 4; ni++)
            #pragma unroll
            for (int e = 0; e < 4; e++) {
                int m = by*128 + wm*64 + mi*16 + (lane >> 2) + ((e >= 2) ? 8 : 0);
                int n = n0 + wn*32 + ni*8 + 2*(lane & 3) + (e & 1);
                int b_ = m >> 11, s = m & 2047;
                float val = c[mi][ni][e] + bias[n - noff];
                if (n < 1024) {
                    int h = n >> 6, d = n & 63;
                    g_q[(((size_t)b_*NH + h)*SS + s)*HD + d] = val;
                } else if (n < 1280) {
                    int nn = n - 1024; int h = nn >> 6, d = nn & 63;
                    g_k[(((size_t)b_*NKV + h)*SS + s)*HD + d] = val;
                } else {
                    int nn = n - 1280; int h = nn >> 6, d = nn & 63;
                    size_t off = (((size_t)b_*NKV + h)*SS + s)*HD + d;
                    __half hh, ll; split1h(val, hh, ll);
                    g_vh[off] = hh; g_vl[off] = ll;
                }
            }
}

// ---------------- RoPE + split (q: scaled; k: unscaled), fused --------------
__global__ void rope_all(const float* __restrict__ cos_t,
                         const float* __restrict__ sin_t, int tq, int total)
{
    int idx = blockIdx.x * blockDim.x + threadIdx.x;
    if (idx >= total) return;
    int which = (idx >= tq);
    if (which) idx -= tq;
    int d  = idx & 31;
    int s  = (idx >> 5) & 2047;
    int bh = idx >> 16;
    const float* src = which ? g_k : g_q;
    __nv_bfloat16* dh = which ? g_kh : g_qh;
    __nv_bfloat16* dl = which ? g_kl : g_ql;
    float scale = which ? 1.0f : SCALE_F;
    size_t base = ((size_t)bh*SS + s)*HD;
    float x1 = src[base + d], x2 = src[base + d + 32];
    float c1 = cos_t[s*HD + d],      s1 = sin_t[s*HD + d];
    float c2 = cos_t[s*HD + d + 32], s2 = sin_t[s*HD + d + 32];
    float y1 = (x1*c1 - x2*s1) * scale;
    float y2 = (x2*c2 + x1*s2) * scale;
    __nv_bfloat16 hh, ll;
    split1(y1, hh, ll); dh[base + d]      = hh; dl[base + d]      = ll;
    split1(y2, hh, ll); dh[base + d + 32] = hh; dl[base + d + 32] = ll;
}

// ---------------- flash attention (64 q-rows, 64-key tiles, 2-stage) --------
#define FSTR 72
#define F_ARR (64*FSTR)
#define F_STAGE_E (4*F_ARR)

__device__ __forceinline__ void load_kv_tile(__nv_bfloat16* st,
    const __nv_bfloat16* khg, const __nv_bfloat16* klg,
    const __half* vhg, const __half* vlg, int t, int tid)
{
    #pragma unroll
    for (int p = 0; p < 4; p++) {
        int cidx = tid + p*128;
        int row = cidx >> 3, ch = (cidx & 7)*8;
        size_t so = ((size_t)t*64 + row)*HD + ch;
        cpa16(&st[          row*FSTR + ch], khg + so);
        cpa16(&st[  F_ARR + row*FSTR + ch], klg + so);
        cpa16(&st[2*F_ARR + row*FSTR + ch], vhg + so);
        cpa16(&st[3*F_ARR + row*FSTR + ch], vlg + so);
    }
    cpa_commit();
}

__global__ __launch_bounds__(128) void flash_kernel()
{
    extern __shared__ __nv_bfloat16 fsm[];

    const int b = blockIdx.z, h = blockIdx.y, qt = blockIdx.x;
    const int tid = threadIdx.x, lane = tid & 31, warp = tid >> 5;
    const int hk = h / GROUPS;
    const int gi = lane >> 3, ii = lane & 7;

    const __nv_bfloat16* qhg = g_qh + (((size_t)b*NH  + h )*SS + qt*64)*HD;
    const __nv_bfloat16* qlg = g_ql + (((size_t)b*NH  + h )*SS + qt*64)*HD;
    const __nv_bfloat16* khg = g_kh + (((size_t)b*NKV + hk)*SS)*HD;
    const __nv_bfloat16* klg = g_kl + (((size_t)b*NKV + hk)*SS)*HD;
    const __half*        vhg = g_vh + (((size_t)b*NKV + hk)*SS)*HD;
    const __half*        vlg = g_vl + (((size_t)b*NKV + hk)*SS)*HD;

    // ---- stage Q through stage-0 smem, grab fragments ----
    {
        #pragma unroll
        for (int p = 0; p < 4; p++) {
            int cidx = tid + p*128;
            int row = cidx >> 3, ch = (cidx & 7)*8;
            size_t so = (size_t)row*HD + ch;
            cpa16(&fsm[         row*FSTR + ch], qhg + so);
            cpa16(&fsm[F_ARR + row*FSTR + ch], qlg + so);
        }
        cpa_commit();
        cpa_wait0();
        __syncthreads();
    }

    uint32_t qh[4][4], ql[4][4];
    #pragma unroll
    for (int kk = 0; kk < 4; kk++) {
        int row = warp*16 + ii + (gi & 1)*8;
        int col = kk*16 + (gi >> 1)*8;
        ldsm4(qh[kk], s2u(&fsm[         row*FSTR + col]));
        ldsm4(ql[kk], s2u(&fsm[F_ARR + row*FSTR + col]));
    }
    __syncthreads();

    load_kv_tile(fsm, khg, klg, vhg, vlg, 0, tid);

    float o[8][4];
    #pragma unroll
    for (int i = 0; i < 8; i++) for (int j = 0; j < 4; j++) o[i][j] = 0.f;
    float m0 = -1e30f, m1 = -1e30f, l0 = 0.f, l1 = 0.f;

    for (int t = 0; t < SS/64; t++) {
        cpa_wait0();
        __syncthreads();
        if (t < SS/64 - 1)
            load_kv_tile(fsm + ((t+1)&1)*F_STAGE_E, khg, klg, vhg, vlg, t+1, tid);

        const __nv_bfloat16* Kh = fsm + (t&1)*F_STAGE_E;
        const __nv_bfloat16* Kl = Kh + F_ARR;
        const __nv_bfloat16* Vh = Kh + 2*F_ARR;   // bytes hold __half data
        const __nv_bfloat16* Vl = Kh + 3*F_ARR;

        // S = Q K^T  (bf16 3-MMA split)
        float s[8][4];
        #pragma unroll
        for (int i = 0; i < 8; i++) for (int j = 0; j < 4; j++) s[i][j] = 0.f;
        #pragma unroll
        for (int kk = 0; kk < 4; kk++) {
            int col = kk*16 + (gi & 1)*8;
            #pragma unroll
            for (int ng = 0; ng < 4; ng++) {
                int row = ng*16 + ii + (gi >> 1)*8;
                uint32_t bh[4], bl[4];
                ldsm4(bh, s2u(&Kh[row*FSTR + col]));
                ldsm4(bl, s2u(&Kl[row*FSTR + col]));
                mma16816(s[2*ng],   qh[kk], &bh[0]);
                mma16816(s[2*ng],   qh[kk], &bl[0]);
                mma16816(s[2*ng],   ql[kk], &bh[0]);
                mma16816(s[2*ng+1], qh[kk], &bh[2]);
                mma16816(s[2*ng+1], qh[kk], &bl[2]);
                mma16816(s[2*ng+1], ql[kk], &bh[2]);
            }
        }

        // online softmax
        float mx0 = -1e30f, mx1 = -1e30f;
        #pragma unroll
        for (int nt = 0; nt < 8; nt++) {
            mx0 = fmaxf(mx0, fmaxf(s[nt][0], s[nt][1]));
            mx1 = fmaxf(mx1, fmaxf(s[nt][2], s[nt][3]));
        }
        mx0 = fmaxf(mx0, __shfl_xor_sync(0xffffffffu, mx0, 1));
        mx0 = fmaxf(mx0, __shfl_xor_sync(0xffffffffu, mx0, 2));
        mx1 = fmaxf(mx1, __shfl_xor_sync(0xffffffffu, mx1, 1));
        mx1 = fmaxf(mx1, __shfl_xor_sync(0xffffffffu, mx1, 2));
        float nm0 = fmaxf(m0, mx0), nm1 = fmaxf(m1, mx1);
        float cr0 = __expf(m0 - nm0), cr1 = __expf(m1 - nm1);
        m0 = nm0; m1 = nm1;
        float sp0 = 0.f, sp1 = 0.f;
        #pragma unroll
        for (int nt = 0; nt < 8; nt++) {
            s[nt][0] = __expf(s[nt][0] - m0); sp0 += s[nt][0];
            s[nt][1] = __expf(s[nt][1] - m0); sp0 += s[nt][1];
            s[nt][2] = __expf(s[nt][2] - m1); sp1 += s[nt][2];
            s[nt][3] = __expf(s[nt][3] - m1); sp1 += s[nt][3];
        }
        l0 = l0*cr0 + sp0;
        l1 = l1*cr1 + sp1;
        #pragma unroll
        for (int nb = 0; nb < 8; nb++) {
            o[nb][0] *= cr0; o[nb][1] *= cr0;
            o[nb][2] *= cr1; o[nb][3] *= cr1;
        }

        // O += P V  (fp16: P unsplit, V hi+lo -> 2 MMAs)
        #pragma unroll
        for (int ks = 0; ks < 4; ks++) {
            uint32_t pa[4];
            {
                const float* s0 = s[2*ks];
                const float* s1 = s[2*ks+1];
                pa[0] = packh2(__float2half(s0[0]), __float2half(s0[1]));
                pa[1] = packh2(__float2half(s0[2]), __float2half(s0[3]));
                pa[2] = packh2(__float2half(s1[0]), __float2half(s1[1]));
                pa[3] = packh2(__float2half(s1[2]), __float2half(s1[3]));
            }
            #pragma unroll
            for (int dg = 0; dg < 4; dg++) {
                int row = ks*16 + ii + (gi & 1)*8;
                int col = dg*16 + (gi >> 1)*8;
                uint32_t bh[4], bl[4];
                ldsm4t(bh, s2u(&Vh[row*FSTR + col]));
                ldsm4t(bl, s2u(&Vl[row*FSTR + col]));
                mma16816h(o[2*dg],   pa, &bh[0]);
                mma16816h(o[2*dg],   pa, &bl[0]);
                mma16816h(o[2*dg+1], pa, &bh[2]);
                mma16816h(o[2*dg+1], pa, &bl[2]);
            }
        }
    }

    // finalize
    l0 += __shfl_xor_sync(0xffffffffu, l0, 1);
    l0 += __shfl_xor_sync(0xffffffffu, l0, 2);
    l1 += __shfl_xor_sync(0xffffffffu, l1, 1);
    l1 += __shfl_xor_sync(0xffffffffu, l1, 2);
    float inv0 = 1.f / l0, inv1 = 1.f / l1;

    int r0 = qt*64 + warp*16 + (lane >> 2);
    size_t o0 = ((size_t)b*SS + r0    )*(NH*HD) + h*HD;
    size_t o1 = ((size_t)b*SS + r0 + 8)*(NH*HD) + h*HD;
    #pragma unroll
    for (int nb = 0; nb < 8; nb++) {
        int d = nb*8 + 2*(lane & 3);
        __nv_bfloat16 h0,h1,l0_,l1_;
        split1(o[nb][0]*inv0, h0, l0_); split1(o[nb][1]*inv0, h1, l1_);
        *(__nv_bfloat162*)&g_aoh[o0 + d] = __nv_bfloat162(h0,h1);
        *(__nv_bfloat162*)&g_aol[o0 + d] = __nv_bfloat162(l0_,l1_);
        split1(o[nb][2]*inv1, h0, l0_); split1(o[nb][3]*inv1, h1, l1_);
        *(__nv_bfloat162*)&g_aoh[o1 + d] = __nv_bfloat162(h0,h1);
        *(__nv_bfloat162*)&g_aol[o1 + d] = __nv_bfloat162(l0_,l1_);
    }
}

// ---------------- O-proj GEMM ----------------------------------------------
__global__ __launch_bounds__(256) void oproj_gemm(
    const float* __restrict__ bo, float* __restrict__ C)
{
    extern __shared__ __nv_bfloat16 gsm[];
    const int tid = threadIdx.x, lane = tid & 31, warp = tid >> 5;
    const int wm = warp >> 2, wn = warp & 3;
    const int gi = lane >> 3, ii = lane & 7;
    const int bx = blockIdx.x, by = blockIdx.y;
    const int n0 = bx * 128;

    float c[4][4][4];
    #pragma unroll
    for (int i=0;i<4;i++) for (int j=0;j<4;j++) for (int e=0;e<4;e++) c[i][j][e]=0.f;

    load_gemm_tile(gsm, g_aoh, g_aol, g_woh, g_wol, by*128, n0, 0, tid);

    for (int t = 0; t < 32; t++) {
        cpa_wait0();
        __syncthreads();
        if (t < 31)
            load_gemm_tile(gsm + ((t+1)&1)*G_STAGE_E, g_aoh, g_aol, g_woh, g_wol,
                           by*128, n0, (t+1)*32, tid);
        gemm_compute(gsm + (t&1)*G_STAGE_E, c, wm, wn, gi, ii);
    }

    #pragma unroll
    for (int mi = 0; mi < 4; mi++)
        #pragma unroll
        for (int ni = 0; ni < 4; ni++)
            #pragma unroll
            for (int e = 0; e < 4; e++) {
                int m = by*128 + wm*64 + mi*16 + (lane >> 2) + ((e >= 2) ? 8 : 0);
                int n = n0 + wn*32 + ni*8 + 2*(lane & 3) + (e & 1);
                C[(size_t)m*HIDD + n] = c[mi][ni][e] + bo[n];
            }
}

// ---------------------------------------------------------------------------
extern "C" void kernel_launch(void* const* d_in, const int* in_sizes, int n_in,
                              void* d_out, int out_size)
{
    const float* X    = (const float*)d_in[0];
    const float* cosp = (const float*)d_in[1];
    const float* sinp = (const float*)d_in[2];
    const float* Wq   = (const float*)d_in[3];
    const float* bq   = (const float*)d_in[4];
    const float* Wk   = (const float*)d_in[5];
    const float* bk   = (const float*)d_in[6];
    const float* Wv   = (const float*)d_in[7];
    const float* bv   = (const float*)d_in[8];
    const float* Wo   = (const float*)d_in[9];
    const float* bo   = (const float*)d_in[10];
    float* out = (float*)d_out;

    const int gemm_smem  = 2 * G_STAGE_E * (int)sizeof(__nv_bfloat16);   // 81920
    const int flash_smem = 2 * F_STAGE_E * (int)sizeof(__nv_bfloat16);   // 73728
    cudaFuncSetAttribute(qkv_gemm,    cudaFuncAttributeMaxDynamicSharedMemorySize, gemm_smem);
    cudaFuncSetAttribute(oproj_gemm,  cudaFuncAttributeMaxDynamicSharedMemorySize, gemm_smem);
    cudaFuncSetAttribute(flash_kernel,cudaFuncAttributeMaxDynamicSharedMemorySize, flash_smem);

    // 0. fused pre-split of X + all weights
    int n4_total = N4_X + 2*N4_WQ + 2*N4_WK;
    split_all<<<(n4_total + 255)/256, 256>>>(X, Wq, Wk, Wv, Wo);

    // 1. QKV projection (M=8192, N=1536, K=1024)
    dim3 g1(1536/128, 8192/128);
    qkv_gemm<<<g1, 256, gemm_smem>>>(bq, bk, bv);

    // 2. RoPE + split, fused q+k
    int tq = BB*NH *SS*32;
    int tk = BB*NKV*SS*32;
    rope_all<<<(tq + tk + 255)/256, 256>>>(cosp, sinp, tq, tq + tk);

    // 3. flash attention
    dim3 g3(SS/64, NH, BB);
    flash_kernel<<<g3, 128, flash_smem>>>();

    // 4. O-proj (M=8192, N=1024, K=1024)
    dim3 g4(1024/128, 8192/128);
    oproj_gemm<<<g4, 256, gemm_smem>>>(bo, out);
}

// round 9
// speedup vs baseline: 3.9609x; 1.0390x over previous
#include <cuda_runtime.h>
#include <cuda_bf16.h>
#include <cuda_fp16.h>
#include <cstdint>

#define BB   4
#define SS   2048
#define HIDD 1024
#define NH   16
#define NKV  4
#define HD   64
#define GROUPS 4
#define SCALE_F 0.125f
#define LOG2E 1.4426950408889634f

// ---------------- scratch (__device__ globals, allocation-free) -------------
__device__ float g_q[BB*NH*SS*HD];
__device__ float g_k[BB*NKV*SS*HD];
__device__ __nv_bfloat16 g_qh[BB*NH*SS*HD],  g_ql[BB*NH*SS*HD];
__device__ __nv_bfloat16 g_kh[BB*NKV*SS*HD], g_kl[BB*NKV*SS*HD];
__device__ __half        g_vh[BB*NKV*SS*HD], g_vl[BB*NKV*SS*HD];
__device__ __nv_bfloat16 g_xh[BB*SS*HIDD],   g_xl[BB*SS*HIDD];
__device__ __nv_bfloat16 g_aoh[BB*SS*NH*HD], g_aol[BB*SS*NH*HD];
__device__ __nv_bfloat16 g_wqh[NH*HD*HIDD],  g_wql[NH*HD*HIDD];
__device__ __nv_bfloat16 g_wkh[NKV*HD*HIDD], g_wkl[NKV*HD*HIDD];
__device__ __nv_bfloat16 g_wvh[NKV*HD*HIDD], g_wvl[NKV*HD*HIDD];
__device__ __nv_bfloat16 g_woh[HIDD*NH*HD],  g_wol[HIDD*NH*HD];

// ---------------- helpers ---------------------------------------------------
__device__ __forceinline__ uint32_t s2u(const void* p) {
    return (uint32_t)__cvta_generic_to_shared(p);
}
__device__ __forceinline__ void mma16816(float* c, const uint32_t* a, const uint32_t* b) {
    asm volatile(
        "mma.sync.aligned.m16n8k16.row.col.f32.bf16.bf16.f32 "
        "{%0,%1,%2,%3}, {%4,%5,%6,%7}, {%8,%9}, {%0,%1,%2,%3};"
        : "+f"(c[0]), "+f"(c[1]), "+f"(c[2]), "+f"(c[3])
        : "r"(a[0]), "r"(a[1]), "r"(a[2]), "r"(a[3]), "r"(b[0]), "r"(b[1]));
}
__device__ __forceinline__ void mma16816h(float* c, const uint32_t* a, const uint32_t* b) {
    asm volatile(
        "mma.sync.aligned.m16n8k16.row.col.f32.f16.f16.f32 "
        "{%0,%1,%2,%3}, {%4,%5,%6,%7}, {%8,%9}, {%0,%1,%2,%3};"
        : "+f"(c[0]), "+f"(c[1]), "+f"(c[2]), "+f"(c[3])
        : "r"(a[0]), "r"(a[1]), "r"(a[2]), "r"(a[3]), "r"(b[0]), "r"(b[1]));
}
__device__ __forceinline__ void ldsm4(uint32_t* r, uint32_t addr) {
    asm volatile("ldmatrix.sync.aligned.m8n8.x4.shared.b16 {%0,%1,%2,%3}, [%4];"
        : "=r"(r[0]), "=r"(r[1]), "=r"(r[2]), "=r"(r[3]) : "r"(addr));
}
__device__ __forceinline__ void ldsm4t(uint32_t* r, uint32_t addr) {
    asm volatile("ldmatrix.sync.aligned.m8n8.x4.trans.shared.b16 {%0,%1,%2,%3}, [%4];"
        : "=r"(r[0]), "=r"(r[1]), "=r"(r[2]), "=r"(r[3]) : "r"(addr));
}
__device__ __forceinline__ void cpa16(void* dst, const void* src) {
    asm volatile("cp.async.cg.shared.global [%0], [%1], 16;" :: "r"(s2u(dst)), "l"(src));
}
__device__ __forceinline__ void cpa_commit() {
    asm volatile("cp.async.commit_group;");
}
__device__ __forceinline__ void cpa_wait0() {
    asm volatile("cp.async.wait_group 0;" ::: "memory");
}
__device__ __forceinline__ float fexp2(float x) {
    float r;
    asm("ex2.approx.f32 %0, %1;" : "=f"(r) : "f"(x));
    return r;
}
__device__ __forceinline__ void split1(float x, __nv_bfloat16& h, __nv_bfloat16& l) {
    h = __float2bfloat16(x);
    l = __float2bfloat16(x - __bfloat162float(h));
}
__device__ __forceinline__ void split1h(float x, __half& h, __half& l) {
    h = __float2half(x);
    l = __float2half(x - __half2float(h));
}
__device__ __forceinline__ uint32_t packh2(__half a, __half b) {
    __half2 t; t.x = a; t.y = b;
    return *(uint32_t*)&t;
}
__device__ __forceinline__ void split4_store(float4 v, __nv_bfloat16* H, __nv_bfloat16* L) {
    __nv_bfloat16 h0,h1,h2,h3,l0,l1,l2,l3;
    split1(v.x,h0,l0); split1(v.y,h1,l1); split1(v.z,h2,l2); split1(v.w,h3,l3);
    ((__nv_bfloat162*)H)[0] = __nv_bfloat162(h0,h1);
    ((__nv_bfloat162*)H)[1] = __nv_bfloat162(h2,h3);
    ((__nv_bfloat162*)L)[0] = __nv_bfloat162(l0,l1);
    ((__nv_bfloat162*)L)[1] = __nv_bfloat162(l2,l3);
}

// ---------------- fused fp32 -> (hi,lo) bf16 split for X + 4 weights --------
#define N4_X  (BB*SS*HIDD/4)
#define N4_WQ (NH*HD*HIDD/4)
#define N4_WK (NKV*HD*HIDD/4)
__global__ void split_all(const float* __restrict__ X,  const float* __restrict__ Wq,
                          const float* __restrict__ Wk, const float* __restrict__ Wv,
                          const float* __restrict__ Wo)
{
    int i = blockIdx.x * blockDim.x + threadIdx.x;
    const float* src; __nv_bfloat16 *h, *l; int off;
    if (i < N4_X)                        { src = X;  h = g_xh;  l = g_xl;  off = i; }
    else if ((i -= N4_X)  < N4_WQ)       { src = Wq; h = g_wqh; l = g_wql; off = i; }
    else if ((i -= N4_WQ) < N4_WK)       { src = Wk; h = g_wkh; l = g_wkl; off = i; }
    else if ((i -= N4_WK) < N4_WK)       { src = Wv; h = g_wvh; l = g_wvl; off = i; }
    else if ((i -= N4_WK) < N4_WQ)       { src = Wo; h = g_woh; l = g_wol; off = i; }
    else return;
    float4 v = *(const float4*)&src[(size_t)off*4];
    split4_store(v, &h[(size_t)off*4], &l[(size_t)off*4]);
}

// ---------------- GEMM common (BM128 BN128 BK32, 2-stage pipeline) ----------
#define GSTR 40
#define G_AH  0
#define G_AL  5120
#define G_BH  10240
#define G_BL  15360
#define G_STAGE_E 20480

__device__ __forceinline__ void load_gemm_tile(__nv_bfloat16* st,
    const __nv_bfloat16* Ahg, const __nv_bfloat16* Alg,
    const __nv_bfloat16* Bhg, const __nv_bfloat16* Blg,
    int arow0, int brow0, int kt, int tid)
{
    #pragma unroll
    for (int p = 0; p < 2; p++) {
        int cidx = tid + p*256;
        int row = cidx >> 2, ch = (cidx & 3)*8;
        size_t so = (size_t)(arow0 + row)*HIDD + kt + ch;
        cpa16(&st[G_AH + row*GSTR + ch], Ahg + so);
        cpa16(&st[G_AL + row*GSTR + ch], Alg + so);
    }
    #pragma unroll
    for (int p = 0; p < 2; p++) {
        int cidx = tid + p*256;
        int row = cidx >> 2, ch = (cidx & 3)*8;
        size_t so = (size_t)(brow0 + row)*HIDD + kt + ch;
        cpa16(&st[G_BH + row*GSTR + ch], Bhg + so);
        cpa16(&st[G_BL + row*GSTR + ch], Blg + so);
    }
    cpa_commit();
}

// accumulator-interleaved: pass over all accumulators per product term
__device__ __forceinline__ void gemm_compute(const __nv_bfloat16* st,
    float c[4][4][4], int wm, int wn, int gi, int ii)
{
    #pragma unroll
    for (int ks = 0; ks < 2; ks++) {
        uint32_t ah[4][4], al[4][4], bh[2][4], bl[2][4];
        #pragma unroll
        for (int mi = 0; mi < 4; mi++) {
            int row = wm*64 + mi*16 + ii + (gi & 1)*8;
            int col = ks*16 + (gi >> 1)*8;
            ldsm4(ah[mi], s2u(&st[G_AH + row*GSTR + col]));
            ldsm4(al[mi], s2u(&st[G_AL + row*GSTR + col]));
        }
        #pragma unroll
        for (int ng = 0; ng < 2; ng++) {
            int row = wn*32 + ng*16 + ii + (gi >> 1)*8;
            int col = ks*16 + (gi & 1)*8;
            ldsm4(bh[ng], s2u(&st[G_BH + row*GSTR + col]));
            ldsm4(bl[ng], s2u(&st[G_BL + row*GSTR + col]));
        }
        // pass 1: hi*hi over all 16 accumulators
        #pragma unroll
        for (int mi = 0; mi < 4; mi++)
            #pragma unroll
            for (int ng = 0; ng < 2; ng++) {
                mma16816(c[mi][2*ng],   ah[mi], &bh[ng][0]);
                mma16816(c[mi][2*ng+1], ah[mi], &bh[ng][2]);
            }
        // pass 2: hi*lo
        #pragma unroll
        for (int mi = 0; mi < 4; mi++)
            #pragma unroll
            for (int ng = 0; ng < 2; ng++) {
                mma16816(c[mi][2*ng],   ah[mi], &bl[ng][0]);
                mma16816(c[mi][2*ng+1], ah[mi], &bl[ng][2]);
            }
        // pass 3: lo*hi
        #pragma unroll
        for (int mi = 0; mi < 4; mi++)
            #pragma unroll
            for (int ng = 0; ng < 2; ng++) {
                mma16816(c[mi][2*ng],   al[mi], &bh[ng][0]);
                mma16816(c[mi][2*ng+1], al[mi], &bh[ng][2]);
            }
    }
}

// ---------------- QKV GEMM ---------------------------------------------------
__global__ __launch_bounds__(256) void qkv_gemm(
    const float* __restrict__ bq, const float* __restrict__ bk, const float* __restrict__ bv)
{
    extern __shared__ __nv_bfloat16 gsm[];
    const int tid = threadIdx.x, lane = tid & 31, warp = tid >> 5;
    const int wm = warp >> 2, wn = warp & 3;
    const int gi = lane >> 3, ii = lane & 7;
    const int bx = blockIdx.x, by = blockIdx.y;
    const int n0 = bx * 128;

    const __nv_bfloat16 *Wh, *Wl; const float* bias; int noff;
    if (n0 < 1024)      { Wh = g_wqh; Wl = g_wql; bias = bq; noff = 0;    }
    else if (n0 < 1280) { Wh = g_wkh; Wl = g_wkl; bias = bk; noff = 1024; }
    else                { Wh = g_wvh; Wl = g_wvl; bias = bv; noff = 1280; }

    float c[4][4][4];
    #pragma unroll
    for (int i=0;i<4;i++) for (int j=0;j<4;j++) for (int e=0;e<4;e++) c[i][j][e]=0.f;

    load_gemm_tile(gsm, g_xh, g_xl, Wh, Wl, by*128, n0 - noff, 0, tid);

    for (int t = 0; t < 32; t++) {
        cpa_wait0();
        __syncthreads();
        if (t < 31)
            load_gemm_tile(gsm + ((t+1)&1)*G_STAGE_E, g_xh, g_xl, Wh, Wl,
                           by*128, n0 - noff, (t+1)*32, tid);
        gemm_compute(gsm + (t&1)*G_STAGE_E, c, wm, wn, gi, ii);
    }

    #pragma unroll
    for (int mi = 0; mi < 4; mi++)
        #pragma unroll
        for (int ni = 0; ni < 4; ni++)
            #pragma unroll
            for (int e = 0; e < 4; e++) {
                int m = by*128 + wm*64 + mi*16 + (lane >> 2) + ((e >= 2) ? 8 : 0);
                int n = n0 + wn*32 + ni*8 + 2*(lane & 3) + (e & 1);
                int b_ = m >> 11, s = m & 2047;
                float val = c[mi][ni][e] + bias[n - noff];
                if (n < 1024) {
                    int h = n >> 6, d = n & 63;
                    g_q[(((size_t)b_*NH + h)*SS + s)*HD + d] = val;
                } else if (n < 1280) {
                    int nn = n - 1024; int h = nn >> 6, d = nn & 63;
                    g_k[(((size_t)b_*NKV + h)*SS + s)*HD + d] = val;
                } else {
                    int nn = n - 1280; int h = nn >> 6, d = nn & 63;
                    size_t off = (((size_t)b_*NKV + h)*SS + s)*HD + d;
                    __half hh, ll; split1h(val, hh, ll);
                    g_vh[off] = hh; g_vl[off] = ll;
                }
            }
}

// ---------------- RoPE + split; q gets 0.125*log2(e) scale ------------------
__global__ void rope_all(const float* __restrict__ cos_t,
                         const float* __restrict__ sin_t, int tq, int total)
{
    int idx = blockIdx.x * blockDim.x + threadIdx.x;
    if (idx >= total) return;
    int which = (idx >= tq);
    if (which) idx -= tq;
    int d  = idx & 31;
    int s  = (idx >> 5) & 2047;
    int bh = idx >> 16;
    const float* src = which ? g_k : g_q;
    __nv_bfloat16* dh = which ? g_kh : g_qh;
    __nv_bfloat16* dl = which ? g_kl : g_ql;
    float scale = which ? 1.0f : (SCALE_F * LOG2E);
    size_t base = ((size_t)bh*SS + s)*HD;
    float x1 = src[base + d], x2 = src[base + d + 32];
    float c1 = cos_t[s*HD + d],      s1 = sin_t[s*HD + d];
    float c2 = cos_t[s*HD + d + 32], s2 = sin_t[s*HD + d + 32];
    float y1 = (x1*c1 - x2*s1) * scale;
    float y2 = (x2*c2 + x1*s2) * scale;
    __nv_bfloat16 hh, ll;
    split1(y1, hh, ll); dh[base + d]      = hh; dl[base + d]      = ll;
    split1(y2, hh, ll); dh[base + d + 32] = hh; dl[base + d + 32] = ll;
}

// ---------------- flash attention (64 q-rows, 64-key tiles, 2-stage) --------
#define FSTR 72
#define F_ARR (64*FSTR)
#define F_STAGE_E (4*F_ARR)

__device__ __forceinline__ void load_kv_tile(__nv_bfloat16* st,
    const __nv_bfloat16* khg, const __nv_bfloat16* klg,
    const __half* vhg, const __half* vlg, int t, int tid)
{
    #pragma unroll
    for (int p = 0; p < 4; p++) {
        int cidx = tid + p*128;
        int row = cidx >> 3, ch = (cidx & 7)*8;
        size_t so = ((size_t)t*64 + row)*HD + ch;
        cpa16(&st[          row*FSTR + ch], khg + so);
        cpa16(&st[  F_ARR + row*FSTR + ch], klg + so);
        cpa16(&st[2*F_ARR + row*FSTR + ch], vhg + so);
        cpa16(&st[3*F_ARR + row*FSTR + ch], vlg + so);
    }
    cpa_commit();
}

__global__ __launch_bounds__(128) void flash_kernel()
{
    extern __shared__ __nv_bfloat16 fsm[];

    const int b = blockIdx.z, h = blockIdx.y, qt = blockIdx.x;
    const int tid = threadIdx.x, lane = tid & 31, warp = tid >> 5;
    const int hk = h / GROUPS;
    const int gi = lane >> 3, ii = lane & 7;

    const __nv_bfloat16* qhg = g_qh + (((size_t)b*NH  + h )*SS + qt*64)*HD;
    const __nv_bfloat16* qlg = g_ql + (((size_t)b*NH  + h )*SS + qt*64)*HD;
    const __nv_bfloat16* khg = g_kh + (((size_t)b*NKV + hk)*SS)*HD;
    const __nv_bfloat16* klg = g_kl + (((size_t)b*NKV + hk)*SS)*HD;
    const __half*        vhg = g_vh + (((size_t)b*NKV + hk)*SS)*HD;
    const __half*        vlg = g_vl + (((size_t)b*NKV + hk)*SS)*HD;

    // stage Q through stage-0 smem, grab fragments
    {
        #pragma unroll
        for (int p = 0; p < 4; p++) {
            int cidx = tid + p*128;
            int row = cidx >> 3, ch = (cidx & 7)*8;
            size_t so = (size_t)row*HD + ch;
            cpa16(&fsm[         row*FSTR + ch], qhg + so);
            cpa16(&fsm[F_ARR + row*FSTR + ch], qlg + so);
        }
        cpa_commit();
        cpa_wait0();
        __syncthreads();
    }

    uint32_t qh[4][4], ql[4][4];
    #pragma unroll
    for (int kk = 0; kk < 4; kk++) {
        int row = warp*16 + ii + (gi & 1)*8;
        int col = kk*16 + (gi >> 1)*8;
        ldsm4(qh[kk], s2u(&fsm[         row*FSTR + col]));
        ldsm4(ql[kk], s2u(&fsm[F_ARR + row*FSTR + col]));
    }
    __syncthreads();

    load_kv_tile(fsm, khg, klg, vhg, vlg, 0, tid);

    float o[8][4];
    #pragma unroll
    for (int i = 0; i < 8; i++) for (int j = 0; j < 4; j++) o[i][j] = 0.f;
    float m0 = -1e30f, m1 = -1e30f, l0 = 0.f, l1 = 0.f;

    for (int t = 0; t < SS/64; t++) {
        cpa_wait0();
        __syncthreads();
        if (t < SS/64 - 1)
            load_kv_tile(fsm + ((t+1)&1)*F_STAGE_E, khg, klg, vhg, vlg, t+1, tid);

        const __nv_bfloat16* Kh = fsm + (t&1)*F_STAGE_E;
        const __nv_bfloat16* Kl = Kh + F_ARR;
        const __nv_bfloat16* Vh = Kh + 2*F_ARR;
        const __nv_bfloat16* Vl = Kh + 3*F_ARR;

        // S = Q K^T (bf16 3-term split, accumulator-interleaved)
        float s[8][4];
        #pragma unroll
        for (int i = 0; i < 8; i++) for (int j = 0; j < 4; j++) s[i][j] = 0.f;
        #pragma unroll
        for (int kk = 0; kk < 4; kk++) {
            int col = kk*16 + (gi & 1)*8;
            uint32_t bh[4][4], bl[4][4];
            #pragma unroll
            for (int ng = 0; ng < 4; ng++) {
                int row = ng*16 + ii + (gi >> 1)*8;
                ldsm4(bh[ng], s2u(&Kh[row*FSTR + col]));
                ldsm4(bl[ng], s2u(&Kl[row*FSTR + col]));
            }
            #pragma unroll
            for (int ng = 0; ng < 4; ng++) {          // pass 1: qh*kh
                mma16816(s[2*ng],   qh[kk], &bh[ng][0]);
                mma16816(s[2*ng+1], qh[kk], &bh[ng][2]);
            }
            #pragma unroll
            for (int ng = 0; ng < 4; ng++) {          // pass 2: qh*kl
                mma16816(s[2*ng],   qh[kk], &bl[ng][0]);
                mma16816(s[2*ng+1], qh[kk], &bl[ng][2]);
            }
            #pragma unroll
            for (int ng = 0; ng < 4; ng++) {          // pass 3: ql*kh
                mma16816(s[2*ng],   ql[kk], &bh[ng][0]);
                mma16816(s[2*ng+1], ql[kk], &bh[ng][2]);
            }
        }

        // online softmax in exp2 domain
        float mx0 = -1e30f, mx1 = -1e30f;
        #pragma unroll
        for (int nt = 0; nt < 8; nt++) {
            mx0 = fmaxf(mx0, fmaxf(s[nt][0], s[nt][1]));
            mx1 = fmaxf(mx1, fmaxf(s[nt][2], s[nt][3]));
        }
        mx0 = fmaxf(mx0, __shfl_xor_sync(0xffffffffu, mx0, 1));
        mx0 = fmaxf(mx0, __shfl_xor_sync(0xffffffffu, mx0, 2));
        mx1 = fmaxf(mx1, __shfl_xor_sync(0xffffffffu, mx1, 1));
        mx1 = fmaxf(mx1, __shfl_xor_sync(0xffffffffu, mx1, 2));
        float nm0 = fmaxf(m0, mx0), nm1 = fmaxf(m1, mx1);
        float cr0 = fexp2(m0 - nm0), cr1 = fexp2(m1 - nm1);
        m0 = nm0; m1 = nm1;
        float sp0 = 0.f, sp1 = 0.f;
        #pragma unroll
        for (int nt = 0; nt < 8; nt++) {
            s[nt][0] = fexp2(s[nt][0] - m0); sp0 += s[nt][0];
            s[nt][1] = fexp2(s[nt][1] - m0); sp0 += s[nt][1];
            s[nt][2] = fexp2(s[nt][2] - m1); sp1 += s[nt][2];
            s[nt][3] = fexp2(s[nt][3] - m1); sp1 += s[nt][3];
        }
        l0 = l0*cr0 + sp0;
        l1 = l1*cr1 + sp1;
        // skip O rescale when no row in the warp changed max (cr==1 exactly)
        if (__ballot_sync(0xffffffffu, (cr0 < 1.f) | (cr1 < 1.f))) {
            #pragma unroll
            for (int nb = 0; nb < 8; nb++) {
                o[nb][0] *= cr0; o[nb][1] *= cr0;
                o[nb][2] *= cr1; o[nb][3] *= cr1;
            }
        }

        // O += P V (fp16, accumulator-interleaved)
        #pragma unroll
        for (int ks = 0; ks < 4; ks++) {
            uint32_t pa[4];
            {
                const float* s0 = s[2*ks];
                const float* s1 = s[2*ks+1];
                pa[0] = packh2(__float2half(s0[0]), __float2half(s0[1]));
                pa[1] = packh2(__float2half(s0[2]), __float2half(s0[3]));
                pa[2] = packh2(__float2half(s1[0]), __float2half(s1[1]));
                pa[3] = packh2(__float2half(s1[2]), __float2half(s1[3]));
            }
            int row = ks*16 + ii + (gi & 1)*8;
            uint32_t bh[4][4], bl[4][4];
            #pragma unroll
            for (int dg = 0; dg < 4; dg++) {
                int col = dg*16 + (gi >> 1)*8;
                ldsm4t(bh[dg], s2u(&Vh[row*FSTR + col]));
                ldsm4t(bl[dg], s2u(&Vl[row*FSTR + col]));
            }
            #pragma unroll
            for (int dg = 0; dg < 4; dg++) {          // pass 1: P*Vh
                mma16816h(o[2*dg],   pa, &bh[dg][0]);
                mma16816h(o[2*dg+1], pa, &bh[dg][2]);
            }
            #pragma unroll
            for (int dg = 0; dg < 4; dg++) {          // pass 2: P*Vl
                mma16816h(o[2*dg],   pa, &bl[dg][0]);
                mma16816h(o[2*dg+1], pa, &bl[dg][2]);
            }
        }
    }

    // finalize
    l0 += __shfl_xor_sync(0xffffffffu, l0, 1);
    l0 += __shfl_xor_sync(0xffffffffu, l0, 2);
    l1 += __shfl_xor_sync(0xffffffffu, l1, 1);
    l1 += __shfl_xor_sync(0xffffffffu, l1, 2);
    float inv0 = 1.f / l0, inv1 = 1.f / l1;

    int r0 = qt*64 + warp*16 + (lane >> 2);
    size_t o0 = ((size_t)b*SS + r0    )*(NH*HD) + h*HD;
    size_t o1 = ((size_t)b*SS + r0 + 8)*(NH*HD) + h*HD;
    #pragma unroll
    for (int nb = 0; nb < 8; nb++) {
        int d = nb*8 + 2*(lane & 3);
        __nv_bfloat16 h0,h1,l0_,l1_;
        split1(o[nb][0]*inv0, h0, l0_); split1(o[nb][1]*inv0, h1, l1_);
        *(__nv_bfloat162*)&g_aoh[o0 + d] = __nv_bfloat162(h0,h1);
        *(__nv_bfloat162*)&g_aol[o0 + d] = __nv_bfloat162(l0_,l1_);
        split1(o[nb][2]*inv1, h0, l0_); split1(o[nb][3]*inv1, h1, l1_);
        *(__nv_bfloat162*)&g_aoh[o1 + d] = __nv_bfloat162(h0,h1);
        *(__nv_bfloat162*)&g_aol[o1 + d] = __nv_bfloat162(l0_,l1_);
    }
}

// ---------------- O-proj GEMM ----------------------------------------------
__global__ __launch_bounds__(256) void oproj_gemm(
    const float* __restrict__ bo, float* __restrict__ C)
{
    extern __shared__ __nv_bfloat16 gsm[];
    const int tid = threadIdx.x, lane = tid & 31, warp = tid >> 5;
    const int wm = warp >> 2, wn = warp & 3;
    const int gi = lane >> 3, ii = lane & 7;
    const int bx = blockIdx.x, by = blockIdx.y;
    const int n0 = bx * 128;

    float c[4][4][4];
    #pragma unroll
    for (int i=0;i<4;i++) for (int j=0;j<4;j++) for (int e=0;e<4;e++) c[i][j][e]=0.f;

    load_gemm_tile(gsm, g_aoh, g_aol, g_woh, g_wol, by*128, n0, 0, tid);

    for (int t = 0; t < 32; t++) {
        cpa_wait0();
        __syncthreads();
        if (t < 31)
            load_gemm_tile(gsm + ((t+1)&1)*G_STAGE_E, g_aoh, g_aol, g_woh, g_wol,
                           by*128, n0, (t+1)*32, tid);
        gemm_compute(gsm + (t&1)*G_STAGE_E, c, wm, wn, gi, ii);
    }

    #pragma unroll
    for (int mi = 0; mi < 4; mi++)
        #pragma unroll
        for (int ni = 0; ni < 4; ni++)
            #pragma unroll
            for (int e = 0; e < 4; e++) {
                int m = by*128 + wm*64 + mi*16 + (lane >> 2) + ((e >= 2) ? 8 : 0);
                int n = n0 + wn*32 + ni*8 + 2*(lane & 3) + (e & 1);
                C[(size_t)m*HIDD + n] = c[mi][ni][e] + bo[n];
            }
}

// ---------------------------------------------------------------------------
extern "C" void kernel_launch(void* const* d_in, const int* in_sizes, int n_in,
                              void* d_out, int out_size)
{
    const float* X    = (const float*)d_in[0];
    const float* cosp = (const float*)d_in[1];
    const float* sinp = (const float*)d_in[2];
    const float* Wq   = (const float*)d_in[3];
    const float* bq   = (const float*)d_in[4];
    const float* Wk   = (const float*)d_in[5];
    const float* bk   = (const float*)d_in[6];
    const float* Wv   = (const float*)d_in[7];
    const float* bv   = (const float*)d_in[8];
    const float* Wo   = (const float*)d_in[9];
    const float* bo   = (const float*)d_in[10];
    float* out = (float*)d_out;

    const int gemm_smem  = 2 * G_STAGE_E * (int)sizeof(__nv_bfloat16);   // 81920
    const int flash_smem = 2 * F_STAGE_E * (int)sizeof(__nv_bfloat16);   // 73728
    cudaFuncSetAttribute(qkv_gemm,    cudaFuncAttributeMaxDynamicSharedMemorySize, gemm_smem);
    cudaFuncSetAttribute(oproj_gemm,  cudaFuncAttributeMaxDynamicSharedMemorySize, gemm_smem);
    cudaFuncSetAttribute(flash_kernel,cudaFuncAttributeMaxDynamicSharedMemorySize, flash_smem);

    int n4_total = N4_X + 2*N4_WQ + 2*N4_WK;
    split_all<<<(n4_total + 255)/256, 256>>>(X, Wq, Wk, Wv, Wo);

    dim3 g1(1536/128, 8192/128);
    qkv_gemm<<<g1, 256, gemm_smem>>>(bq, bk, bv);

    int tq = BB*NH *SS*32;
    int tk = BB*NKV*SS*32;
    rope_all<<<(tq + tk + 255)/256, 256>>>(cosp, sinp, tq, tq + tk);

    dim3 g3(SS/64, NH, BB);
    flash_kernel<<<g3, 128, flash_smem>>>();

    dim3 g4(1024/128, 8192/128);
    oproj_gemm<<<g4, 256, gemm_smem>>>(bo, out);
}

// round 10
// speedup vs baseline: 5.1960x; 1.3118x over previous
#include <cuda_runtime.h>
#include <cuda_bf16.h>
#include <cuda_fp16.h>
#include <cstdint>

#define BB   4
#define SS   2048
#define HIDD 1024
#define NH   16
#define NKV  4
#define HD   64
#define GROUPS 4
#define SCALE_F 0.125f
#define LOG2E 1.4426950408889634f

// ---------------- scratch (__device__ globals, allocation-free) -------------
__device__ float g_q[BB*NH*SS*HD];
__device__ float g_k[BB*NKV*SS*HD];
__device__ __half g_qh[BB*NH*SS*HD],  g_ql[BB*NH*SS*HD];   // Q hi/lo fp16
__device__ __half g_kf[BB*NKV*SS*HD];                      // K single fp16
__device__ __half g_vh[BB*NKV*SS*HD], g_vl[BB*NKV*SS*HD];  // V hi/lo fp16
__device__ __half g_xh[BB*SS*HIDD],   g_xl[BB*SS*HIDD];    // X hi/lo fp16
__device__ __half g_aoh[BB*SS*NH*HD], g_aol[BB*SS*NH*HD];  // attn out hi/lo
__device__ __half g_wqf[NH*HD*HIDD];                       // weights single fp16
__device__ __half g_wkf[NKV*HD*HIDD];
__device__ __half g_wvf[NKV*HD*HIDD];
__device__ __half g_wof[HIDD*NH*HD];

// ---------------- helpers ---------------------------------------------------
__device__ __forceinline__ uint32_t s2u(const void* p) {
    return (uint32_t)__cvta_generic_to_shared(p);
}
__device__ __forceinline__ void mma16816h(float* c, const uint32_t* a, const uint32_t* b) {
    asm volatile(
        "mma.sync.aligned.m16n8k16.row.col.f32.f16.f16.f32 "
        "{%0,%1,%2,%3}, {%4,%5,%6,%7}, {%8,%9}, {%0,%1,%2,%3};"
        : "+f"(c[0]), "+f"(c[1]), "+f"(c[2]), "+f"(c[3])
        : "r"(a[0]), "r"(a[1]), "r"(a[2]), "r"(a[3]), "r"(b[0]), "r"(b[1]));
}
__device__ __forceinline__ void ldsm4(uint32_t* r, uint32_t addr) {
    asm volatile("ldmatrix.sync.aligned.m8n8.x4.shared.b16 {%0,%1,%2,%3}, [%4];"
        : "=r"(r[0]), "=r"(r[1]), "=r"(r[2]), "=r"(r[3]) : "r"(addr));
}
__device__ __forceinline__ void ldsm4t(uint32_t* r, uint32_t addr) {
    asm volatile("ldmatrix.sync.aligned.m8n8.x4.trans.shared.b16 {%0,%1,%2,%3}, [%4];"
        : "=r"(r[0]), "=r"(r[1]), "=r"(r[2]), "=r"(r[3]) : "r"(addr));
}
__device__ __forceinline__ void cpa16(void* dst, const void* src) {
    asm volatile("cp.async.cg.shared.global [%0], [%1], 16;" :: "r"(s2u(dst)), "l"(src));
}
__device__ __forceinline__ void cpa_commit() {
    asm volatile("cp.async.commit_group;");
}
__device__ __forceinline__ void cpa_wait0() {
    asm volatile("cp.async.wait_group 0;" ::: "memory");
}
__device__ __forceinline__ float fexp2(float x) {
    float r;
    asm("ex2.approx.f32 %0, %1;" : "=f"(r) : "f"(x));
    return r;
}
__device__ __forceinline__ void split1h(float x, __half& h, __half& l) {
    h = __float2half(x);
    l = __float2half(x - __half2float(h));
}
__device__ __forceinline__ uint32_t packh2(__half a, __half b) {
    __half2 t; t.x = a; t.y = b;
    return *(uint32_t*)&t;
}
__device__ __forceinline__ void split4h_store(float4 v, __half* H, __half* L) {
    __half h0,h1,h2,h3,l0,l1,l2,l3;
    split1h(v.x,h0,l0); split1h(v.y,h1,l1); split1h(v.z,h2,l2); split1h(v.w,h3,l3);
    ((__half2*)H)[0] = __half2(h0,h1);
    ((__half2*)H)[1] = __half2(h2,h3);
    ((__half2*)L)[0] = __half2(l0,l1);
    ((__half2*)L)[1] = __half2(l2,l3);
}
__device__ __forceinline__ void cvt4h_store(float4 v, __half* D) {
    ((__half2*)D)[0] = __floats2half2_rn(v.x, v.y);
    ((__half2*)D)[1] = __floats2half2_rn(v.z, v.w);
}

// ---------------- pre-split: X -> hi/lo fp16; weights -> single fp16 --------
#define N4_X  (BB*SS*HIDD/4)
#define N4_WQ (NH*HD*HIDD/4)
#define N4_WK (NKV*HD*HIDD/4)
__global__ void split_all(const float* __restrict__ X,  const float* __restrict__ Wq,
                          const float* __restrict__ Wk, const float* __restrict__ Wv,
                          const float* __restrict__ Wo)
{
    int i = blockIdx.x * blockDim.x + threadIdx.x;
    if (i < N4_X) {
        float4 v = *(const float4*)&X[(size_t)i*4];
        split4h_store(v, &g_xh[(size_t)i*4], &g_xl[(size_t)i*4]);
        return;
    }
    i -= N4_X;
    const float* src; __half* dst; int off;
    if (i < N4_WQ)                 { src = Wq; dst = g_wqf; off = i; }
    else if ((i -= N4_WQ) < N4_WK) { src = Wk; dst = g_wkf; off = i; }
    else if ((i -= N4_WK) < N4_WK) { src = Wv; dst = g_wvf; off = i; }
    else if ((i -= N4_WK) < N4_WQ) { src = Wo; dst = g_wof; off = i; }
    else return;
    float4 v = *(const float4*)&src[(size_t)off*4];
    cvt4h_store(v, &dst[(size_t)off*4]);
}

// ---------------- GEMM common (BM128 BN128 BK32, 2-stage, fp16 2-term) ------
#define GSTR 40
#define G_AH  0
#define G_AL  5120
#define G_BF  10240
#define G_STAGE_E 15360   // halves per stage (30720 B)

__device__ __forceinline__ void load_gemm_tile(__half* st,
    const __half* Ahg, const __half* Alg, const __half* Bfg,
    int arow0, int brow0, int kt, int tid)
{
    #pragma unroll
    for (int p = 0; p < 2; p++) {
        int cidx = tid + p*256;
        int row = cidx >> 2, ch = (cidx & 3)*8;
        size_t so = (size_t)(arow0 + row)*HIDD + kt + ch;
        cpa16(&st[G_AH + row*GSTR + ch], Ahg + so);
        cpa16(&st[G_AL + row*GSTR + ch], Alg + so);
    }
    #pragma unroll
    for (int p = 0; p < 2; p++) {
        int cidx = tid + p*256;
        int row = cidx >> 2, ch = (cidx & 3)*8;
        size_t so = (size_t)(brow0 + row)*HIDD + kt + ch;
        cpa16(&st[G_BF + row*GSTR + ch], Bfg + so);
    }
    cpa_commit();
}

// fp16 2-term, accumulator-interleaved
__device__ __forceinline__ void gemm_compute(const __half* st,
    float c[4][4][4], int wm, int wn, int gi, int ii)
{
    #pragma unroll
    for (int ks = 0; ks < 2; ks++) {
        uint32_t ah[4][4], al[4][4], bf[2][4];
        #pragma unroll
        for (int mi = 0; mi < 4; mi++) {
            int row = wm*64 + mi*16 + ii + (gi & 1)*8;
            int col = ks*16 + (gi >> 1)*8;
            ldsm4(ah[mi], s2u(&st[G_AH + row*GSTR + col]));
            ldsm4(al[mi], s2u(&st[G_AL + row*GSTR + col]));
        }
        #pragma unroll
        for (int ng = 0; ng < 2; ng++) {
            int row = wn*32 + ng*16 + ii + (gi >> 1)*8;
            int col = ks*16 + (gi & 1)*8;
            ldsm4(bf[ng], s2u(&st[G_BF + row*GSTR + col]));
        }
        #pragma unroll
        for (int mi = 0; mi < 4; mi++)          // pass 1: Ahi * B
            #pragma unroll
            for (int ng = 0; ng < 2; ng++) {
                mma16816h(c[mi][2*ng],   ah[mi], &bf[ng][0]);
                mma16816h(c[mi][2*ng+1], ah[mi], &bf[ng][2]);
            }
        #pragma unroll
        for (int mi = 0; mi < 4; mi++)          // pass 2: Alo * B
            #pragma unroll
            for (int ng = 0; ng < 2; ng++) {
                mma16816h(c[mi][2*ng],   al[mi], &bf[ng][0]);
                mma16816h(c[mi][2*ng+1], al[mi], &bf[ng][2]);
            }
    }
}

// ---------------- QKV GEMM ---------------------------------------------------
__global__ __launch_bounds__(256) void qkv_gemm(
    const float* __restrict__ bq, const float* __restrict__ bk, const float* __restrict__ bv)
{
    extern __shared__ __half gsm[];
    const int tid = threadIdx.x, lane = tid & 31, warp = tid >> 5;
    const int wm = warp >> 2, wn = warp & 3;
    const int gi = lane >> 3, ii = lane & 7;
    const int bx = blockIdx.x, by = blockIdx.y;
    const int n0 = bx * 128;

    const __half* Wf; const float* bias; int noff;
    if (n0 < 1024)      { Wf = g_wqf; bias = bq; noff = 0;    }
    else if (n0 < 1280) { Wf = g_wkf; bias = bk; noff = 1024; }
    else                { Wf = g_wvf; bias = bv; noff = 1280; }

    float c[4][4][4];
    #pragma unroll
    for (int i=0;i<4;i++) for (int j=0;j<4;j++) for (int e=0;e<4;e++) c[i][j][e]=0.f;

    load_gemm_tile(gsm, g_xh, g_xl, Wf, by*128, n0 - noff, 0, tid);

    for (int t = 0; t < 32; t++) {
        cpa_wait0();
        __syncthreads();
        if (t < 31)
            load_gemm_tile(gsm + ((t+1)&1)*G_STAGE_E, g_xh, g_xl, Wf,
                           by*128, n0 - noff, (t+1)*32, tid);
        gemm_compute(gsm + (t&1)*G_STAGE_E, c, wm, wn, gi, ii);
    }

    #pragma unroll
    for (int mi = 0; mi < 4; mi++)
        #pragma unroll
        for (int ni = 0; ni < 4; ni++)
            #pragma unroll
            for (int e = 0; e < 4; e++) {
                int m = by*128 + wm*64 + mi*16 + (lane >> 2) + ((e >= 2) ? 8 : 0);
                int n = n0 + wn*32 + ni*8 + 2*(lane & 3) + (e & 1);
                int b_ = m >> 11, s = m & 2047;
                float val = c[mi][ni][e] + bias[n - noff];
                if (n < 1024) {
                    int h = n >> 6, d = n & 63;
                    g_q[(((size_t)b_*NH + h)*SS + s)*HD + d] = val;
                } else if (n < 1280) {
                    int nn = n - 1024; int h = nn >> 6, d = nn & 63;
                    g_k[(((size_t)b_*NKV + h)*SS + s)*HD + d] = val;
                } else {
                    int nn = n - 1280; int h = nn >> 6, d = nn & 63;
                    size_t off = (((size_t)b_*NKV + h)*SS + s)*HD + d;
                    __half hh, ll; split1h(val, hh, ll);
                    g_vh[off] = hh; g_vl[off] = ll;
                }
            }
}

// ---------------- RoPE; q -> split fp16 (scaled), k -> single fp16 ----------
__global__ void rope_all(const float* __restrict__ cos_t,
                         const float* __restrict__ sin_t, int tq, int total)
{
    int idx = blockIdx.x * blockDim.x + threadIdx.x;
    if (idx >= total) return;
    int which = (idx >= tq);
    if (which) idx -= tq;
    int d  = idx & 31;
    int s  = (idx >> 5) & 2047;
    int bh = idx >> 16;
    size_t base = ((size_t)bh*SS + s)*HD;
    const float* src = which ? g_k : g_q;
    float scale = which ? 1.0f : (SCALE_F * LOG2E);
    float x1 = src[base + d], x2 = src[base + d + 32];
    float c1 = cos_t[s*HD + d],      s1 = sin_t[s*HD + d];
    float c2 = cos_t[s*HD + d + 32], s2 = sin_t[s*HD + d + 32];
    float y1 = (x1*c1 - x2*s1) * scale;
    float y2 = (x2*c2 + x1*s2) * scale;
    if (which) {
        g_kf[base + d]      = __float2half(y1);
        g_kf[base + d + 32] = __float2half(y2);
    } else {
        __half hh, ll;
        split1h(y1, hh, ll); g_qh[base + d]      = hh; g_ql[base + d]      = ll;
        split1h(y2, hh, ll); g_qh[base + d + 32] = hh; g_ql[base + d + 32] = ll;
    }
}

// ---------------- flash attention (64 q-rows, 64-key tiles, 2-stage) --------
#define FSTR 72
#define F_ARR (64*FSTR)
#define F_STAGE_E (3*F_ARR)     // Kf, Vh, Vl

__device__ __forceinline__ void load_kv_tile(__half* st,
    const __half* kfg, const __half* vhg, const __half* vlg, int t, int tid)
{
    #pragma unroll
    for (int p = 0; p < 4; p++) {
        int cidx = tid + p*128;
        int row = cidx >> 3, ch = (cidx & 7)*8;
        size_t so = ((size_t)t*64 + row)*HD + ch;
        cpa16(&st[          row*FSTR + ch], kfg + so);
        cpa16(&st[  F_ARR + row*FSTR + ch], vhg + so);
        cpa16(&st[2*F_ARR + row*FSTR + ch], vlg + so);
    }
    cpa_commit();
}

__global__ __launch_bounds__(128) void flash_kernel()
{
    extern __shared__ __half fsm[];

    const int b = blockIdx.z, h = blockIdx.y, qt = blockIdx.x;
    const int tid = threadIdx.x, lane = tid & 31, warp = tid >> 5;
    const int hk = h / GROUPS;
    const int gi = lane >> 3, ii = lane & 7;

    const __half* qhg = g_qh + (((size_t)b*NH  + h )*SS + qt*64)*HD;
    const __half* qlg = g_ql + (((size_t)b*NH  + h )*SS + qt*64)*HD;
    const __half* kfg = g_kf + (((size_t)b*NKV + hk)*SS)*HD;
    const __half* vhg = g_vh + (((size_t)b*NKV + hk)*SS)*HD;
    const __half* vlg = g_vl + (((size_t)b*NKV + hk)*SS)*HD;

    // stage Q (hi/lo) through stage-0 smem, grab fragments
    {
        #pragma unroll
        for (int p = 0; p < 4; p++) {
            int cidx = tid + p*128;
            int row = cidx >> 3, ch = (cidx & 7)*8;
            size_t so = (size_t)row*HD + ch;
            cpa16(&fsm[         row*FSTR + ch], qhg + so);
            cpa16(&fsm[F_ARR + row*FSTR + ch], qlg + so);
        }
        cpa_commit();
        cpa_wait0();
        __syncthreads();
    }

    uint32_t qh[4][4], ql[4][4];
    #pragma unroll
    for (int kk = 0; kk < 4; kk++) {
        int row = warp*16 + ii + (gi & 1)*8;
        int col = kk*16 + (gi >> 1)*8;
        ldsm4(qh[kk], s2u(&fsm[         row*FSTR + col]));
        ldsm4(ql[kk], s2u(&fsm[F_ARR + row*FSTR + col]));
    }
    __syncthreads();

    load_kv_tile(fsm, kfg, vhg, vlg, 0, tid);

    float o[8][4];
    #pragma unroll
    for (int i = 0; i < 8; i++) for (int j = 0; j < 4; j++) o[i][j] = 0.f;
    float m0 = -1e30f, m1 = -1e30f, l0 = 0.f, l1 = 0.f;

    for (int t = 0; t < SS/64; t++) {
        cpa_wait0();
        __syncthreads();
        if (t < SS/64 - 1)
            load_kv_tile(fsm + ((t+1)&1)*F_STAGE_E, kfg, vhg, vlg, t+1, tid);

        const __half* Kf = fsm + (t&1)*F_STAGE_E;
        const __half* Vh = Kf + F_ARR;
        const __half* Vl = Kf + 2*F_ARR;

        // S = Q K^T (fp16: Q hi+lo, K single -> 2 MMAs/tile-frag)
        float s[8][4];
        #pragma unroll
        for (int i = 0; i < 8; i++) for (int j = 0; j < 4; j++) s[i][j] = 0.f;
        #pragma unroll
        for (int kk = 0; kk < 4; kk++) {
            int col = kk*16 + (gi & 1)*8;
            uint32_t kf[4][4];
            #pragma unroll
            for (int ng = 0; ng < 4; ng++) {
                int row = ng*16 + ii + (gi >> 1)*8;
                ldsm4(kf[ng], s2u(&Kf[row*FSTR + col]));
            }
            #pragma unroll
            for (int ng = 0; ng < 4; ng++) {          // pass 1: qh*k
                mma16816h(s[2*ng],   qh[kk], &kf[ng][0]);
                mma16816h(s[2*ng+1], qh[kk], &kf[ng][2]);
            }
            #pragma unroll
            for (int ng = 0; ng < 4; ng++) {          // pass 2: ql*k
                mma16816h(s[2*ng],   ql[kk], &kf[ng][0]);
                mma16816h(s[2*ng+1], ql[kk], &kf[ng][2]);
            }
        }

        // online softmax in exp2 domain
        float mx0 = -1e30f, mx1 = -1e30f;
        #pragma unroll
        for (int nt = 0; nt < 8; nt++) {
            mx0 = fmaxf(mx0, fmaxf(s[nt][0], s[nt][1]));
            mx1 = fmaxf(mx1, fmaxf(s[nt][2], s[nt][3]));
        }
        mx0 = fmaxf(mx0, __shfl_xor_sync(0xffffffffu, mx0, 1));
        mx0 = fmaxf(mx0, __shfl_xor_sync(0xffffffffu, mx0, 2));
        mx1 = fmaxf(mx1, __shfl_xor_sync(0xffffffffu, mx1, 1));
        mx1 = fmaxf(mx1, __shfl_xor_sync(0xffffffffu, mx1, 2));
        float nm0 = fmaxf(m0, mx0), nm1 = fmaxf(m1, mx1);
        float cr0 = fexp2(m0 - nm0), cr1 = fexp2(m1 - nm1);
        m0 = nm0; m1 = nm1;
        float sp0 = 0.f, sp1 = 0.f;
        #pragma unroll
        for (int nt = 0; nt < 8; nt++) {
            s[nt][0] = fexp2(s[nt][0] - m0); sp0 += s[nt][0];
            s[nt][1] = fexp2(s[nt][1] - m0); sp0 += s[nt][1];
            s[nt][2] = fexp2(s[nt][2] - m1); sp1 += s[nt][2];
            s[nt][3] = fexp2(s[nt][3] - m1); sp1 += s[nt][3];
        }
        l0 = l0*cr0 + sp0;
        l1 = l1*cr1 + sp1;
        if (__ballot_sync(0xffffffffu, (cr0 < 1.f) | (cr1 < 1.f))) {
            #pragma unroll
            for (int nb = 0; nb < 8; nb++) {
                o[nb][0] *= cr0; o[nb][1] *= cr0;
                o[nb][2] *= cr1; o[nb][3] *= cr1;
            }
        }

        // O += P V (fp16: P single, V hi+lo)
        #pragma unroll
        for (int ks = 0; ks < 4; ks++) {
            uint32_t pa[4];
            {
                const float* s0 = s[2*ks];
                const float* s1 = s[2*ks+1];
                pa[0] = packh2(__float2half(s0[0]), __float2half(s0[1]));
                pa[1] = packh2(__float2half(s0[2]), __float2half(s0[3]));
                pa[2] = packh2(__float2half(s1[0]), __float2half(s1[1]));
                pa[3] = packh2(__float2half(s1[2]), __float2half(s1[3]));
            }
            int row = ks*16 + ii + (gi & 1)*8;
            uint32_t bh[4][4], bl[4][4];
            #pragma unroll
            for (int dg = 0; dg < 4; dg++) {
                int col = dg*16 + (gi >> 1)*8;
                ldsm4t(bh[dg], s2u(&Vh[row*FSTR + col]));
                ldsm4t(bl[dg], s2u(&Vl[row*FSTR + col]));
            }
            #pragma unroll
            for (int dg = 0; dg < 4; dg++) {          // pass 1: P*Vh
                mma16816h(o[2*dg],   pa, &bh[dg][0]);
                mma16816h(o[2*dg+1], pa, &bh[dg][2]);
            }
            #pragma unroll
            for (int dg = 0; dg < 4; dg++) {          // pass 2: P*Vl
                mma16816h(o[2*dg],   pa, &bl[dg][0]);
                mma16816h(o[2*dg+1], pa, &bl[dg][2]);
            }
        }
    }

    // finalize
    l0 += __shfl_xor_sync(0xffffffffu, l0, 1);
    l0 += __shfl_xor_sync(0xffffffffu, l0, 2);
    l1 += __shfl_xor_sync(0xffffffffu, l1, 1);
    l1 += __shfl_xor_sync(0xffffffffu, l1, 2);
    float inv0 = 1.f / l0, inv1 = 1.f / l1;

    int r0 = qt*64 + warp*16 + (lane >> 2);
    size_t o0 = ((size_t)b*SS + r0    )*(NH*HD) + h*HD;
    size_t o1 = ((size_t)b*SS + r0 + 8)*(NH*HD) + h*HD;
    #pragma unroll
    for (int nb = 0; nb < 8; nb++) {
        int d = nb*8 + 2*(lane & 3);
        __half h0,h1,l0_,l1_;
        split1h(o[nb][0]*inv0, h0, l0_); split1h(o[nb][1]*inv0, h1, l1_);
        *(__half2*)&g_aoh[o0 + d] = __half2(h0,h1);
        *(__half2*)&g_aol[o0 + d] = __half2(l0_,l1_);
        split1h(o[nb][2]*inv1, h0, l0_); split1h(o[nb][3]*inv1, h1, l1_);
        *(__half2*)&g_aoh[o1 + d] = __half2(h0,h1);
        *(__half2*)&g_aol[o1 + d] = __half2(l0_,l1_);
    }
}

// ---------------- O-proj GEMM ----------------------------------------------
__global__ __launch_bounds__(256) void oproj_gemm(
    const float* __restrict__ bo, float* __restrict__ C)
{
    extern __shared__ __half gsm[];
    const int tid = threadIdx.x, lane = tid & 31, warp = tid >> 5;
    const int wm = warp >> 2, wn = warp & 3;
    const int gi = lane >> 3, ii = lane & 7;
    const int bx = blockIdx.x, by = blockIdx.y;
    const int n0 = bx * 128;

    float c[4][4][4];
    #pragma unroll
    for (int i=0;i<4;i++) for (int j=0;j<4;j++) for (int e=0;e<4;e++) c[i][j][e]=0.f;

    load_gemm_tile(gsm, g_aoh, g_aol, g_wof, by*128, n0, 0, tid);

    for (int t = 0; t < 32; t++) {
        cpa_wait0();
        __syncthreads();
        if (t < 31)
            load_gemm_tile(gsm + ((t+1)&1)*G_STAGE_E, g_aoh, g_aol, g_wof,
                           by*128, n0, (t+1)*32, tid);
        gemm_compute(gsm + (t&1)*G_STAGE_E, c, wm, wn, gi, ii);
    }

    #pragma unroll
    for (int mi = 0; mi < 4; mi++)
        #pragma unroll
        for (int ni = 0; ni < 4; ni++)
            #pragma unroll
            for (int e = 0; e < 4; e++) {
                int m = by*128 + wm*64 + mi*16 + (lane >> 2) + ((e >= 2) ? 8 : 0);
                int n = n0 + wn*32 + ni*8 + 2*(lane & 3) + (e & 1);
                C[(size_t)m*HIDD + n] = c[mi][ni][e] + bo[n];
            }
}

// ---------------------------------------------------------------------------
extern "C" void kernel_launch(void* const* d_in, const int* in_sizes, int n_in,
                              void* d_out, int out_size)
{
    const float* X    = (const float*)d_in[0];
    const float* cosp = (const float*)d_in[1];
    const float* sinp = (const float*)d_in[2];
    const float* Wq   = (const float*)d_in[3];
    const float* bq   = (const float*)d_in[4];
    const float* Wk   = (const float*)d_in[5];
    const float* bk   = (const float*)d_in[6];
    const float* Wv   = (const float*)d_in[7];
    const float* bv   = (const float*)d_in[8];
    const float* Wo   = (const float*)d_in[9];
    const float* bo   = (const float*)d_in[10];
    float* out = (float*)d_out;

    const int gemm_smem  = 2 * G_STAGE_E * (int)sizeof(__half);   // 61440
    const int flash_smem = 2 * F_STAGE_E * (int)sizeof(__half);   // 55296
    cudaFuncSetAttribute(qkv_gemm,    cudaFuncAttributeMaxDynamicSharedMemorySize, gemm_smem);
    cudaFuncSetAttribute(oproj_gemm,  cudaFuncAttributeMaxDynamicSharedMemorySize, gemm_smem);
    cudaFuncSetAttribute(flash_kernel,cudaFuncAttributeMaxDynamicSharedMemorySize, flash_smem);

    int n4_total = N4_X + 2*N4_WQ + 2*N4_WK;
    split_all<<<(n4_total + 255)/256, 256>>>(X, Wq, Wk, Wv, Wo);

    dim3 g1(1536/128, 8192/128);
    qkv_gemm<<<g1, 256, gemm_smem>>>(bq, bk, bv);

    int tq = BB*NH *SS*32;
    int tk = BB*NKV*SS*32;
    rope_all<<<(tq + tk + 255)/256, 256>>>(cosp, sinp, tq, tq + tk);

    dim3 g3(SS/64, NH, BB);
    flash_kernel<<<g3, 128, flash_smem>>>();

    dim3 g4(1024/128, 8192/128);
    oproj_gemm<<<g4, 256, gemm_smem>>>(bo, out);
}

// round 12
// speedup vs baseline: 6.5109x; 1.2531x over previous
#include <cuda_runtime.h>
#include <cuda_bf16.h>
#include <cuda_fp16.h>
#include <cstdint>

#define BB   4
#define SS   2048
#define HIDD 1024
#define NH   16
#define NKV  4
#define HD   64
#define GROUPS 4
#define SCALE_F 0.125f
#define LOG2E 1.4426950408889634f

// ---------------- scratch (__device__ globals, allocation-free) -------------
__device__ float g_q[BB*NH*SS*HD];
__device__ float g_k[BB*NKV*SS*HD];
__device__ __half g_qf[BB*NH*SS*HD];                       // Q single fp16 (scaled)
__device__ __half g_kf[BB*NKV*SS*HD];                      // K single fp16
__device__ __half g_vf[BB*NKV*SS*HD];                      // V single fp16
__device__ __half g_xh[BB*SS*HIDD],   g_xl[BB*SS*HIDD];    // X hi/lo fp16
__device__ __half g_aoh[BB*SS*NH*HD], g_aol[BB*SS*NH*HD];  // attn out hi/lo
__device__ __half g_wqf[NH*HD*HIDD];                       // weights single fp16
__device__ __half g_wkf[NKV*HD*HIDD];
__device__ __half g_wvf[NKV*HD*HIDD];
__device__ __half g_wof[HIDD*NH*HD];

// ---------------- helpers ---------------------------------------------------
__device__ __forceinline__ uint32_t s2u(const void* p) {
    return (uint32_t)__cvta_generic_to_shared(p);
}
__device__ __forceinline__ void mma16816h(float* c, const uint32_t* a, const uint32_t* b) {
    asm volatile(
        "mma.sync.aligned.m16n8k16.row.col.f32.f16.f16.f32 "
        "{%0,%1,%2,%3}, {%4,%5,%6,%7}, {%8,%9}, {%0,%1,%2,%3};"
        : "+f"(c[0]), "+f"(c[1]), "+f"(c[2]), "+f"(c[3])
        : "r"(a[0]), "r"(a[1]), "r"(a[2]), "r"(a[3]), "r"(b[0]), "r"(b[1]));
}
__device__ __forceinline__ void ldsm4(uint32_t* r, uint32_t addr) {
    asm volatile("ldmatrix.sync.aligned.m8n8.x4.shared.b16 {%0,%1,%2,%3}, [%4];"
        : "=r"(r[0]), "=r"(r[1]), "=r"(r[2]), "=r"(r[3]) : "r"(addr));
}
__device__ __forceinline__ void ldsm4t(uint32_t* r, uint32_t addr) {
    asm volatile("ldmatrix.sync.aligned.m8n8.x4.trans.shared.b16 {%0,%1,%2,%3}, [%4];"
        : "=r"(r[0]), "=r"(r[1]), "=r"(r[2]), "=r"(r[3]) : "r"(addr));
}
__device__ __forceinline__ void cpa16(void* dst, const void* src) {
    asm volatile("cp.async.cg.shared.global [%0], [%1], 16;" :: "r"(s2u(dst)), "l"(src));
}
__device__ __forceinline__ void cpa_commit() {
    asm volatile("cp.async.commit_group;");
}
__device__ __forceinline__ void cpa_wait0() {
    asm volatile("cp.async.wait_group 0;" ::: "memory");
}
__device__ __forceinline__ float fexp2(float x) {
    float r;
    asm("ex2.approx.f32 %0, %1;" : "=f"(r) : "f"(x));
    return r;
}
__device__ __forceinline__ void split1h(float x, __half& h, __half& l) {
    h = __float2half(x);
    l = __float2half(x - __half2float(h));
}
__device__ __forceinline__ uint32_t packh2(__half a, __half b) {
    __half2 t; t.x = a; t.y = b;
    return *(uint32_t*)&t;
}
__device__ __forceinline__ void split4h_store(float4 v, __half* H, __half* L) {
    __half h0,h1,h2,h3,l0,l1,l2,l3;
    split1h(v.x,h0,l0); split1h(v.y,h1,l1); split1h(v.z,h2,l2); split1h(v.w,h3,l3);
    ((__half2*)H)[0] = __half2(h0,h1);
    ((__half2*)H)[1] = __half2(h2,h3);
    ((__half2*)L)[0] = __half2(l0,l1);
    ((__half2*)L)[1] = __half2(l2,l3);
}
__device__ __forceinline__ void cvt4h_store(float4 v, __half* D) {
    ((__half2*)D)[0] = __floats2half2_rn(v.x, v.y);
    ((__half2*)D)[1] = __floats2half2_rn(v.z, v.w);
}

// ---------------- pre-split: X -> hi/lo fp16; weights -> single fp16 --------
#define N4_X  (BB*SS*HIDD/4)
#define N4_WQ (NH*HD*HIDD/4)
#define N4_WK (NKV*HD*HIDD/4)
__global__ void split_all(const float* __restrict__ X,  const float* __restrict__ Wq,
                          const float* __restrict__ Wk, const float* __restrict__ Wv,
                          const float* __restrict__ Wo)
{
    int i = blockIdx.x * blockDim.x + threadIdx.x;
    if (i < N4_X) {
        float4 v = *(const float4*)&X[(size_t)i*4];
        split4h_store(v, &g_xh[(size_t)i*4], &g_xl[(size_t)i*4]);
        return;
    }
    i -= N4_X;
    const float* src; __half* dst; int off;
    if (i < N4_WQ)                 { src = Wq; dst = g_wqf; off = i; }
    else if ((i -= N4_WQ) < N4_WK) { src = Wk; dst = g_wkf; off = i; }
    else if ((i -= N4_WK) < N4_WK) { src = Wv; dst = g_wvf; off = i; }
    else if ((i -= N4_WK) < N4_WQ) { src = Wo; dst = g_wof; off = i; }
    else return;
    float4 v = *(const float4*)&src[(size_t)off*4];
    cvt4h_store(v, &dst[(size_t)off*4]);
}

// ---------------- GEMM common (BM128 BN128 BK32, 2-stage, fp16 2-term) ------
#define GSTR 40
#define G_AH  0
#define G_AL  5120
#define G_BF  10240
#define G_STAGE_E 15360   // halves per stage (30720 B)

__device__ __forceinline__ void load_gemm_tile(__half* st,
    const __half* Ahg, const __half* Alg, const __half* Bfg,
    int arow0, int brow0, int kt, int tid)
{
    #pragma unroll
    for (int p = 0; p < 2; p++) {
        int cidx = tid + p*256;
        int row = cidx >> 2, ch = (cidx & 3)*8;
        size_t so = (size_t)(arow0 + row)*HIDD + kt + ch;
        cpa16(&st[G_AH + row*GSTR + ch], Ahg + so);
        cpa16(&st[G_AL + row*GSTR + ch], Alg + so);
    }
    #pragma unroll
    for (int p = 0; p < 2; p++) {
        int cidx = tid + p*256;
        int row = cidx >> 2, ch = (cidx & 3)*8;
        size_t so = (size_t)(brow0 + row)*HIDD + kt + ch;
        cpa16(&st[G_BF + row*GSTR + ch], Bfg + so);
    }
    cpa_commit();
}

// fp16 2-term (A hi/lo x B single), accumulator-interleaved
__device__ __forceinline__ void gemm_compute(const __half* st,
    float c[4][4][4], int wm, int wn, int gi, int ii)
{
    #pragma unroll
    for (int ks = 0; ks < 2; ks++) {
        uint32_t ah[4][4], al[4][4], bf[2][4];
        #pragma unroll
        for (int mi = 0; mi < 4; mi++) {
            int row = wm*64 + mi*16 + ii + (gi & 1)*8;
            int col = ks*16 + (gi >> 1)*8;
            ldsm4(ah[mi], s2u(&st[G_AH + row*GSTR + col]));
            ldsm4(al[mi], s2u(&st[G_AL + row*GSTR + col]));
        }
        #pragma unroll
        for (int ng = 0; ng < 2; ng++) {
            int row = wn*32 + ng*16 + ii + (gi >> 1)*8;
            int col = ks*16 + (gi & 1)*8;
            ldsm4(bf[ng], s2u(&st[G_BF + row*GSTR + col]));
        }
        #pragma unroll
        for (int mi = 0; mi < 4; mi++)          // pass 1: Ahi * B
            #pragma unroll
            for (int ng = 0; ng < 2; ng++) {
                mma16816h(c[mi][2*ng],   ah[mi], &bf[ng][0]);
                mma16816h(c[mi][2*ng+1], ah[mi], &bf[ng][2]);
            }
        #pragma unroll
        for (int mi = 0; mi < 4; mi++)          // pass 2: Alo * B
            #pragma unroll
            for (int ng = 0; ng < 2; ng++) {
                mma16816h(c[mi][2*ng],   al[mi], &bf[ng][0]);
                mma16816h(c[mi][2*ng+1], al[mi], &bf[ng][2]);
            }
    }
}

// ---------------- QKV GEMM ---------------------------------------------------
__global__ __launch_bounds__(256) void qkv_gemm(
    const float* __restrict__ bq, const float* __restrict__ bk, const float* __restrict__ bv)
{
    extern __shared__ __half gsm[];
    const int tid = threadIdx.x, lane = tid & 31, warp = tid >> 5;
    const int wm = warp >> 2, wn = warp & 3;
    const int gi = lane >> 3, ii = lane & 7;
    const int bx = blockIdx.x, by = blockIdx.y;
    const int n0 = bx * 128;

    const __half* Wf; const float* bias; int noff;
    if (n0 < 1024)      { Wf = g_wqf; bias = bq; noff = 0;    }
    else if (n0 < 1280) { Wf = g_wkf; bias = bk; noff = 1024; }
    else                { Wf = g_wvf; bias = bv; noff = 1280; }

    float c[4][4][4];
    #pragma unroll
    for (int i=0;i<4;i++) for (int j=0;j<4;j++) for (int e=0;e<4;e++) c[i][j][e]=0.f;

    load_gemm_tile(gsm, g_xh, g_xl, Wf, by*128, n0 - noff, 0, tid);

    for (int t = 0; t < 32; t++) {
        cpa_wait0();
        __syncthreads();
        if (t < 31)
            load_gemm_tile(gsm + ((t+1)&1)*G_STAGE_E, g_xh, g_xl, Wf,
                           by*128, n0 - noff, (t+1)*32, tid);
        gemm_compute(gsm + (t&1)*G_STAGE_E, c, wm, wn, gi, ii);
    }

    #pragma unroll
    for (int mi = 0; mi < 4; mi++)
        #pragma unroll
        for (int ni = 0; ni < 4; ni++)
            #pragma unroll
            for (int e = 0; e < 4; e++) {
                int m = by*128 + wm*64 + mi*16 + (lane >> 2) + ((e >= 2) ? 8 : 0);
                int n = n0 + wn*32 + ni*8 + 2*(lane & 3) + (e & 1);
                int b_ = m >> 11, s = m & 2047;
                float val = c[mi][ni][e] + bias[n - noff];
                if (n < 1024) {
                    int h = n >> 6, d = n & 63;
                    g_q[(((size_t)b_*NH + h)*SS + s)*HD + d] = val;
                } else if (n < 1280) {
                    int nn = n - 1024; int h = nn >> 6, d = nn & 63;
                    g_k[(((size_t)b_*NKV + h)*SS + s)*HD + d] = val;
                } else {
                    int nn = n - 1280; int h = nn >> 6, d = nn & 63;
                    size_t off = (((size_t)b_*NKV + h)*SS + s)*HD + d;
                    g_vf[off] = __float2half(val);
                }
            }
}

// ---------------- RoPE; q -> single fp16 (scaled), k -> single fp16 ---------
__global__ void rope_all(const float* __restrict__ cos_t,
                         const float* __restrict__ sin_t, int tq, int total)
{
    int idx = blockIdx.x * blockDim.x + threadIdx.x;
    if (idx >= total) return;
    int which = (idx >= tq);
    if (which) idx -= tq;
    int d  = idx & 31;
    int s  = (idx >> 5) & 2047;
    int bh = idx >> 16;
    size_t base = ((size_t)bh*SS + s)*HD;
    const float* src = which ? g_k : g_q;
    __half* dst = which ? g_kf : g_qf;
    float scale = which ? 1.0f : (SCALE_F * LOG2E);
    float x1 = src[base + d], x2 = src[base + d + 32];
    float c1 = cos_t[s*HD + d],      s1 = sin_t[s*HD + d];
    float c2 = cos_t[s*HD + d + 32], s2 = sin_t[s*HD + d + 32];
    dst[base + d]      = __float2half((x1*c1 - x2*s1) * scale);
    dst[base + d + 32] = __float2half((x2*c2 + x1*s2) * scale);
}

// ---------------- flash attention (64 q-rows, 64-key tiles, 2-stage) --------
#define FSTR 72
#define F_ARR (64*FSTR)
#define F_STAGE_E (2*F_ARR)     // Kf, Vf

__device__ __forceinline__ void load_kv_tile(__half* st,
    const __half* kfg, const __half* vfg, int t, int tid)
{
    #pragma unroll
    for (int p = 0; p < 4; p++) {
        int cidx = tid + p*128;
        int row = cidx >> 3, ch = (cidx & 7)*8;
        size_t so = ((size_t)t*64 + row)*HD + ch;
        cpa16(&st[        row*FSTR + ch], kfg + so);
        cpa16(&st[F_ARR + row*FSTR + ch], vfg + so);
    }
    cpa_commit();
}

__global__ __launch_bounds__(128) void flash_kernel()
{
    extern __shared__ __half fsm[];

    const int b = blockIdx.z, h = blockIdx.y, qt = blockIdx.x;
    const int tid = threadIdx.x, lane = tid & 31, warp = tid >> 5;
    const int hk = h / GROUPS;
    const int gi = lane >> 3, ii = lane & 7;

    const __half* qfg = g_qf + (((size_t)b*NH  + h )*SS + qt*64)*HD;
    const __half* kfg = g_kf + (((size_t)b*NKV + hk)*SS)*HD;
    const __half* vfg = g_vf + (((size_t)b*NKV + hk)*SS)*HD;

    // stage Q through stage-0 smem, grab fragments
    {
        #pragma unroll
        for (int p = 0; p < 4; p++) {
            int cidx = tid + p*128;
            int row = cidx >> 3, ch = (cidx & 7)*8;
            size_t so = (size_t)row*HD + ch;
            cpa16(&fsm[row*FSTR + ch], qfg + so);
        }
        cpa_commit();
        cpa_wait0();
        __syncthreads();
    }

    uint32_t qf[4][4];
    #pragma unroll
    for (int kk = 0; kk < 4; kk++) {
        int row = warp*16 + ii + (gi & 1)*8;
        int col = kk*16 + (gi >> 1)*8;
        ldsm4(qf[kk], s2u(&fsm[row*FSTR + col]));
    }
    __syncthreads();

    load_kv_tile(fsm, kfg, vfg, 0, tid);

    float o[8][4];
    #pragma unroll
    for (int i = 0; i < 8; i++) for (int j = 0; j < 4; j++) o[i][j] = 0.f;
    float m0 = -1e30f, m1 = -1e30f, l0 = 0.f, l1 = 0.f;

    for (int t = 0; t < SS/64; t++) {
        cpa_wait0();
        __syncthreads();
        if (t < SS/64 - 1)
            load_kv_tile(fsm + ((t+1)&1)*F_STAGE_E, kfg, vfg, t+1, tid);

        const __half* Kf = fsm + (t&1)*F_STAGE_E;
        const __half* Vf = Kf + F_ARR;

        // S = Q K^T (single fp16)
        float s[8][4];
        #pragma unroll
        for (int i = 0; i < 8; i++) for (int j = 0; j < 4; j++) s[i][j] = 0.f;
        #pragma unroll
        for (int kk = 0; kk < 4; kk++) {
            int col = kk*16 + (gi & 1)*8;
            uint32_t kf[4][4];
            #pragma unroll
            for (int ng = 0; ng < 4; ng++) {
                int row = ng*16 + ii + (gi >> 1)*8;
                ldsm4(kf[ng], s2u(&Kf[row*FSTR + col]));
            }
            #pragma unroll
            for (int ng = 0; ng < 4; ng++) {
                mma16816h(s[2*ng],   qf[kk], &kf[ng][0]);
                mma16816h(s[2*ng+1], qf[kk], &kf[ng][2]);
            }
        }

        // online softmax in exp2 domain
        float mx0 = -1e30f, mx1 = -1e30f;
        #pragma unroll
        for (int nt = 0; nt < 8; nt++) {
            mx0 = fmaxf(mx0, fmaxf(s[nt][0], s[nt][1]));
            mx1 = fmaxf(mx1, fmaxf(s[nt][2], s[nt][3]));
        }
        mx0 = fmaxf(mx0, __shfl_xor_sync(0xffffffffu, mx0, 1));
        mx0 = fmaxf(mx0, __shfl_xor_sync(0xffffffffu, mx0, 2));
        mx1 = fmaxf(mx1, __shfl_xor_sync(0xffffffffu, mx1, 1));
        mx1 = fmaxf(mx1, __shfl_xor_sync(0xffffffffu, mx1, 2));
        float nm0 = fmaxf(m0, mx0), nm1 = fmaxf(m1, mx1);
        float cr0 = fexp2(m0 - nm0), cr1 = fexp2(m1 - nm1);
        m0 = nm0; m1 = nm1;
        float sp0 = 0.f, sp1 = 0.f;
        #pragma unroll
        for (int nt = 0; nt < 8; nt++) {
            s[nt][0] = fexp2(s[nt][0] - m0); sp0 += s[nt][0];
            s[nt][1] = fexp2(s[nt][1] - m0); sp0 += s[nt][1];
            s[nt][2] = fexp2(s[nt][2] - m1); sp1 += s[nt][2];
            s[nt][3] = fexp2(s[nt][3] - m1); sp1 += s[nt][3];
        }
        l0 = l0*cr0 + sp0;
        l1 = l1*cr1 + sp1;
        if (__ballot_sync(0xffffffffu, (cr0 < 1.f) | (cr1 < 1.f))) {
            #pragma unroll
            for (int nb = 0; nb < 8; nb++) {
                o[nb][0] *= cr0; o[nb][1] *= cr0;
                o[nb][2] *= cr1; o[nb][3] *= cr1;
            }
        }

        // O += P V (single fp16 both)
        #pragma unroll
        for (int ks = 0; ks < 4; ks++) {
            uint32_t pa[4];
            {
                const float* s0 = s[2*ks];
                const float* s1 = s[2*ks+1];
                pa[0] = packh2(__float2half(s0[0]), __float2half(s0[1]));
                pa[1] = packh2(__float2half(s0[2]), __float2half(s0[3]));
                pa[2] = packh2(__float2half(s1[0]), __float2half(s1[1]));
                pa[3] = packh2(__float2half(s1[2]), __float2half(s1[3]));
            }
            int row = ks*16 + ii + (gi & 1)*8;
            uint32_t bv[4][4];
            #pragma unroll
            for (int dg = 0; dg < 4; dg++) {
                int col = dg*16 + (gi >> 1)*8;
                ldsm4t(bv[dg], s2u(&Vf[row*FSTR + col]));
            }
            #pragma unroll
            for (int dg = 0; dg < 4; dg++) {
                mma16816h(o[2*dg],   pa, &bv[dg][0]);
                mma16816h(o[2*dg+1], pa, &bv[dg][2]);
            }
        }
    }

    // finalize
    l0 += __shfl_xor_sync(0xffffffffu, l0, 1);
    l0 += __shfl_xor_sync(0xffffffffu, l0, 2);
    l1 += __shfl_xor_sync(0xffffffffu, l1, 1);
    l1 += __shfl_xor_sync(0xffffffffu, l1, 2);
    float inv0 = 1.f / l0, inv1 = 1.f / l1;

    int r0 = qt*64 + warp*16 + (lane >> 2);
    size_t o0 = ((size_t)b*SS + r0    )*(NH*HD) + h*HD;
    size_t o1 = ((size_t)b*SS + r0 + 8)*(NH*HD) + h*HD;
    #pragma unroll
    for (int nb = 0; nb < 8; nb++) {
        int d = nb*8 + 2*(lane & 3);
        __half h0,h1,l0_,l1_;
        split1h(o[nb][0]*inv0, h0, l0_); split1h(o[nb][1]*inv0, h1, l1_);
        *(__half2*)&g_aoh[o0 + d] = __half2(h0,h1);
        *(__half2*)&g_aol[o0 + d] = __half2(l0_,l1_);
        split1h(o[nb][2]*inv1, h0, l0_); split1h(o[nb][3]*inv1, h1, l1_);
        *(__half2*)&g_aoh[o1 + d] = __half2(h0,h1);
        *(__half2*)&g_aol[o1 + d] = __half2(l0_,l1_);
    }
}

// ---------------- O-proj GEMM ----------------------------------------------
__global__ __launch_bounds__(256) void oproj_gemm(
    const float* __restrict__ bo, float* __restrict__ C)
{
    extern __shared__ __half gsm[];
    const int tid = threadIdx.x, lane = tid & 31, warp = tid >> 5;
    const int wm = warp >> 2, wn = warp & 3;
    const int gi = lane >> 3, ii = lane & 7;
    const int bx = blockIdx.x, by = blockIdx.y;
    const int n0 = bx * 128;

    float c[4][4][4];
    #pragma unroll
    for (int i=0;i<4;i++) for (int j=0;j<4;j++) for (int e=0;e<4;e++) c[i][j][e]=0.f;

    load_gemm_tile(gsm, g_aoh, g_aol, g_wof, by*128, n0, 0, tid);

    for (int t = 0; t < 32; t++) {
        cpa_wait0();
        __syncthreads();
        if (t < 31)
            load_gemm_tile(gsm + ((t+1)&1)*G_STAGE_E, g_aoh, g_aol, g_wof,
                           by*128, n0, (t+1)*32, tid);
        gemm_compute(gsm + (t&1)*G_STAGE_E, c, wm, wn, gi, ii);
    }

    #pragma unroll
    for (int mi = 0; mi < 4; mi++)
        #pragma unroll
        for (int ni = 0; ni < 4; ni++)
            #pragma unroll
            for (int e = 0; e < 4; e++) {
                int m = by*128 + wm*64 + mi*16 + (lane >> 2) + ((e >= 2) ? 8 : 0);
                int n = n0 + wn*32 + ni*8 + 2*(lane & 3) + (e & 1);
                C[(size_t)m*HIDD + n] = c[mi][ni][e] + bo[n];
            }
}

// ---------------------------------------------------------------------------
extern "C" void kernel_launch(void* const* d_in, const int* in_sizes, int n_in,
                              void* d_out, int out_size)
{
    const float* X    = (const float*)d_in[0];
    const float* cosp = (const float*)d_in[1];
    const float* sinp = (const float*)d_in[2];
    const float* Wq   = (const float*)d_in[3];
    const float* bq   = (const float*)d_in[4];
    const float* Wk   = (const float*)d_in[5];
    const float* bk   = (const float*)d_in[6];
    const float* Wv   = (const float*)d_in[7];
    const float* bv   = (const float*)d_in[8];
    const float* Wo   = (const float*)d_in[9];
    const float* bo   = (const float*)d_in[10];
    float* out = (float*)d_out;

    const int gemm_smem  = 2 * G_STAGE_E * (int)sizeof(__half);   // 61440
    const int flash_smem = 2 * F_STAGE_E * (int)sizeof(__half);   // 36864
    cudaFuncSetAttribute(qkv_gemm,    cudaFuncAttributeMaxDynamicSharedMemorySize, gemm_smem);
    cudaFuncSetAttribute(oproj_gemm,  cudaFuncAttributeMaxDynamicSharedMemorySize, gemm_smem);
    cudaFuncSetAttribute(flash_kernel,cudaFuncAttributeMaxDynamicSharedMemorySize, flash_smem);

    int n4_total = N4_X + 2*N4_WQ + 2*N4_WK;
    split_all<<<(n4_total + 255)/256, 256>>>(X, Wq, Wk, Wv, Wo);

    dim3 g1(1536/128, 8192/128);
    qkv_gemm<<<g1, 256, gemm_smem>>>(bq, bk, bv);

    int tq = BB*NH *SS*32;
    int tk = BB*NKV*SS*32;
    rope_all<<<(tq + tk + 255)/256, 256>>>(cosp, sinp, tq, tq + tk);

    dim3 g3(SS/64, NH, BB);
    flash_kernel<<<g3, 128, flash_smem>>>();

    dim3 g4(1024/128, 8192/128);
    oproj_gemm<<<g4, 256, gemm_smem>>>(bo, out);
}

// round 13
// speedup vs baseline: 8.2540x; 1.2677x over previous
#include <cuda_runtime.h>
#include <cuda_bf16.h>
#include <cuda_fp16.h>
#include <cstdint>

#define BB   4
#define SS   2048
#define HIDD 1024
#define NH   16
#define NKV  4
#define HD   64
#define GROUPS 4
#define SCALE_F 0.125f
#define LOG2E 1.4426950408889634f

// ---------------- scratch (__device__ globals, allocation-free) -------------
__device__ float g_q[BB*NH*SS*HD];
__device__ float g_k[BB*NKV*SS*HD];
__device__ __half g_qf[BB*NH*SS*HD];      // Q single fp16 (scaled, exp2 domain)
__device__ __half g_kf[BB*NKV*SS*HD];     // K single fp16
__device__ __half g_vf[BB*NKV*SS*HD];     // V single fp16
__device__ __half g_xf[BB*SS*HIDD];       // X single fp16
__device__ __half g_aof[BB*SS*NH*HD];     // attn out single fp16
__device__ __half g_wqf[NH*HD*HIDD];      // weights single fp16
__device__ __half g_wkf[NKV*HD*HIDD];
__device__ __half g_wvf[NKV*HD*HIDD];
__device__ __half g_wof[HIDD*NH*HD];

// ---------------- helpers ---------------------------------------------------
__device__ __forceinline__ uint32_t s2u(const void* p) {
    return (uint32_t)__cvta_generic_to_shared(p);
}
__device__ __forceinline__ void mma16816h(float* c, const uint32_t* a, const uint32_t* b) {
    asm volatile(
        "mma.sync.aligned.m16n8k16.row.col.f32.f16.f16.f32 "
        "{%0,%1,%2,%3}, {%4,%5,%6,%7}, {%8,%9}, {%0,%1,%2,%3};"
        : "+f"(c[0]), "+f"(c[1]), "+f"(c[2]), "+f"(c[3])
        : "r"(a[0]), "r"(a[1]), "r"(a[2]), "r"(a[3]), "r"(b[0]), "r"(b[1]));
}
__device__ __forceinline__ void ldsm4(uint32_t* r, uint32_t addr) {
    asm volatile("ldmatrix.sync.aligned.m8n8.x4.shared.b16 {%0,%1,%2,%3}, [%4];"
        : "=r"(r[0]), "=r"(r[1]), "=r"(r[2]), "=r"(r[3]) : "r"(addr));
}
__device__ __forceinline__ void ldsm4t(uint32_t* r, uint32_t addr) {
    asm volatile("ldmatrix.sync.aligned.m8n8.x4.trans.shared.b16 {%0,%1,%2,%3}, [%4];"
        : "=r"(r[0]), "=r"(r[1]), "=r"(r[2]), "=r"(r[3]) : "r"(addr));
}
__device__ __forceinline__ void cpa16(void* dst, const void* src) {
    asm volatile("cp.async.cg.shared.global [%0], [%1], 16;" :: "r"(s2u(dst)), "l"(src));
}
__device__ __forceinline__ void cpa_commit() {
    asm volatile("cp.async.commit_group;");
}
__device__ __forceinline__ void cpa_wait0() {
    asm volatile("cp.async.wait_group 0;" ::: "memory");
}
__device__ __forceinline__ float fexp2(float x) {
    float r;
    asm("ex2.approx.f32 %0, %1;" : "=f"(r) : "f"(x));
    return r;
}
__device__ __forceinline__ uint32_t packh2(__half a, __half b) {
    __half2 t; t.x = a; t.y = b;
    return *(uint32_t*)&t;
}
__device__ __forceinline__ void cvt4h_store(float4 v, __half* D) {
    ((__half2*)D)[0] = __floats2half2_rn(v.x, v.y);
    ((__half2*)D)[1] = __floats2half2_rn(v.z, v.w);
}

// ---------------- pre-convert: X + weights -> single fp16 -------------------
#define N4_X  (BB*SS*HIDD/4)
#define N4_WQ (NH*HD*HIDD/4)
#define N4_WK (NKV*HD*HIDD/4)
__global__ void split_all(const float* __restrict__ X,  const float* __restrict__ Wq,
                          const float* __restrict__ Wk, const float* __restrict__ Wv,
                          const float* __restrict__ Wo)
{
    int i = blockIdx.x * blockDim.x + threadIdx.x;
    const float* src; __half* dst; int off;
    if (i < N4_X)                  { src = X;  dst = g_xf;  off = i; }
    else if ((i -= N4_X)  < N4_WQ) { src = Wq; dst = g_wqf; off = i; }
    else if ((i -= N4_WQ) < N4_WK) { src = Wk; dst = g_wkf; off = i; }
    else if ((i -= N4_WK) < N4_WK) { src = Wv; dst = g_wvf; off = i; }
    else if ((i -= N4_WK) < N4_WQ) { src = Wo; dst = g_wof; off = i; }
    else return;
    float4 v = *(const float4*)&src[(size_t)off*4];
    cvt4h_store(v, &dst[(size_t)off*4]);
}

// ---------------- GEMM common (BM128 BN128 BK32, 2-stage, fp16 single) ------
#define GSTR 40
#define G_AF  0
#define G_BF  5120
#define G_STAGE_E 10240   // halves per stage (20480 B)

__device__ __forceinline__ void load_gemm_tile(__half* st,
    const __half* Afg, const __half* Bfg,
    int arow0, int brow0, int kt, int tid)
{
    #pragma unroll
    for (int p = 0; p < 2; p++) {
        int cidx = tid + p*256;
        int row = cidx >> 2, ch = (cidx & 3)*8;
        size_t so = (size_t)(arow0 + row)*HIDD + kt + ch;
        cpa16(&st[G_AF + row*GSTR + ch], Afg + so);
    }
    #pragma unroll
    for (int p = 0; p < 2; p++) {
        int cidx = tid + p*256;
        int row = cidx >> 2, ch = (cidx & 3)*8;
        size_t so = (size_t)(brow0 + row)*HIDD + kt + ch;
        cpa16(&st[G_BF + row*GSTR + ch], Bfg + so);
    }
    cpa_commit();
}

// single-term fp16, accumulator-interleaved
__device__ __forceinline__ void gemm_compute(const __half* st,
    float c[4][4][4], int wm, int wn, int gi, int ii)
{
    #pragma unroll
    for (int ks = 0; ks < 2; ks++) {
        uint32_t af[4][4], bf[2][4];
        #pragma unroll
        for (int mi = 0; mi < 4; mi++) {
            int row = wm*64 + mi*16 + ii + (gi & 1)*8;
            int col = ks*16 + (gi >> 1)*8;
            ldsm4(af[mi], s2u(&st[G_AF + row*GSTR + col]));
        }
        #pragma unroll
        for (int ng = 0; ng < 2; ng++) {
            int row = wn*32 + ng*16 + ii + (gi >> 1)*8;
            int col = ks*16 + (gi & 1)*8;
            ldsm4(bf[ng], s2u(&st[G_BF + row*GSTR + col]));
        }
        #pragma unroll
        for (int mi = 0; mi < 4; mi++)
            #pragma unroll
            for (int ng = 0; ng < 2; ng++) {
                mma16816h(c[mi][2*ng],   af[mi], &bf[ng][0]);
                mma16816h(c[mi][2*ng+1], af[mi], &bf[ng][2]);
            }
    }
}

// ---------------- QKV GEMM ---------------------------------------------------
__global__ __launch_bounds__(256) void qkv_gemm(
    const float* __restrict__ bq, const float* __restrict__ bk, const float* __restrict__ bv)
{
    extern __shared__ __half gsm[];
    const int tid = threadIdx.x, lane = tid & 31, warp = tid >> 5;
    const int wm = warp >> 2, wn = warp & 3;
    const int gi = lane >> 3, ii = lane & 7;
    const int bx = blockIdx.x, by = blockIdx.y;
    const int n0 = bx * 128;

    const __half* Wf; const float* bias; int noff;
    if (n0 < 1024)      { Wf = g_wqf; bias = bq; noff = 0;    }
    else if (n0 < 1280) { Wf = g_wkf; bias = bk; noff = 1024; }
    else                { Wf = g_wvf; bias = bv; noff = 1280; }

    float c[4][4][4];
    #pragma unroll
    for (int i=0;i<4;i++) for (int j=0;j<4;j++) for (int e=0;e<4;e++) c[i][j][e]=0.f;

    load_gemm_tile(gsm, g_xf, Wf, by*128, n0 - noff, 0, tid);

    for (int t = 0; t < 32; t++) {
        cpa_wait0();
        __syncthreads();
        if (t < 31)
            load_gemm_tile(gsm + ((t+1)&1)*G_STAGE_E, g_xf, Wf,
                           by*128, n0 - noff, (t+1)*32, tid);
        gemm_compute(gsm + (t&1)*G_STAGE_E, c, wm, wn, gi, ii);
    }

    #pragma unroll
    for (int mi = 0; mi < 4; mi++)
        #pragma unroll
        for (int ni = 0; ni < 4; ni++)
            #pragma unroll
            for (int e = 0; e < 4; e++) {
                int m = by*128 + wm*64 + mi*16 + (lane >> 2) + ((e >= 2) ? 8 : 0);
                int n = n0 + wn*32 + ni*8 + 2*(lane & 3) + (e & 1);
                int b_ = m >> 11, s = m & 2047;
                float val = c[mi][ni][e] + bias[n - noff];
                if (n < 1024) {
                    int h = n >> 6, d = n & 63;
                    g_q[(((size_t)b_*NH + h)*SS + s)*HD + d] = val;
                } else if (n < 1280) {
                    int nn = n - 1024; int h = nn >> 6, d = nn & 63;
                    g_k[(((size_t)b_*NKV + h)*SS + s)*HD + d] = val;
                } else {
                    int nn = n - 1280; int h = nn >> 6, d = nn & 63;
                    size_t off = (((size_t)b_*NKV + h)*SS + s)*HD + d;
                    g_vf[off] = __float2half(val);
                }
            }
}

// ---------------- RoPE; q -> single fp16 (scaled), k -> single fp16 ---------
__global__ void rope_all(const float* __restrict__ cos_t,
                         const float* __restrict__ sin_t, int tq, int total)
{
    int idx = blockIdx.x * blockDim.x + threadIdx.x;
    if (idx >= total) return;
    int which = (idx >= tq);
    if (which) idx -= tq;
    int d  = idx & 31;
    int s  = (idx >> 5) & 2047;
    int bh = idx >> 16;
    size_t base = ((size_t)bh*SS + s)*HD;
    const float* src = which ? g_k : g_q;
    __half* dst = which ? g_kf : g_qf;
    float scale = which ? 1.0f : (SCALE_F * LOG2E);
    float x1 = src[base + d], x2 = src[base + d + 32];
    float c1 = cos_t[s*HD + d],      s1 = sin_t[s*HD + d];
    float c2 = cos_t[s*HD + d + 32], s2 = sin_t[s*HD + d + 32];
    dst[base + d]      = __float2half((x1*c1 - x2*s1) * scale);
    dst[base + d + 32] = __float2half((x2*c2 + x1*s2) * scale);
}

// ---------------- flash attention (64 q-rows, 64-key tiles, 2-stage) --------
#define FSTR 72
#define F_ARR (64*FSTR)
#define F_STAGE_E (2*F_ARR)     // Kf, Vf

__device__ __forceinline__ void load_kv_tile(__half* st,
    const __half* kfg, const __half* vfg, int t, int tid)
{
    #pragma unroll
    for (int p = 0; p < 4; p++) {
        int cidx = tid + p*128;
        int row = cidx >> 3, ch = (cidx & 7)*8;
        size_t so = ((size_t)t*64 + row)*HD + ch;
        cpa16(&st[        row*FSTR + ch], kfg + so);
        cpa16(&st[F_ARR + row*FSTR + ch], vfg + so);
    }
    cpa_commit();
}

__global__ __launch_bounds__(128) void flash_kernel()
{
    extern __shared__ __half fsm[];

    const int b = blockIdx.z, h = blockIdx.y, qt = blockIdx.x;
    const int tid = threadIdx.x, lane = tid & 31, warp = tid >> 5;
    const int hk = h / GROUPS;
    const int gi = lane >> 3, ii = lane & 7;

    const __half* qfg = g_qf + (((size_t)b*NH  + h )*SS + qt*64)*HD;
    const __half* kfg = g_kf + (((size_t)b*NKV + hk)*SS)*HD;
    const __half* vfg = g_vf + (((size_t)b*NKV + hk)*SS)*HD;

    // stage Q through stage-0 smem, grab fragments
    {
        #pragma unroll
        for (int p = 0; p < 4; p++) {
            int cidx = tid + p*128;
            int row = cidx >> 3, ch = (cidx & 7)*8;
            size_t so = (size_t)row*HD + ch;
            cpa16(&fsm[row*FSTR + ch], qfg + so);
        }
        cpa_commit();
        cpa_wait0();
        __syncthreads();
    }

    uint32_t qf[4][4];
    #pragma unroll
    for (int kk = 0; kk < 4; kk++) {
        int row = warp*16 + ii + (gi & 1)*8;
        int col = kk*16 + (gi >> 1)*8;
        ldsm4(qf[kk], s2u(&fsm[row*FSTR + col]));
    }
    __syncthreads();

    load_kv_tile(fsm, kfg, vfg, 0, tid);

    float o[8][4];
    #pragma unroll
    for (int i = 0; i < 8; i++) for (int j = 0; j < 4; j++) o[i][j] = 0.f;
    float m0 = -1e30f, m1 = -1e30f, l0 = 0.f, l1 = 0.f;

    for (int t = 0; t < SS/64; t++) {
        cpa_wait0();
        __syncthreads();
        if (t < SS/64 - 1)
            load_kv_tile(fsm + ((t+1)&1)*F_STAGE_E, kfg, vfg, t+1, tid);

        const __half* Kf = fsm + (t&1)*F_STAGE_E;
        const __half* Vf = Kf + F_ARR;

        // S = Q K^T (single fp16)
        float s[8][4];
        #pragma unroll
        for (int i = 0; i < 8; i++) for (int j = 0; j < 4; j++) s[i][j] = 0.f;
        #pragma unroll
        for (int kk = 0; kk < 4; kk++) {
            int col = kk*16 + (gi & 1)*8;
            uint32_t kf[4][4];
            #pragma unroll
            for (int ng = 0; ng < 4; ng++) {
                int row = ng*16 + ii + (gi >> 1)*8;
                ldsm4(kf[ng], s2u(&Kf[row*FSTR + col]));
            }
            #pragma unroll
            for (int ng = 0; ng < 4; ng++) {
                mma16816h(s[2*ng],   qf[kk], &kf[ng][0]);
                mma16816h(s[2*ng+1], qf[kk], &kf[ng][2]);
            }
        }

        // online softmax in exp2 domain
        float mx0 = -1e30f, mx1 = -1e30f;
        #pragma unroll
        for (int nt = 0; nt < 8; nt++) {
            mx0 = fmaxf(mx0, fmaxf(s[nt][0], s[nt][1]));
            mx1 = fmaxf(mx1, fmaxf(s[nt][2], s[nt][3]));
        }
        mx0 = fmaxf(mx0, __shfl_xor_sync(0xffffffffu, mx0, 1));
        mx0 = fmaxf(mx0, __shfl_xor_sync(0xffffffffu, mx0, 2));
        mx1 = fmaxf(mx1, __shfl_xor_sync(0xffffffffu, mx1, 1));
        mx1 = fmaxf(mx1, __shfl_xor_sync(0xffffffffu, mx1, 2));
        float nm0 = fmaxf(m0, mx0), nm1 = fmaxf(m1, mx1);
        float cr0 = fexp2(m0 - nm0), cr1 = fexp2(m1 - nm1);
        m0 = nm0; m1 = nm1;
        float sp0 = 0.f, sp1 = 0.f;
        #pragma unroll
        for (int nt = 0; nt < 8; nt++) {
            s[nt][0] = fexp2(s[nt][0] - m0); sp0 += s[nt][0];
            s[nt][1] = fexp2(s[nt][1] - m0); sp0 += s[nt][1];
            s[nt][2] = fexp2(s[nt][2] - m1); sp1 += s[nt][2];
            s[nt][3] = fexp2(s[nt][3] - m1); sp1 += s[nt][3];
        }
        l0 = l0*cr0 + sp0;
        l1 = l1*cr1 + sp1;
        if (__ballot_sync(0xffffffffu, (cr0 < 1.f) | (cr1 < 1.f))) {
            #pragma unroll
            for (int nb = 0; nb < 8; nb++) {
                o[nb][0] *= cr0; o[nb][1] *= cr0;
                o[nb][2] *= cr1; o[nb][3] *= cr1;
            }
        }

        // O += P V (single fp16 both)
        #pragma unroll
        for (int ks = 0; ks < 4; ks++) {
            uint32_t pa[4];
            {
                const float* s0 = s[2*ks];
                const float* s1 = s[2*ks+1];
                pa[0] = packh2(__float2half(s0[0]), __float2half(s0[1]));
                pa[1] = packh2(__float2half(s0[2]), __float2half(s0[3]));
                pa[2] = packh2(__float2half(s1[0]), __float2half(s1[1]));
                pa[3] = packh2(__float2half(s1[2]), __float2half(s1[3]));
            }
            int row = ks*16 + ii + (gi & 1)*8;
            uint32_t bv[4][4];
            #pragma unroll
            for (int dg = 0; dg < 4; dg++) {
                int col = dg*16 + (gi >> 1)*8;
                ldsm4t(bv[dg], s2u(&Vf[row*FSTR + col]));
            }
            #pragma unroll
            for (int dg = 0; dg < 4; dg++) {
                mma16816h(o[2*dg],   pa, &bv[dg][0]);
                mma16816h(o[2*dg+1], pa, &bv[dg][2]);
            }
        }
    }

    // finalize -> single fp16 attn-out
    l0 += __shfl_xor_sync(0xffffffffu, l0, 1);
    l0 += __shfl_xor_sync(0xffffffffu, l0, 2);
    l1 += __shfl_xor_sync(0xffffffffu, l1, 1);
    l1 += __shfl_xor_sync(0xffffffffu, l1, 2);
    float inv0 = 1.f / l0, inv1 = 1.f / l1;

    int r0 = qt*64 + warp*16 + (lane >> 2);
    size_t o0 = ((size_t)b*SS + r0    )*(NH*HD) + h*HD;
    size_t o1 = ((size_t)b*SS + r0 + 8)*(NH*HD) + h*HD;
    #pragma unroll
    for (int nb = 0; nb < 8; nb++) {
        int d = nb*8 + 2*(lane & 3);
        *(__half2*)&g_aof[o0 + d] = __floats2half2_rn(o[nb][0]*inv0, o[nb][1]*inv0);
        *(__half2*)&g_aof[o1 + d] = __floats2half2_rn(o[nb][2]*inv1, o[nb][3]*inv1);
    }
}

// ---------------- O-proj GEMM ----------------------------------------------
__global__ __launch_bounds__(256) void oproj_gemm(
    const float* __restrict__ bo, float* __restrict__ C)
{
    extern __shared__ __half gsm[];
    const int tid = threadIdx.x, lane = tid & 31, warp = tid >> 5;
    const int wm = warp >> 2, wn = warp & 3;
    const int gi = lane >> 3, ii = lane & 7;
    const int bx = blockIdx.x, by = blockIdx.y;
    const int n0 = bx * 128;

    float c[4][4][4];
    #pragma unroll
    for (int i=0;i<4;i++) for (int j=0;j<4;j++) for (int e=0;e<4;e++) c[i][j][e]=0.f;

    load_gemm_tile(gsm, g_aof, g_wof, by*128, n0, 0, tid);

    for (int t = 0; t < 32; t++) {
        cpa_wait0();
        __syncthreads();
        if (t < 31)
            load_gemm_tile(gsm + ((t+1)&1)*G_STAGE_E, g_aof, g_wof,
                           by*128, n0, (t+1)*32, tid);
        gemm_compute(gsm + (t&1)*G_STAGE_E, c, wm, wn, gi, ii);
    }

    #pragma unroll
    for (int mi = 0; mi < 4; mi++)
        #pragma unroll
        for (int ni = 0; ni < 4; ni++)
            #pragma unroll
            for (int e = 0; e < 4; e++) {
                int m = by*128 + wm*64 + mi*16 + (lane >> 2) + ((e >= 2) ? 8 : 0);
                int n = n0 + wn*32 + ni*8 + 2*(lane & 3) + (e & 1);
                C[(size_t)m*HIDD + n] = c[mi][ni][e] + bo[n];
            }
}

// ---------------------------------------------------------------------------
extern "C" void kernel_launch(void* const* d_in, const int* in_sizes, int n_in,
                              void* d_out, int out_size)
{
    const float* X    = (const float*)d_in[0];
    const float* cosp = (const float*)d_in[1];
    const float* sinp = (const float*)d_in[2];
    const float* Wq   = (const float*)d_in[3];
    const float* bq   = (const float*)d_in[4];
    const float* Wk   = (const float*)d_in[5];
    const float* bk   = (const float*)d_in[6];
    const float* Wv   = (const float*)d_in[7];
    const float* bv   = (const float*)d_in[8];
    const float* Wo   = (const float*)d_in[9];
    const float* bo   = (const float*)d_in[10];
    float* out = (float*)d_out;

    const int gemm_smem  = 2 * G_STAGE_E * (int)sizeof(__half);   // 40960
    const int flash_smem = 2 * F_STAGE_E * (int)sizeof(__half);   // 36864
    cudaFuncSetAttribute(qkv_gemm,    cudaFuncAttributeMaxDynamicSharedMemorySize, gemm_smem);
    cudaFuncSetAttribute(oproj_gemm,  cudaFuncAttributeMaxDynamicSharedMemorySize, gemm_smem);
    cudaFuncSetAttribute(flash_kernel,cudaFuncAttributeMaxDynamicSharedMemorySize, flash_smem);

    int n4_total = N4_X + 2*N4_WQ + 2*N4_WK;
    split_all<<<(n4_total + 255)/256, 256>>>(X, Wq, Wk, Wv, Wo);

    dim3 g1(1536/128, 8192/128);
    qkv_gemm<<<g1, 256, gemm_smem>>>(bq, bk, bv);

    int tq = BB*NH *SS*32;
    int tk = BB*NKV*SS*32;
    rope_all<<<(tq + tk + 255)/256, 256>>>(cosp, sinp, tq, tq + tk);

    dim3 g3(SS/64, NH, BB);
    flash_kernel<<<g3, 128, flash_smem>>>();

    dim3 g4(1024/128, 8192/128);
    oproj_gemm<<<g4, 256, gemm_smem>>>(bo, out);
}

// round 14
// speedup vs baseline: 8.6243x; 1.0449x over previous
#include <cuda_runtime.h>
#include <cuda_bf16.h>
#include <cuda_fp16.h>
#include <cstdint>

#define BB   4
#define SS   2048
#define HIDD 1024
#define NH   16
#define NKV  4
#define HD   64
#define GROUPS 4
#define SCALE_F 0.125f
#define LOG2E 1.4426950408889634f

// ---------------- scratch (__device__ globals, allocation-free) -------------
__device__ float g_q[BB*NH*SS*HD];
__device__ float g_k[BB*NKV*SS*HD];
__device__ __half g_qf[BB*NH*SS*HD];      // Q single fp16 (scaled, exp2 domain)
__device__ __half g_kf[BB*NKV*SS*HD];     // K single fp16
__device__ __half g_vf[BB*NKV*SS*HD];     // V single fp16
__device__ __half g_xf[BB*SS*HIDD];       // X single fp16
__device__ __half g_aof[BB*SS*NH*HD];     // attn out single fp16
__device__ __half g_wqf[NH*HD*HIDD];      // weights single fp16
__device__ __half g_wkf[NKV*HD*HIDD];
__device__ __half g_wvf[NKV*HD*HIDD];
__device__ __half g_wof[HIDD*NH*HD];

// ---------------- helpers ---------------------------------------------------
__device__ __forceinline__ uint32_t s2u(const void* p) {
    return (uint32_t)__cvta_generic_to_shared(p);
}
__device__ __forceinline__ void mma16816h(float* c, const uint32_t* a, const uint32_t* b) {
    asm volatile(
        "mma.sync.aligned.m16n8k16.row.col.f32.f16.f16.f32 "
        "{%0,%1,%2,%3}, {%4,%5,%6,%7}, {%8,%9}, {%0,%1,%2,%3};"
        : "+f"(c[0]), "+f"(c[1]), "+f"(c[2]), "+f"(c[3])
        : "r"(a[0]), "r"(a[1]), "r"(a[2]), "r"(a[3]), "r"(b[0]), "r"(b[1]));
}
__device__ __forceinline__ void ldsm4(uint32_t* r, uint32_t addr) {
    asm volatile("ldmatrix.sync.aligned.m8n8.x4.shared.b16 {%0,%1,%2,%3}, [%4];"
        : "=r"(r[0]), "=r"(r[1]), "=r"(r[2]), "=r"(r[3]) : "r"(addr));
}
__device__ __forceinline__ void ldsm4t(uint32_t* r, uint32_t addr) {
    asm volatile("ldmatrix.sync.aligned.m8n8.x4.trans.shared.b16 {%0,%1,%2,%3}, [%4];"
        : "=r"(r[0]), "=r"(r[1]), "=r"(r[2]), "=r"(r[3]) : "r"(addr));
}
__device__ __forceinline__ void cpa16(void* dst, const void* src) {
    asm volatile("cp.async.cg.shared.global [%0], [%1], 16;" :: "r"(s2u(dst)), "l"(src));
}
__device__ __forceinline__ void cpa_commit() {
    asm volatile("cp.async.commit_group;");
}
__device__ __forceinline__ void cpa_wait0() {
    asm volatile("cp.async.wait_group 0;" ::: "memory");
}
__device__ __forceinline__ float fexp2(float x) {
    float r;
    asm("ex2.approx.f32 %0, %1;" : "=f"(r) : "f"(x));
    return r;
}
// packed-half2 exp2: one MUFU op, output IS the fp16 A-fragment word
__device__ __forceinline__ uint32_t fexp2h2(float lo, float hi) {
    __half2 t = __floats2half2_rn(lo, hi);
    uint32_t x = *(uint32_t*)&t, r;
    asm("ex2.approx.f16x2 %0, %1;" : "=r"(r) : "r"(x));
    return r;
}
__device__ __forceinline__ void cvt4h_store(float4 v, __half* D) {
    ((__half2*)D)[0] = __floats2half2_rn(v.x, v.y);
    ((__half2*)D)[1] = __floats2half2_rn(v.z, v.w);
}

// ---------------- pre-convert: X + weights -> single fp16 -------------------
#define N4_X  (BB*SS*HIDD/4)
#define N4_WQ (NH*HD*HIDD/4)
#define N4_WK (NKV*HD*HIDD/4)
__global__ void split_all(const float* __restrict__ X,  const float* __restrict__ Wq,
                          const float* __restrict__ Wk, const float* __restrict__ Wv,
                          const float* __restrict__ Wo)
{
    int i = blockIdx.x * blockDim.x + threadIdx.x;
    const float* src; __half* dst; int off;
    if (i < N4_X)                  { src = X;  dst = g_xf;  off = i; }
    else if ((i -= N4_X)  < N4_WQ) { src = Wq; dst = g_wqf; off = i; }
    else if ((i -= N4_WQ) < N4_WK) { src = Wk; dst = g_wkf; off = i; }
    else if ((i -= N4_WK) < N4_WK) { src = Wv; dst = g_wvf; off = i; }
    else if ((i -= N4_WK) < N4_WQ) { src = Wo; dst = g_wof; off = i; }
    else return;
    float4 v = *(const float4*)&src[(size_t)off*4];
    cvt4h_store(v, &dst[(size_t)off*4]);
}

// ---------------- GEMM common (BM128 BN128 BK32, 2-stage, fp16 single) ------
#define GSTR 40
#define G_AF  0
#define G_BF  5120
#define G_STAGE_E 10240   // halves per stage (20480 B)

__device__ __forceinline__ void load_gemm_tile(__half* st,
    const __half* Afg, const __half* Bfg,
    int arow0, int brow0, int kt, int tid)
{
    #pragma unroll
    for (int p = 0; p < 2; p++) {
        int cidx = tid + p*256;
        int row = cidx >> 2, ch = (cidx & 3)*8;
        size_t so = (size_t)(arow0 + row)*HIDD + kt + ch;
        cpa16(&st[G_AF + row*GSTR + ch], Afg + so);
    }
    #pragma unroll
    for (int p = 0; p < 2; p++) {
        int cidx = tid + p*256;
        int row = cidx >> 2, ch = (cidx & 3)*8;
        size_t so = (size_t)(brow0 + row)*HIDD + kt + ch;
        cpa16(&st[G_BF + row*GSTR + ch], Bfg + so);
    }
    cpa_commit();
}

// single-term fp16, accumulator-interleaved
__device__ __forceinline__ void gemm_compute(uint32_t stb,
    float c[4][4][4], int wm, int wn, int gi, int ii)
{
    #pragma unroll
    for (int ks = 0; ks < 2; ks++) {
        uint32_t af[4][4], bf[2][4];
        #pragma unroll
        for (int mi = 0; mi < 4; mi++) {
            int row = wm*64 + mi*16 + ii + (gi & 1)*8;
            int col = ks*16 + (gi >> 1)*8;
            ldsm4(af[mi], stb + (G_AF + row*GSTR + col)*2);
        }
        #pragma unroll
        for (int ng = 0; ng < 2; ng++) {
            int row = wn*32 + ng*16 + ii + (gi >> 1)*8;
            int col = ks*16 + (gi & 1)*8;
            ldsm4(bf[ng], stb + (G_BF + row*GSTR + col)*2);
        }
        #pragma unroll
        for (int mi = 0; mi < 4; mi++)
            #pragma unroll
            for (int ng = 0; ng < 2; ng++) {
                mma16816h(c[mi][2*ng],   af[mi], &bf[ng][0]);
                mma16816h(c[mi][2*ng+1], af[mi], &bf[ng][2]);
            }
    }
}

// ---------------- QKV GEMM ---------------------------------------------------
__global__ __launch_bounds__(256) void qkv_gemm(
    const float* __restrict__ bq, const float* __restrict__ bk, const float* __restrict__ bv)
{
    extern __shared__ __half gsm[];
    const int tid = threadIdx.x, lane = tid & 31, warp = tid >> 5;
    const int wm = warp >> 2, wn = warp & 3;
    const int gi = lane >> 3, ii = lane & 7;
    const int bx = blockIdx.x, by = blockIdx.y;
    const int n0 = bx * 128;
    const uint32_t gb = s2u(gsm);

    const __half* Wf; const float* bias; int noff;
    if (n0 < 1024)      { Wf = g_wqf; bias = bq; noff = 0;    }
    else if (n0 < 1280) { Wf = g_wkf; bias = bk; noff = 1024; }
    else                { Wf = g_wvf; bias = bv; noff = 1280; }

    float c[4][4][4];
    #pragma unroll
    for (int i=0;i<4;i++) for (int j=0;j<4;j++) for (int e=0;e<4;e++) c[i][j][e]=0.f;

    load_gemm_tile(gsm, g_xf, Wf, by*128, n0 - noff, 0, tid);

    for (int t = 0; t < 32; t++) {
        cpa_wait0();
        __syncthreads();
        if (t < 31)
            load_gemm_tile(gsm + ((t+1)&1)*G_STAGE_E, g_xf, Wf,
                           by*128, n0 - noff, (t+1)*32, tid);
        gemm_compute(gb + (t&1)*G_STAGE_E*2, c, wm, wn, gi, ii);
    }

    #pragma unroll
    for (int mi = 0; mi < 4; mi++)
        #pragma unroll
        for (int ni = 0; ni < 4; ni++)
            #pragma unroll
            for (int e = 0; e < 4; e++) {
                int m = by*128 + wm*64 + mi*16 + (lane >> 2) + ((e >= 2) ? 8 : 0);
                int n = n0 + wn*32 + ni*8 + 2*(lane & 3) + (e & 1);
                int b_ = m >> 11, s = m & 2047;
                float val = c[mi][ni][e] + bias[n - noff];
                if (n < 1024) {
                    int h = n >> 6, d = n & 63;
                    g_q[(((size_t)b_*NH + h)*SS + s)*HD + d] = val;
                } else if (n < 1280) {
                    int nn = n - 1024; int h = nn >> 6, d = nn & 63;
                    g_k[(((size_t)b_*NKV + h)*SS + s)*HD + d] = val;
                } else {
                    int nn = n - 1280; int h = nn >> 6, d = nn & 63;
                    size_t off = (((size_t)b_*NKV + h)*SS + s)*HD + d;
                    g_vf[off] = __float2half(val);
                }
            }
}

// ---------------- RoPE; q -> single fp16 (scaled), k -> single fp16 ---------
__global__ void rope_all(const float* __restrict__ cos_t,
                         const float* __restrict__ sin_t, int tq, int total)
{
    int idx = blockIdx.x * blockDim.x + threadIdx.x;
    if (idx >= total) return;
    int which = (idx >= tq);
    if (which) idx -= tq;
    int d  = idx & 31;
    int s  = (idx >> 5) & 2047;
    int bh = idx >> 16;
    size_t base = ((size_t)bh*SS + s)*HD;
    const float* src = which ? g_k : g_q;
    __half* dst = which ? g_kf : g_qf;
    float scale = which ? 1.0f : (SCALE_F * LOG2E);
    float x1 = src[base + d], x2 = src[base + d + 32];
    float c1 = cos_t[s*HD + d],      s1 = sin_t[s*HD + d];
    float c2 = cos_t[s*HD + d + 32], s2 = sin_t[s*HD + d + 32];
    dst[base + d]      = __float2half((x1*c1 - x2*s1) * scale);
    dst[base + d + 32] = __float2half((x2*c2 + x1*s2) * scale);
}

// ---------------- flash attention (64 q-rows, 64-key tiles, 2-stage) --------
#define FSTR 72
#define F_ARR (64*FSTR)
#define F_STAGE_E (2*F_ARR)     // Kf, Vf

__device__ __forceinline__ void load_kv_tile(__half* st,
    const __half* kfg, const __half* vfg, int t, int tid)
{
    #pragma unroll
    for (int p = 0; p < 4; p++) {
        int cidx = tid + p*128;
        int row = cidx >> 3, ch = (cidx & 7)*8;
        size_t so = ((size_t)t*64 + row)*HD + ch;
        cpa16(&st[        row*FSTR + ch], kfg + so);
        cpa16(&st[F_ARR + row*FSTR + ch], vfg + so);
    }
    cpa_commit();
}

__global__ __launch_bounds__(128) void flash_kernel()
{
    extern __shared__ __half fsm[];

    const int b = blockIdx.z, h = blockIdx.y, qt = blockIdx.x;
    const int tid = threadIdx.x, lane = tid & 31, warp = tid >> 5;
    const int hk = h / GROUPS;
    const int gi = lane >> 3, ii = lane & 7;
    const uint32_t fb = s2u(fsm);

    const __half* qfg = g_qf + (((size_t)b*NH  + h )*SS + qt*64)*HD;
    const __half* kfg = g_kf + (((size_t)b*NKV + hk)*SS)*HD;
    const __half* vfg = g_vf + (((size_t)b*NKV + hk)*SS)*HD;

    // stage Q through stage-0 smem, grab fragments
    {
        #pragma unroll
        for (int p = 0; p < 4; p++) {
            int cidx = tid + p*128;
            int row = cidx >> 3, ch = (cidx & 7)*8;
            size_t so = (size_t)row*HD + ch;
            cpa16(&fsm[row*FSTR + ch], qfg + so);
        }
        cpa_commit();
        cpa_wait0();
        __syncthreads();
    }

    uint32_t qf[4][4];
    #pragma unroll
    for (int kk = 0; kk < 4; kk++) {
        int row = warp*16 + ii + (gi & 1)*8;
        int col = kk*16 + (gi >> 1)*8;
        ldsm4(qf[kk], fb + (row*FSTR + col)*2);
    }
    __syncthreads();

    load_kv_tile(fsm, kfg, vfg, 0, tid);

    const uint32_t onesb[2] = {0x3C003C00u, 0x3C003C00u};   // fp16 1.0 x4
    float o[8][4];
    #pragma unroll
    for (int i = 0; i < 8; i++) for (int j = 0; j < 4; j++) o[i][j] = 0.f;
    float lacc[4] = {0.f, 0.f, 0.f, 0.f};                   // row-sum accumulator (ones-MMA)
    float m0 = -1e30f, m1 = -1e30f;

    for (int t = 0; t < SS/64; t++) {
        cpa_wait0();
        __syncthreads();
        if (t < SS/64 - 1)
            load_kv_tile(fsm + ((t+1)&1)*F_STAGE_E, kfg, vfg, t+1, tid);

        const uint32_t stb = fb + ((t&1)*F_STAGE_E)*2;   // stage base (bytes)

        // S = Q K^T (single fp16)
        float s[8][4];
        #pragma unroll
        for (int i = 0; i < 8; i++) for (int j = 0; j < 4; j++) s[i][j] = 0.f;
        #pragma unroll
        for (int kk = 0; kk < 4; kk++) {
            int col = kk*16 + (gi & 1)*8;
            uint32_t kf[4][4];
            #pragma unroll
            for (int ng = 0; ng < 4; ng++) {
                int row = ng*16 + ii + (gi >> 1)*8;
                ldsm4(kf[ng], stb + (row*FSTR + col)*2);
            }
            #pragma unroll
            for (int ng = 0; ng < 4; ng++) {
                mma16816h(s[2*ng],   qf[kk], &kf[ng][0]);
                mma16816h(s[2*ng+1], qf[kk], &kf[ng][2]);
            }
        }

        // online softmax (exp2 domain): running max + rescale
        float mx0 = -1e30f, mx1 = -1e30f;
        #pragma unroll
        for (int nt = 0; nt < 8; nt++) {
            mx0 = fmaxf(mx0, fmaxf(s[nt][0], s[nt][1]));
            mx1 = fmaxf(mx1, fmaxf(s[nt][2], s[nt][3]));
        }
        mx0 = fmaxf(mx0, __shfl_xor_sync(0xffffffffu, mx0, 1));
        mx0 = fmaxf(mx0, __shfl_xor_sync(0xffffffffu, mx0, 2));
        mx1 = fmaxf(mx1, __shfl_xor_sync(0xffffffffu, mx1, 1));
        mx1 = fmaxf(mx1, __shfl_xor_sync(0xffffffffu, mx1, 2));
        float nm0 = fmaxf(m0, mx0), nm1 = fmaxf(m1, mx1);
        float cr0 = fexp2(m0 - nm0), cr1 = fexp2(m1 - nm1);
        m0 = nm0; m1 = nm1;
        if (__ballot_sync(0xffffffffu, (cr0 < 1.f) | (cr1 < 1.f))) {
            #pragma unroll
            for (int nb = 0; nb < 8; nb++) {
                o[nb][0] *= cr0; o[nb][1] *= cr0;
                o[nb][2] *= cr1; o[nb][3] *= cr1;
            }
            lacc[0] *= cr0; lacc[1] *= cr0;
            lacc[2] *= cr1; lacc[3] *= cr1;
        }

        // P = exp2(s-m) as packed fp16 frags; l += P*ones; O += P*V
        #pragma unroll
        for (int ks = 0; ks < 4; ks++) {
            const float* s0 = s[2*ks];
            const float* s1 = s[2*ks+1];
            uint32_t pa[4];
            pa[0] = fexp2h2(s0[0] - m0, s0[1] - m0);
            pa[1] = fexp2h2(s0[2] - m1, s0[3] - m1);
            pa[2] = fexp2h2(s1[0] - m0, s1[1] - m0);
            pa[3] = fexp2h2(s1[2] - m1, s1[3] - m1);

            mma16816h(lacc, pa, onesb);   // row sums (replicated across cols)

            int row = ks*16 + ii + (gi & 1)*8;
            uint32_t bv[4][4];
            #pragma unroll
            for (int dg = 0; dg < 4; dg++) {
                int col = dg*16 + (gi >> 1)*8;
                ldsm4t(bv[dg], stb + (F_ARR + row*FSTR + col)*2);
            }
            #pragma unroll
            for (int dg = 0; dg < 4; dg++) {
                mma16816h(o[2*dg],   pa, &bv[dg][0]);
                mma16816h(o[2*dg+1], pa, &bv[dg][2]);
            }
        }
    }

    // finalize (ones-MMA already reduced over keys; no shuffles needed)
    float inv0 = 1.f / lacc[0], inv1 = 1.f / lacc[2];

    int r0 = qt*64 + warp*16 + (lane >> 2);
    size_t o0 = ((size_t)b*SS + r0    )*(NH*HD) + h*HD;
    size_t o1 = ((size_t)b*SS + r0 + 8)*(NH*HD) + h*HD;
    #pragma unroll
    for (int nb = 0; nb < 8; nb++) {
        int d = nb*8 + 2*(lane & 3);
        *(__half2*)&g_aof[o0 + d] = __floats2half2_rn(o[nb][0]*inv0, o[nb][1]*inv0);
        *(__half2*)&g_aof[o1 + d] = __floats2half2_rn(o[nb][2]*inv1, o[nb][3]*inv1);
    }
}

// ---------------- O-proj GEMM ----------------------------------------------
__global__ __launch_bounds__(256) void oproj_gemm(
    const float* __restrict__ bo, float* __restrict__ C)
{
    extern __shared__ __half gsm[];
    const int tid = threadIdx.x, lane = tid & 31, warp = tid >> 5;
    const int wm = warp >> 2, wn = warp & 3;
    const int gi = lane >> 3, ii = lane & 7;
    const int bx = blockIdx.x, by = blockIdx.y;
    const int n0 = bx * 128;
    const uint32_t gb = s2u(gsm);

    float c[4][4][4];
    #pragma unroll
    for (int i=0;i<4;i++) for (int j=0;j<4;j++) for (int e=0;e<4;e++) c[i][j][e]=0.f;

    load_gemm_tile(gsm, g_aof, g_wof, by*128, n0, 0, tid);

    for (int t = 0; t < 32; t++) {
        cpa_wait0();
        __syncthreads();
        if (t < 31)
            load_gemm_tile(gsm + ((t+1)&1)*G_STAGE_E, g_aof, g_wof,
                           by*128, n0, (t+1)*32, tid);
        gemm_compute(gb + (t&1)*G_STAGE_E*2, c, wm, wn, gi, ii);
    }

    #pragma unroll
    for (int mi = 0; mi < 4; mi++)
        #pragma unroll
        for (int ni = 0; ni < 4; ni++)
            #pragma unroll
            for (int e = 0; e < 4; e++) {
                int m = by*128 + wm*64 + mi*16 + (lane >> 2) + ((e >= 2) ? 8 : 0);
                int n = n0 + wn*32 + ni*8 + 2*(lane & 3) + (e & 1);
                C[(size_t)m*HIDD + n] = c[mi][ni][e] + bo[n];
            }
}

// ---------------------------------------------------------------------------
extern "C" void kernel_launch(void* const* d_in, const int* in_sizes, int n_in,
                              void* d_out, int out_size)
{
    const float* X    = (const float*)d_in[0];
    const float* cosp = (const float*)d_in[1];
    const float* sinp = (const float*)d_in[2];
    const float* Wq   = (const float*)d_in[3];
    const float* bq   = (const float*)d_in[4];
    const float* Wk   = (const float*)d_in[5];
    const float* bk   = (const float*)d_in[6];
    const float* Wv   = (const float*)d_in[7];
    const float* bv   = (const float*)d_in[8];
    const float* Wo   = (const float*)d_in[9];
    const float* bo   = (const float*)d_in[10];
    float* out = (float*)d_out;

    const int gemm_smem  = 2 * G_STAGE_E * (int)sizeof(__half);   // 40960
    const int flash_smem = 2 * F_STAGE_E * (int)sizeof(__half);   // 36864
    cudaFuncSetAttribute(qkv_gemm,    cudaFuncAttributeMaxDynamicSharedMemorySize, gemm_smem);
    cudaFuncSetAttribute(oproj_gemm,  cudaFuncAttributeMaxDynamicSharedMemorySize, gemm_smem);
    cudaFuncSetAttribute(flash_kernel,cudaFuncAttributeMaxDynamicSharedMemorySize, flash_smem);

    int n4_total = N4_X + 2*N4_WQ + 2*N4_WK;
    split_all<<<(n4_total + 255)/256, 256>>>(X, Wq, Wk, Wv, Wo);

    dim3 g1(1536/128, 8192/128);
    qkv_gemm<<<g1, 256, gemm_smem>>>(bq, bk, bv);

    int tq = BB*NH *SS*32;
    int tk = BB*NKV*SS*32;
    rope_all<<<(tq + tk + 255)/256, 256>>>(cosp, sinp, tq, tq + tk);

    dim3 g3(SS/64, NH, BB);
    flash_kernel<<<g3, 128, flash_smem>>>();

    dim3 g4(1024/128, 8192/128);
    oproj_gemm<<<g4, 256, gemm_smem>>>(bo, out);
}